// round 5
// baseline (speedup 1.0000x reference)
#include <cuda_runtime.h>
#include <cuda_bf16.h>
#include <cuda_fp16.h>
#include <math.h>
#include <stdint.h>

// ---------------- problem-size caps (fixed by setup_inputs) ----------------
#define MAXN 50000
#define NPADMAX 50048   // MAXN rounded up to 128

// ---------------- device scratch (no allocation allowed) -------------------
__device__ int   g_deg[MAXN];
__device__ int   g_cnt[MAXN];
__device__ int   g_cur[MAXN];
__device__ int   g_roff[MAXN + 1];
__device__ int   g_csrc[800000];
__device__ float g_cw[800000];
__device__ float g_dis[MAXN];
__device__ float g_xc[(size_t)MAXN * 384];     // dense Tx1 scratch [N, F]
__device__ float g_gate[(size_t)MAXN * 768];   // gate pre-activations (used as fp16)
__device__ float g_h[(size_t)MAXN * 64];       // layer3 gconv output fp32
__device__ float g_h2[(size_t)MAXN * 128];     // post-linear output (dense)
__device__ float g_wbias[1344];                // combined gate biases (l1|l2|l3)
__device__ __align__(256) __nv_bfloat16 g_bufA[(size_t)NPADMAX * 768]; // gconv A2
__device__ __align__(256) __nv_bfloat16 g_bufB[(size_t)NPADMAX * 512]; // lin A2
__device__ __align__(256) __nv_bfloat16 g_bbuf[524288];                // all B2

// B buffer element offsets (each region is rows x 2*Kp)
#define O_B1  0        // l1 gate: 768 x 64
#define O_B2  49152    // l2 gate: 384 x 768
#define O_B3  344064   // l3 gate: 192 x 384
#define O_BL1 417792   // lin1: 128 x 512
#define O_BL2 483328   // lin2: 64 x 256

// ====================== graph preprocessing ================================

__global__ void k_degree(const int* __restrict__ src, const int* __restrict__ dst, int E) {
    int e = blockIdx.x * blockDim.x + threadIdx.x;
    if (e >= E) return;
    atomicAdd(&g_deg[src[e]], 1);
    atomicAdd(&g_cnt[dst[e]], 1);
}

__global__ void k_dis(int n) {
    int i = blockIdx.x * blockDim.x + threadIdx.x;
    if (i >= n) return;
    int d = g_deg[i];
    g_dis[i] = d > 0 ? rsqrtf((float)d) : 0.0f;
}

__global__ void k_scan(int n) {
    __shared__ int ssum[1024];
    int tid = threadIdx.x;
    const int T = 1024;
    int chunk = (n + T - 1) / T;
    int beg = tid * chunk;
    int end = beg + chunk; if (end > n) end = n;
    int s = 0;
    for (int i = beg; i < end; i++) s += g_cnt[i];
    ssum[tid] = s;
    __syncthreads();
    for (int off = 1; off < T; off <<= 1) {
        int v = (tid >= off) ? ssum[tid - off] : 0;
        __syncthreads();
        ssum[tid] += v;
        __syncthreads();
    }
    int run = (tid > 0) ? ssum[tid - 1] : 0;
    for (int i = beg; i < end; i++) { g_roff[i] = run; run += g_cnt[i]; }
    if (tid == T - 1) g_roff[n] = ssum[T - 1];
}

__global__ void k_fill(const int* __restrict__ src, const int* __restrict__ dst, int E) {
    int e = blockIdx.x * blockDim.x + threadIdx.x;
    if (e >= E) return;
    int s = src[e], d = dst[e];
    int pos = g_roff[d] + atomicAdd(&g_cur[d], 1);
    g_csrc[pos] = s;
    g_cw[pos] = -g_dis[s] * g_dis[d];
}

// ====================== bf16 split helper ==================================

__device__ __forceinline__ void bsplit(float x, __nv_bfloat16& hi, __nv_bfloat16& lo) {
    hi = __float2bfloat16_rn(x);
    lo = __float2bfloat16_rn(x - __bfloat162float(hi));
}

// ====================== merged weight/bias preprocessing ===================

__device__ __forceinline__ void prep_gateB(const float* __restrict__ Wx, int F, int H,
                                           int Kp, int nrow, int kk,
                                           __nv_bfloat16* __restrict__ dst) {
    int gp = nrow / H, o = nrow % H;
    int gate = (gp == 0) ? 0 : (gp + 1);   // gates {0,2,3}
    float w = 0.0f;
    if (kk < 3 * F) {
        int kc = kk / F, f = kk % F;
        w = Wx[(((size_t)gate * 3 + kc) * F + f) * H + o];
    }
    __nv_bfloat16 hi, lo; bsplit(w, hi, lo);
    dst[(size_t)nrow * 2 * Kp + kk] = hi;
    dst[(size_t)nrow * 2 * Kp + Kp + kk] = lo;
}

__device__ __forceinline__ void prep_linB(const float* __restrict__ W, int Hout,
                                          int Kp, int nrow, int kk,
                                          __nv_bfloat16* __restrict__ dst) {
    float w = W[(size_t)kk * Hout + nrow];
    __nv_bfloat16 hi, lo; bsplit(w, hi, lo);
    dst[(size_t)nrow * 2 * Kp + kk] = hi;
    dst[(size_t)nrow * 2 * Kp + Kp + kk] = lo;
}

#define E1 24576     // 768*32
#define E2 172032    // +384*384
#define E3 208896    // +192*192
#define E4 241664    // +128*256
#define E5 249856    // +64*128
#define E6 251200    // +1344 biases

__global__ void k_prep_all(
    const float* __restrict__ w1, const float* __restrict__ w2, const float* __restrict__ w3,
    const float* __restrict__ wl1, const float* __restrict__ wl2,
    const float* __restrict__ bx1, const float* __restrict__ bh1, const float* __restrict__ b1,
    const float* __restrict__ bx2, const float* __restrict__ bh2, const float* __restrict__ b2,
    const float* __restrict__ bx3, const float* __restrict__ bh3, const float* __restrict__ b3) {
    int idx = blockIdx.x * blockDim.x + threadIdx.x;
    if (idx >= E6) return;
    if (idx < E1) {
        prep_gateB(w1, 3, 256, 32, idx / 32, idx % 32, g_bbuf + O_B1);
    } else if (idx < E2) {
        int t = idx - E1;
        prep_gateB(w2, 128, 128, 384, t / 384, t % 384, g_bbuf + O_B2);
    } else if (idx < E3) {
        int t = idx - E2;
        prep_gateB(w3, 64, 64, 192, t / 192, t % 192, g_bbuf + O_B3);
    } else if (idx < E4) {
        int t = idx - E3;
        prep_linB(wl1, 128, 256, t / 256, t % 256, g_bbuf + O_BL1);
    } else if (idx < E5) {
        int t = idx - E4;
        prep_linB(wl2, 64, 128, t / 128, t % 128, g_bbuf + O_BL2);
    } else {
        int t = idx - E5;
        const float *bx, *bh, *bb; int H, base;
        if (t < 768)       { bx = bx1; bh = bh1; bb = b1; H = 256; base = 0; }
        else if (t < 1152) { bx = bx2; bh = bh2; bb = b2; H = 128; base = 768; t -= 768; }
        else               { bx = bx3; bh = bh3; bb = b3; H = 64;  base = 1152; t -= 1152; }
        int gp = t / H, o = t % H;
        int gate = (gp == 0) ? 0 : (gp + 1);
        g_wbias[base + t] = bx[gate * H + o] + bh[gate * H + o] + bb[gate * H + o];
    }
}

// ====================== layer-1 cheb prep (F=3) ============================

__global__ void k_l1a(const float* __restrict__ x, float* __restrict__ t1d,
                      __nv_bfloat16* __restrict__ A2, int n, int npad) {
    int row = blockIdx.x * blockDim.x + threadIdx.x;
    if (row >= npad) return;
    float t0[3] = {0, 0, 0}, t1[3] = {0, 0, 0};
    if (row < n) {
        t0[0] = x[row * 3]; t0[1] = x[row * 3 + 1]; t0[2] = x[row * 3 + 2];
        int j0 = g_roff[row], j1 = g_roff[row + 1];
        for (int j = j0; j < j1; j++) {
            int sidx = g_csrc[j]; float w = g_cw[j];
            t1[0] += w * x[sidx * 3];
            t1[1] += w * x[sidx * 3 + 1];
            t1[2] += w * x[sidx * 3 + 2];
        }
        t1d[row * 3] = t1[0]; t1d[row * 3 + 1] = t1[1]; t1d[row * 3 + 2] = t1[2];
    }
    size_t base = (size_t)row * 64;
    __nv_bfloat16 hi, lo;
#pragma unroll
    for (int k = 0; k < 3; k++) {
        bsplit(t0[k], hi, lo);
        A2[base + k] = hi; A2[base + 32 + k] = lo;
        bsplit(t1[k], hi, lo);
        A2[base + 3 + k] = hi; A2[base + 35 + k] = lo;
    }
#pragma unroll
    for (int k = 9; k < 32; k++) {
        A2[base + k] = __float2bfloat16(0.f);
        A2[base + 32 + k] = __float2bfloat16(0.f);
    }
}

__global__ void k_l1b(const float* __restrict__ t1d, const float* __restrict__ x,
                      __nv_bfloat16* __restrict__ A2, int n, int npad) {
    int row = blockIdx.x * blockDim.x + threadIdx.x;
    if (row >= npad) return;
    float t2[3] = {0, 0, 0};
    if (row < n) {
        int j0 = g_roff[row], j1 = g_roff[row + 1];
        for (int j = j0; j < j1; j++) {
            int sidx = g_csrc[j]; float w = g_cw[j];
            t2[0] += w * t1d[sidx * 3];
            t2[1] += w * t1d[sidx * 3 + 1];
            t2[2] += w * t1d[sidx * 3 + 2];
        }
        t2[0] = 2.f * t2[0] - x[row * 3];
        t2[1] = 2.f * t2[1] - x[row * 3 + 1];
        t2[2] = 2.f * t2[2] - x[row * 3 + 2];
    }
    size_t base = (size_t)row * 64;
    __nv_bfloat16 hi, lo;
#pragma unroll
    for (int k = 0; k < 3; k++) {
        bsplit(t2[k], hi, lo);
        A2[base + 6 + k] = hi; A2[base + 38 + k] = lo;
    }
}

// ====================== fused SpMV + split =================================

template <int F, int CHEB2>
__global__ void k_spmv_split(const float* __restrict__ X, const float* __restrict__ X0,
                             float* __restrict__ Yd,
                             __nv_bfloat16* __restrict__ A2, int Kp, int sec,
                             int n, int npad) {
    const int TPR = F / 4;
    int tid = threadIdx.x;
    int row = blockIdx.x * (256 / TPR) + tid / TPR;
    int f = (tid % TPR) * 4;
    if (row >= npad) return;
    float a0 = 0.f, a1 = 0.f, a2 = 0.f, a3 = 0.f;
    if (row < n) {
        int j0 = g_roff[row], j1 = g_roff[row + 1];
        for (int j = j0; j < j1; j++) {
            int sidx = g_csrc[j]; float w = g_cw[j];
            float4 xv = *reinterpret_cast<const float4*>(X + (size_t)sidx * F + f);
            a0 += w * xv.x; a1 += w * xv.y; a2 += w * xv.z; a3 += w * xv.w;
        }
        if (CHEB2) {
            float4 x0 = *reinterpret_cast<const float4*>(X0 + (size_t)row * F + f);
            a0 = 2.f * a0 - x0.x; a1 = 2.f * a1 - x0.y;
            a2 = 2.f * a2 - x0.z; a3 = 2.f * a3 - x0.w;
        }
        if (Yd)
            *reinterpret_cast<float4*>(Yd + (size_t)row * F + f) = make_float4(a0, a1, a2, a3);
    }
    __nv_bfloat16 h0, l0, h1, l1, h2, l2, h3, l3;
    bsplit(a0, h0, l0); bsplit(a1, h1, l1); bsplit(a2, h2, l2); bsplit(a3, h3, l3);
    size_t base = (size_t)row * 2 * Kp + sec + f;
    __nv_bfloat162* ph = reinterpret_cast<__nv_bfloat162*>(A2 + base);
    ph[0] = __nv_bfloat162(h0, h1); ph[1] = __nv_bfloat162(h2, h3);
    __nv_bfloat162* pl = reinterpret_cast<__nv_bfloat162*>(A2 + base + Kp);
    pl[0] = __nv_bfloat162(l0, l1); pl[1] = __nv_bfloat162(l2, l3);
}

// ====================== mma.sync split-bf16 GEMM ===========================
// C[M,Nc] = A @ B^T, A=[Ahi|Alo], B=[Bhi|Blo] (row stride 2*Kp, K-major).
// acc += Ahi*Bhi + Ahi*Blo + Alo*Bhi. CTA 128x64, BK=32, 8 warps (4x2).
// 3-stage cp.async ring, ONE barrier per k-tile.
// Output: fp16 C (gate pre-acts) or fp32 C (+bias/lrelu) and/or bf16 split S.

#define CP16(dst, src) \
    asm volatile("cp.async.ca.shared.global [%0], [%1], 16;\n" :: "r"(dst), "l"(src))
#define CP_COMMIT() asm volatile("cp.async.commit_group;\n" ::: "memory")
#define CP_WAIT1()  asm volatile("cp.async.wait_group 1;\n" ::: "memory")
#define CP_WAIT0()  asm volatile("cp.async.wait_group 0;\n" ::: "memory")

__device__ __forceinline__ uint32_t smem_u32(const void* p) {
    uint32_t a;
    asm("{ .reg .u64 t; cvta.to.shared.u64 t, %1; cvt.u32.u64 %0, t; }"
        : "=r"(a) : "l"(p));
    return a;
}

__device__ __forceinline__ void ldm_x4(uint32_t* r, uint32_t addr) {
    asm volatile("ldmatrix.sync.aligned.m8n8.x4.shared.b16 {%0,%1,%2,%3}, [%4];"
                 : "=r"(r[0]), "=r"(r[1]), "=r"(r[2]), "=r"(r[3]) : "r"(addr));
}

__device__ __forceinline__ void mma16816(float* c, const uint32_t* a, const uint32_t* b) {
    asm volatile(
        "mma.sync.aligned.m16n8k16.row.col.f32.bf16.bf16.f32 "
        "{%0,%1,%2,%3}, {%4,%5,%6,%7}, {%8,%9}, {%0,%1,%2,%3};"
        : "+f"(c[0]), "+f"(c[1]), "+f"(c[2]), "+f"(c[3])
        : "r"(a[0]), "r"(a[1]), "r"(a[2]), "r"(a[3]), "r"(b[0]), "r"(b[1]));
}

// stage layout (80B padded rows): A-hi 0-127, A-lo 128-255, B-hi 256-319,
// B-lo 320-383. Stage = 384*80 = 30720B, 3 stages = 92160B.
#define GSTAGE 30720

__global__ __launch_bounds__(256, 2) void gemm_mma2(
    const __nv_bfloat16* __restrict__ A, const __nv_bfloat16* __restrict__ B,
    const float* __restrict__ bias, void* __restrict__ Cout, int halfOut,
    __nv_bfloat16* __restrict__ S, int sKp,
    int M, int Kp, int Nc, int act) {
    extern __shared__ char smem[];
    const uint32_t s0 = smem_u32(smem);
    const int tid = threadIdx.x;
    const int wid = tid >> 5;
    const int lane = tid & 31;
    const int wm = wid & 3, wn = wid >> 2;
    const int bn = blockIdx.x << 6;
    const int bm = blockIdx.y << 7;
    const size_t strA = 2 * (size_t)Kp;

    float acc[2][4][4];
#pragma unroll
    for (int i = 0; i < 2; i++)
#pragma unroll
        for (int j = 0; j < 4; j++)
#pragma unroll
            for (int k = 0; k < 4; k++) acc[i][j][k] = 0.f;

#define LOAD_STAGE(stg, kc) do {                                             \
    uint32_t dstBase = s0 + (stg) * GSTAGE;                                  \
    _Pragma("unroll")                                                        \
    for (int u = tid; u < 1536; u += 256) {                                  \
        uint32_t d; const char* g;                                           \
        if (u < 1024) {                                                      \
            int hl = u >> 9, t = u & 511, row = t >> 2, seg = t & 3;         \
            d = dstBase + (hl * 128 + row) * 80 + seg * 16;                  \
            g = (const char*)A + ((size_t)(bm + row) * strA                  \
                + (size_t)hl * Kp + (kc)) * 2 + seg * 16;                    \
        } else {                                                             \
            int t = u - 1024; int hl = t >> 8; t &= 255;                     \
            int row = t >> 2, seg = t & 3;                                   \
            d = dstBase + (256 + hl * 64 + row) * 80 + seg * 16;             \
            g = (const char*)B + ((size_t)(bn + row) * strA                  \
                + (size_t)hl * Kp + (kc)) * 2 + seg * 16;                    \
        }                                                                    \
        CP16(d, g);                                                          \
    } } while (0)

    const int nK = Kp >> 5;
    LOAD_STAGE(0, 0);
    CP_COMMIT();
    if (nK > 1) { LOAD_STAGE(1, 32); CP_COMMIT(); }

    for (int kt = 0; kt < nK; kt++) {
        if (kt + 1 < nK) CP_WAIT1(); else CP_WAIT0();
        __syncthreads();
        if (kt + 2 < nK) {
            LOAD_STAGE((kt + 2) % 3, (kt + 2) << 5);
            CP_COMMIT();
        }
        uint32_t base = s0 + (kt % 3) * GSTAGE;
        uint32_t kb = (lane >> 4) * 16;
        uint32_t arow = wm * 32 + (lane & 15);
        uint32_t brow = 256 + wn * 32 + (lane & 15);
#pragma unroll
        for (int kk = 0; kk < 2; kk++) {
            uint32_t a_hi[2][4], a_lo[2][4];
#pragma unroll
            for (int mt = 0; mt < 2; mt++) {
                ldm_x4(a_hi[mt], base + (arow + mt * 16) * 80 + kk * 32 + kb);
                ldm_x4(a_lo[mt], base + (arow + mt * 16 + 128) * 80 + kk * 32 + kb);
            }
            uint32_t b_hi[4][2], b_lo[4][2];
#pragma unroll
            for (int j = 0; j < 2; j++) {
                uint32_t r[4];
                ldm_x4(r, base + (brow + j * 16) * 80 + kk * 32 + kb);
                b_hi[2 * j][0] = r[0]; b_hi[2 * j][1] = r[2];
                b_hi[2 * j + 1][0] = r[1]; b_hi[2 * j + 1][1] = r[3];
                ldm_x4(r, base + (brow + j * 16 + 64) * 80 + kk * 32 + kb);
                b_lo[2 * j][0] = r[0]; b_lo[2 * j][1] = r[2];
                b_lo[2 * j + 1][0] = r[1]; b_lo[2 * j + 1][1] = r[3];
            }
#pragma unroll
            for (int mt = 0; mt < 2; mt++)
#pragma unroll
                for (int nt = 0; nt < 4; nt++) {
                    mma16816(acc[mt][nt], a_hi[mt], b_hi[nt]);
                    mma16816(acc[mt][nt], a_hi[mt], b_lo[nt]);
                    mma16816(acc[mt][nt], a_lo[mt], b_hi[nt]);
                }
        }
    }

    // epilogue
    const int gid = lane >> 2, tig = lane & 3;
#pragma unroll
    for (int mt = 0; mt < 2; mt++) {
#pragma unroll
        for (int half = 0; half < 2; half++) {
            int row = bm + wm * 32 + mt * 16 + half * 8 + gid;
            bool valid = row < M;
#pragma unroll
            for (int nt = 0; nt < 4; nt++) {
                int col = bn + wn * 32 + nt * 8 + tig * 2;
                float v0 = 0.f, v1 = 0.f;
                if (valid) {
                    v0 = acc[mt][nt][2 * half + 0] + bias[col];
                    v1 = acc[mt][nt][2 * half + 1] + bias[col + 1];
                    if (act) {
                        v0 = v0 > 0.f ? v0 : 0.1f * v0;
                        v1 = v1 > 0.f ? v1 : 0.1f * v1;
                    }
                    if (halfOut) {
                        *reinterpret_cast<__half2*>(
                            (__half*)Cout + (size_t)row * Nc + col) =
                            __floats2half2_rn(v0, v1);
                    } else {
                        *reinterpret_cast<float2*>(
                            (float*)Cout + (size_t)row * Nc + col) =
                            make_float2(v0, v1);
                    }
                }
                if (S) {
                    __nv_bfloat16 h0, l0, h1, l1;
                    bsplit(v0, h0, l0); bsplit(v1, h1, l1);
                    size_t sb = (size_t)row * 2 * sKp + col;
                    *reinterpret_cast<__nv_bfloat162*>(S + sb) = __nv_bfloat162(h0, h1);
                    *reinterpret_cast<__nv_bfloat162*>(S + sb + sKp) = __nv_bfloat162(l0, l1);
                }
            }
        }
    }
}

// ====================== LSTM gate fusion ===================================

__device__ __forceinline__ float sigf(float x) { return 1.0f / (1.0f + expf(-x)); }

__device__ __forceinline__ float gate_eval_h(const __half* g, const float* wcO, int H, int o) {
    float I = sigf(__half2float(g[o]));
    float T = tanhf(__half2float(g[H + o]));
    float Cv = I * T;
    float O = sigf(__half2float(g[2 * H + o]) + wcO[o] * Cv);
    float y = O * tanhf(Cv);
    return y > 0.f ? y : 0.1f * y;   // fused leaky relu
}

__global__ void k_gates(const __half* __restrict__ G, const float* __restrict__ wcO,
                        float* __restrict__ Y, int n, int H) {
    int idx = blockIdx.x * blockDim.x + threadIdx.x;
    if (idx >= n * H) return;
    int r = idx / H, o = idx % H;
    Y[(size_t)r * H + o] = gate_eval_h(G + (size_t)r * 3 * H, wcO, H, o);
}

// gates -> [hi|lo] split A2 (Kp == H)
__global__ void k_gates_split(const __half* __restrict__ G, const float* __restrict__ wcO,
                              __nv_bfloat16* __restrict__ A2, int n, int npad, int H) {
    int idx = blockIdx.x * blockDim.x + threadIdx.x;
    if (idx >= npad * H) return;
    int r = idx / H, o = idx % H;
    float y = 0.0f;
    if (r < n) y = gate_eval_h(G + (size_t)r * 3 * H, wcO, H, o);
    __nv_bfloat16 hi, lo; bsplit(y, hi, lo);
    size_t base = (size_t)r * 2 * H;
    A2[base + o] = hi;
    A2[base + H + o] = lo;
}

// ====================== final small GEMM [N,64]@[64,3] =====================

__global__ void k_lin3(const float* __restrict__ Hin, const float* __restrict__ W,
                       const float* __restrict__ b, float* __restrict__ out, int n) {
    __shared__ float w[64 * 3];
    if (threadIdx.x < 192) w[threadIdx.x] = W[threadIdx.x];
    __syncthreads();
    int r = blockIdx.x * blockDim.x + threadIdx.x;
    if (r >= n) return;
    float a0 = b[0], a1 = b[1], a2 = b[2];
    const float* h = Hin + (size_t)r * 64;
#pragma unroll
    for (int k = 0; k < 64; k++) {
        float hv = h[k];
        a0 += hv * w[k * 3 + 0];
        a1 += hv * w[k * 3 + 1];
        a2 += hv * w[k * 3 + 2];
    }
    float* o = out + (size_t)r * 3;
    o[0] = a0; o[1] = a1; o[2] = a2;
}

// ====================== host orchestration =================================

static inline int ceildiv(int a, int b) { return (a + b - 1) / b; }

extern "C" void kernel_launch(void* const* d_in, const int* in_sizes, int n_in,
                              void* d_out, int out_size) {
    const float* x = (const float*)d_in[0];
    const int* ei = (const int*)d_in[1];
    int N = in_sizes[0] / 3;
    int E = in_sizes[1] / 2;
    const int* src = ei;
    const int* dst = ei + E;
    int Npad = (N + 127) & ~127;
    int Mt = Npad / 128;

    const float* l1_Wx = (const float*)d_in[2];
    const float* l1_bx = (const float*)d_in[3];
    const float* l1_bh = (const float*)d_in[5];
    const float* l1_wc = (const float*)d_in[6];
    const float* l1_b  = (const float*)d_in[7];
    const float* l2_Wx = (const float*)d_in[8];
    const float* l2_bx = (const float*)d_in[9];
    const float* l2_bh = (const float*)d_in[11];
    const float* l2_wc = (const float*)d_in[12];
    const float* l2_b  = (const float*)d_in[13];
    const float* l3_Wx = (const float*)d_in[14];
    const float* l3_bx = (const float*)d_in[15];
    const float* l3_bh = (const float*)d_in[17];
    const float* l3_wc = (const float*)d_in[18];
    const float* l3_b  = (const float*)d_in[19];
    const float* lin1_W = (const float*)d_in[20];
    const float* lin1_b = (const float*)d_in[21];
    const float* lin2_W = (const float*)d_in[22];
    const float* lin2_b = (const float*)d_in[23];
    const float* lin3_W = (const float*)d_in[24];
    const float* lin3_b = (const float*)d_in[25];
    float* out = (float*)d_out;

    void* p;
    cudaGetSymbolAddress(&p, g_deg);   int* deg = (int*)p;
    cudaGetSymbolAddress(&p, g_cnt);   int* cnt = (int*)p;
    cudaGetSymbolAddress(&p, g_cur);   int* cur = (int*)p;
    cudaGetSymbolAddress(&p, g_xc);    float* xc = (float*)p;
    cudaGetSymbolAddress(&p, g_gate);  __half* G = (__half*)p;
    cudaGetSymbolAddress(&p, g_h);     float* Hbuf = (float*)p;
    cudaGetSymbolAddress(&p, g_h2);    float* H2 = (float*)p;
    cudaGetSymbolAddress(&p, g_wbias); float* wb = (float*)p;
    cudaGetSymbolAddress(&p, g_bufA);  __nv_bfloat16* bufA = (__nv_bfloat16*)p;
    cudaGetSymbolAddress(&p, g_bufB);  __nv_bfloat16* bufB = (__nv_bfloat16*)p;
    cudaGetSymbolAddress(&p, g_bbuf);  __nv_bfloat16* bb = (__nv_bfloat16*)p;

    cudaFuncSetAttribute(gemm_mma2, cudaFuncAttributeMaxDynamicSharedMemorySize,
                         3 * GSTAGE);

    cudaStream_t s = 0;

    // ---- graph preprocessing ----
    cudaMemsetAsync(deg, 0, N * sizeof(int), s);
    cudaMemsetAsync(cnt, 0, N * sizeof(int), s);
    cudaMemsetAsync(cur, 0, N * sizeof(int), s);
    k_degree<<<ceildiv(E, 256), 256, 0, s>>>(src, dst, E);
    k_dis<<<ceildiv(N, 256), 256, 0, s>>>(N);
    k_scan<<<1, 1024, 0, s>>>(N);
    k_fill<<<ceildiv(E, 256), 256, 0, s>>>(src, dst, E);

    // ---- all weight/bias preprocessing in one kernel ----
    k_prep_all<<<ceildiv(E6, 256), 256, 0, s>>>(
        l1_Wx, l2_Wx, l3_Wx, lin1_W, lin2_W,
        l1_bx, l1_bh, l1_b, l2_bx, l2_bh, l2_b, l3_bx, l3_bh, l3_b);

    // ================= layer 1 (F=3, H=256) =================
    k_l1a<<<ceildiv(Npad, 256), 256, 0, s>>>(x, xc, bufA, N, Npad);
    k_l1b<<<ceildiv(Npad, 256), 256, 0, s>>>(xc, x, bufA, N, Npad);
    gemm_mma2<<<dim3(768 / 64, Mt), 256, 3 * GSTAGE, s>>>(
        bufA, bb + O_B1, wb, G, 1, nullptr, 0, N, 32, 768, 0);
    k_gates_split<<<ceildiv(Npad * 256, 256), 256, 0, s>>>(G, l1_wc + 512, bufB, N, Npad, 256);
    // lin1: [N,256]@[256,128] + lrelu, fused split of T0 (layer2 Kp=384)
    gemm_mma2<<<dim3(128 / 64, Mt), 256, 3 * GSTAGE, s>>>(
        bufB, bb + O_BL1, lin1_b, H2, 0, bufA, 384, N, 256, 128, 1);

    // ================= layer 2 (F=128, H=128) =================
    k_spmv_split<128, 0><<<ceildiv(Npad, 8), 256, 0, s>>>(H2, nullptr, xc, bufA, 384, 128, N, Npad);
    k_spmv_split<128, 1><<<ceildiv(Npad, 8), 256, 0, s>>>(xc, H2, nullptr, bufA, 384, 256, N, Npad);
    gemm_mma2<<<dim3(384 / 64, Mt), 256, 3 * GSTAGE, s>>>(
        bufA, bb + O_B2, wb + 768, G, 1, nullptr, 0, N, 384, 384, 0);
    k_gates_split<<<ceildiv(Npad * 128, 256), 256, 0, s>>>(G, l2_wc + 256, bufB, N, Npad, 128);
    // lin2: [N,128]@[128,64] + lrelu, fused split of T0 (layer3 Kp=192)
    gemm_mma2<<<dim3(64 / 64, Mt), 256, 3 * GSTAGE, s>>>(
        bufB, bb + O_BL2, lin2_b, H2, 0, bufA, 192, N, 128, 64, 1);

    // ================= layer 3 (F=64, H=64) =================
    k_spmv_split<64, 0><<<ceildiv(Npad, 16), 256, 0, s>>>(H2, nullptr, xc, bufA, 192, 64, N, Npad);
    k_spmv_split<64, 1><<<ceildiv(Npad, 16), 256, 0, s>>>(xc, H2, nullptr, bufA, 192, 128, N, Npad);
    gemm_mma2<<<dim3(192 / 64, Mt), 256, 3 * GSTAGE, s>>>(
        bufA, bb + O_B3, wb + 1152, G, 1, nullptr, 0, N, 192, 192, 0);
    k_gates<<<ceildiv(N * 64, 256), 256, 0, s>>>(G, l3_wc + 128, Hbuf, N, 64);
    k_lin3<<<ceildiv(N, 256), 256, 0, s>>>(Hbuf, lin3_W, lin3_b, out, N);
}

// round 6
// speedup vs baseline: 1.1302x; 1.1302x over previous
#include <cuda_runtime.h>
#include <cuda_fp16.h>
#include <math.h>
#include <stdint.h>

// ---------------- problem-size caps (fixed by setup_inputs) ----------------
#define MAXN 50000
#define NPADMAX 50048   // MAXN rounded up to 128

// ---------------- device scratch (no allocation allowed) -------------------
__device__ int   g_tmp[3 * MAXN];    // deg | cnt | cur (one memset)
__device__ int   g_roff[MAXN + 1];
__device__ int   g_csrc[800000];
__device__ float g_cw[800000];
__device__ float g_xc[(size_t)MAXN * 384];     // dense Tx1 scratch [N, F]
__device__ float g_gate[(size_t)MAXN * 768];   // gate pre-activations (fp16 view)
__device__ float g_h[(size_t)MAXN * 64];       // layer3 gconv output fp32
__device__ float g_h2[(size_t)MAXN * 128];     // post-linear output (dense)
__device__ float g_wbias[1344];                // combined gate biases (l1|l2|l3)
__device__ __align__(256) __half g_bufA[(size_t)NPADMAX * 768]; // act A (hi|lo)
__device__ __align__(256) __half g_bufB[(size_t)NPADMAX * 512]; // lin A (hi|lo)
__device__ __align__(256) __half g_bbuf[262144];                // all weights fp16

// weight buffer element offsets (rows x Kp, single fp16)
#define O_B1  0        // l1 gate: 768 x 32
#define O_B2  24576    // l2 gate: 384 x 384
#define O_B3  172032   // l3 gate: 192 x 192
#define O_BL1 208896   // lin1: 128 x 256
#define O_BL2 241664   // lin2: 64 x 128

// ====================== graph preprocessing ================================

__global__ void k_degree(const int* __restrict__ src, const int* __restrict__ dst, int E) {
    int e = blockIdx.x * blockDim.x + threadIdx.x;
    if (e >= E) return;
    atomicAdd(&g_tmp[src[e]], 1);            // deg
    atomicAdd(&g_tmp[MAXN + dst[e]], 1);     // cnt
}

__global__ void k_scan(int n) {
    __shared__ int ssum[1024];
    int tid = threadIdx.x;
    const int T = 1024;
    int chunk = (n + T - 1) / T;
    int beg = tid * chunk;
    int end = beg + chunk; if (end > n) end = n;
    int s = 0;
    for (int i = beg; i < end; i++) s += g_tmp[MAXN + i];
    ssum[tid] = s;
    __syncthreads();
    for (int off = 1; off < T; off <<= 1) {
        int v = (tid >= off) ? ssum[tid - off] : 0;
        __syncthreads();
        ssum[tid] += v;
        __syncthreads();
    }
    int run = (tid > 0) ? ssum[tid - 1] : 0;
    for (int i = beg; i < end; i++) { g_roff[i] = run; run += g_tmp[MAXN + i]; }
    if (tid == T - 1) g_roff[n] = ssum[T - 1];
}

__global__ void k_fill(const int* __restrict__ src, const int* __restrict__ dst, int E) {
    int e = blockIdx.x * blockDim.x + threadIdx.x;
    if (e >= E) return;
    int s = src[e], d = dst[e];
    int pos = g_roff[d] + atomicAdd(&g_tmp[2 * MAXN + d], 1);
    int ds = g_tmp[s], dd = g_tmp[d];
    float is = ds > 0 ? rsqrtf((float)ds) : 0.0f;
    float id = dd > 0 ? rsqrtf((float)dd) : 0.0f;
    g_csrc[pos] = s;
    g_cw[pos] = -is * id;
}

// ====================== fp16 split helper ==================================

__device__ __forceinline__ void hsplit(float x, __half& hi, __half& lo) {
    hi = __float2half_rn(x);
    lo = __float2half_rn(x - __half2float(hi));
}

// ====================== merged weight/bias preprocessing ===================
// weights single fp16, rows x Kp, K-major (B[n][k]).

__device__ __forceinline__ void prep_gateB(const float* __restrict__ Wx, int F, int H,
                                           int Kp, int nrow, int kk,
                                           __half* __restrict__ dst) {
    int gp = nrow / H, o = nrow % H;
    int gate = (gp == 0) ? 0 : (gp + 1);   // gates {0,2,3}
    float w = 0.0f;
    if (kk < 3 * F) {
        int kc = kk / F, f = kk % F;
        w = Wx[(((size_t)gate * 3 + kc) * F + f) * H + o];
    }
    dst[(size_t)nrow * Kp + kk] = __float2half_rn(w);
}

__device__ __forceinline__ void prep_linB(const float* __restrict__ W, int Hout,
                                          int Kp, int nrow, int kk,
                                          __half* __restrict__ dst) {
    dst[(size_t)nrow * Kp + kk] = __float2half_rn(W[(size_t)kk * Hout + nrow]);
}

#define E1 24576     // 768*32
#define E2 172032    // +384*384
#define E3 208896    // +192*192
#define E4 241664    // +128*256
#define E5 249856    // +64*128
#define E6 251200    // +1344 biases

__global__ void k_prep_all(
    const float* __restrict__ w1, const float* __restrict__ w2, const float* __restrict__ w3,
    const float* __restrict__ wl1, const float* __restrict__ wl2,
    const float* __restrict__ bx1, const float* __restrict__ bh1, const float* __restrict__ b1,
    const float* __restrict__ bx2, const float* __restrict__ bh2, const float* __restrict__ b2,
    const float* __restrict__ bx3, const float* __restrict__ bh3, const float* __restrict__ b3) {
    int idx = blockIdx.x * blockDim.x + threadIdx.x;
    if (idx >= E6) return;
    if (idx < E1) {
        prep_gateB(w1, 3, 256, 32, idx / 32, idx % 32, g_bbuf + O_B1);
    } else if (idx < E2) {
        int t = idx - E1;
        prep_gateB(w2, 128, 128, 384, t / 384, t % 384, g_bbuf + O_B2);
    } else if (idx < E3) {
        int t = idx - E2;
        prep_gateB(w3, 64, 64, 192, t / 192, t % 192, g_bbuf + O_B3);
    } else if (idx < E4) {
        int t = idx - E3;
        prep_linB(wl1, 128, 256, t / 256, t % 256, g_bbuf + O_BL1);
    } else if (idx < E5) {
        int t = idx - E4;
        prep_linB(wl2, 64, 128, t / 128, t % 128, g_bbuf + O_BL2);
    } else {
        int t = idx - E5;
        const float *bx, *bh, *bb; int H, base;
        if (t < 768)       { bx = bx1; bh = bh1; bb = b1; H = 256; base = 0; }
        else if (t < 1152) { bx = bx2; bh = bh2; bb = b2; H = 128; base = 768; t -= 768; }
        else               { bx = bx3; bh = bh3; bb = b3; H = 64;  base = 1152; t -= 1152; }
        int gp = t / H, o = t % H;
        int gate = (gp == 0) ? 0 : (gp + 1);
        g_wbias[base + t] = bx[gate * H + o] + bh[gate * H + o] + bb[gate * H + o];
    }
}

// ====================== layer-1 cheb prep (F=3) ============================
// A row layout (Kp=32): hi [T0(0-2) T1(3-5) T2(6-8) 0(9-31)], lo at +32.

__global__ void k_l1a(const float* __restrict__ x, float* __restrict__ t1d,
                      __half* __restrict__ A2, int n, int npad) {
    int row = blockIdx.x * blockDim.x + threadIdx.x;
    if (row >= npad) return;
    float t0[3] = {0, 0, 0}, t1[3] = {0, 0, 0};
    if (row < n) {
        t0[0] = x[row * 3]; t0[1] = x[row * 3 + 1]; t0[2] = x[row * 3 + 2];
        int j0 = g_roff[row], j1 = g_roff[row + 1];
        for (int j = j0; j < j1; j++) {
            int sidx = g_csrc[j]; float w = g_cw[j];
            t1[0] += w * x[sidx * 3];
            t1[1] += w * x[sidx * 3 + 1];
            t1[2] += w * x[sidx * 3 + 2];
        }
        t1d[row * 3] = t1[0]; t1d[row * 3 + 1] = t1[1]; t1d[row * 3 + 2] = t1[2];
    }
    size_t base = (size_t)row * 64;
    __half hi, lo;
#pragma unroll
    for (int k = 0; k < 3; k++) {
        hsplit(t0[k], hi, lo);
        A2[base + k] = hi; A2[base + 32 + k] = lo;
        hsplit(t1[k], hi, lo);
        A2[base + 3 + k] = hi; A2[base + 35 + k] = lo;
    }
#pragma unroll
    for (int k = 9; k < 32; k++) {
        A2[base + k] = __float2half(0.f);
        A2[base + 32 + k] = __float2half(0.f);
    }
}

__global__ void k_l1b(const float* __restrict__ t1d, const float* __restrict__ x,
                      __half* __restrict__ A2, int n, int npad) {
    int row = blockIdx.x * blockDim.x + threadIdx.x;
    if (row >= npad) return;
    float t2[3] = {0, 0, 0};
    if (row < n) {
        int j0 = g_roff[row], j1 = g_roff[row + 1];
        for (int j = j0; j < j1; j++) {
            int sidx = g_csrc[j]; float w = g_cw[j];
            t2[0] += w * t1d[sidx * 3];
            t2[1] += w * t1d[sidx * 3 + 1];
            t2[2] += w * t1d[sidx * 3 + 2];
        }
        t2[0] = 2.f * t2[0] - x[row * 3];
        t2[1] = 2.f * t2[1] - x[row * 3 + 1];
        t2[2] = 2.f * t2[2] - x[row * 3 + 2];
    }
    size_t base = (size_t)row * 64;
    __half hi, lo;
#pragma unroll
    for (int k = 0; k < 3; k++) {
        hsplit(t2[k], hi, lo);
        A2[base + 6 + k] = hi; A2[base + 38 + k] = lo;
    }
}

// ====================== fused SpMV + split =================================

template <int F, int CHEB2>
__global__ void k_spmv_split(const float* __restrict__ X, const float* __restrict__ X0,
                             float* __restrict__ Yd,
                             __half* __restrict__ A2, int Kp, int sec,
                             int n, int npad) {
    const int TPR = F / 4;
    int tid = threadIdx.x;
    int row = blockIdx.x * (256 / TPR) + tid / TPR;
    int f = (tid % TPR) * 4;
    if (row >= npad) return;
    float a0 = 0.f, a1 = 0.f, a2 = 0.f, a3 = 0.f;
    if (row < n) {
        int j0 = g_roff[row], j1 = g_roff[row + 1];
        for (int j = j0; j < j1; j++) {
            int sidx = g_csrc[j]; float w = g_cw[j];
            float4 xv = *reinterpret_cast<const float4*>(X + (size_t)sidx * F + f);
            a0 += w * xv.x; a1 += w * xv.y; a2 += w * xv.z; a3 += w * xv.w;
        }
        if (CHEB2) {
            float4 x0 = *reinterpret_cast<const float4*>(X0 + (size_t)row * F + f);
            a0 = 2.f * a0 - x0.x; a1 = 2.f * a1 - x0.y;
            a2 = 2.f * a2 - x0.z; a3 = 2.f * a3 - x0.w;
        }
        if (Yd)
            *reinterpret_cast<float4*>(Yd + (size_t)row * F + f) = make_float4(a0, a1, a2, a3);
    }
    __half h0, l0, h1, l1, h2, l2, h3, l3;
    hsplit(a0, h0, l0); hsplit(a1, h1, l1); hsplit(a2, h2, l2); hsplit(a3, h3, l3);
    size_t base = (size_t)row * 2 * Kp + sec + f;
    __half2* ph = reinterpret_cast<__half2*>(A2 + base);
    ph[0] = __halves2half2(h0, h1); ph[1] = __halves2half2(h2, h3);
    __half2* pl = reinterpret_cast<__half2*>(A2 + base + Kp);
    pl[0] = __halves2half2(l0, l1); pl[1] = __halves2half2(l2, l3);
}

// ====================== mma.sync split-fp16 GEMM ===========================
// C[M,Nc] = A @ B^T, A=[Ahi|Alo] (stride 2*Kp), B single fp16 (stride Kp).
// acc += Ahi*B + Alo*B. CTA 128x64, BK=32, 8 warps (4x2), 3-stage cp.async.

#define CP16(dst, src) \
    asm volatile("cp.async.ca.shared.global [%0], [%1], 16;\n" :: "r"(dst), "l"(src))
#define CP_COMMIT() asm volatile("cp.async.commit_group;\n" ::: "memory")
#define CP_WAIT1()  asm volatile("cp.async.wait_group 1;\n" ::: "memory")
#define CP_WAIT0()  asm volatile("cp.async.wait_group 0;\n" ::: "memory")

__device__ __forceinline__ uint32_t smem_u32(const void* p) {
    uint32_t a;
    asm("{ .reg .u64 t; cvta.to.shared.u64 t, %1; cvt.u32.u64 %0, t; }"
        : "=r"(a) : "l"(p));
    return a;
}

__device__ __forceinline__ void ldm_x4(uint32_t* r, uint32_t addr) {
    asm volatile("ldmatrix.sync.aligned.m8n8.x4.shared.b16 {%0,%1,%2,%3}, [%4];"
                 : "=r"(r[0]), "=r"(r[1]), "=r"(r[2]), "=r"(r[3]) : "r"(addr));
}

__device__ __forceinline__ void mma16816h(float* c, const uint32_t* a, const uint32_t* b) {
    asm volatile(
        "mma.sync.aligned.m16n8k16.row.col.f32.f16.f16.f32 "
        "{%0,%1,%2,%3}, {%4,%5,%6,%7}, {%8,%9}, {%0,%1,%2,%3};"
        : "+f"(c[0]), "+f"(c[1]), "+f"(c[2]), "+f"(c[3])
        : "r"(a[0]), "r"(a[1]), "r"(a[2]), "r"(a[3]), "r"(b[0]), "r"(b[1]));
}

// stage layout (80B rows): A-hi 0-127, A-lo 128-255, B 256-319.
// Stage = 320*80 = 25600B, 3 stages = 76800B.
#define GSTAGE 25600

__global__ __launch_bounds__(256, 2) void gemm_mma2(
    const __half* __restrict__ A, const __half* __restrict__ B,
    const float* __restrict__ bias, void* __restrict__ Cout, int halfOut,
    __half* __restrict__ S, int sKp,
    int M, int Kp, int Nc, int act) {
    extern __shared__ char smem[];
    const uint32_t s0 = smem_u32(smem);
    const int tid = threadIdx.x;
    const int wid = tid >> 5;
    const int lane = tid & 31;
    const int wm = wid & 3, wn = wid >> 2;
    const int bn = blockIdx.x << 6;
    const int bm = blockIdx.y << 7;
    const size_t strA = 2 * (size_t)Kp;

    float acc[2][4][4];
#pragma unroll
    for (int i = 0; i < 2; i++)
#pragma unroll
        for (int j = 0; j < 4; j++)
#pragma unroll
            for (int k = 0; k < 4; k++) acc[i][j][k] = 0.f;

#define LOAD_STAGE(stg, kc) do {                                             \
    uint32_t dstBase = s0 + (stg) * GSTAGE;                                  \
    _Pragma("unroll")                                                        \
    for (int u = tid; u < 1280; u += 256) {                                  \
        uint32_t d; const char* g;                                           \
        if (u < 1024) {                                                      \
            int hl = u >> 9, t = u & 511, row = t >> 2, seg = t & 3;         \
            d = dstBase + (hl * 128 + row) * 80 + seg * 16;                  \
            g = (const char*)A + ((size_t)(bm + row) * strA                  \
                + (size_t)hl * Kp + (kc)) * 2 + seg * 16;                    \
        } else {                                                             \
            int t = u - 1024; int row = t >> 2, seg = t & 3;                 \
            d = dstBase + (256 + row) * 80 + seg * 16;                       \
            g = (const char*)B + ((size_t)(bn + row) * Kp + (kc)) * 2        \
                + seg * 16;                                                  \
        }                                                                    \
        CP16(d, g);                                                          \
    } } while (0)

    const int nK = Kp >> 5;
    LOAD_STAGE(0, 0);
    CP_COMMIT();
    if (nK > 1) { LOAD_STAGE(1, 32); CP_COMMIT(); }

    for (int kt = 0; kt < nK; kt++) {
        if (kt + 1 < nK) CP_WAIT1(); else CP_WAIT0();
        __syncthreads();
        if (kt + 2 < nK) {
            LOAD_STAGE((kt + 2) % 3, (kt + 2) << 5);
            CP_COMMIT();
        }
        uint32_t base = s0 + (kt % 3) * GSTAGE;
        uint32_t kb = (lane >> 4) * 16;
        uint32_t arow = wm * 32 + (lane & 15);
        uint32_t brow = 256 + wn * 32 + (lane & 15);
#pragma unroll
        for (int kk = 0; kk < 2; kk++) {
            uint32_t a_hi[2][4], a_lo[2][4];
#pragma unroll
            for (int mt = 0; mt < 2; mt++) {
                ldm_x4(a_hi[mt], base + (arow + mt * 16) * 80 + kk * 32 + kb);
                ldm_x4(a_lo[mt], base + (arow + mt * 16 + 128) * 80 + kk * 32 + kb);
            }
            uint32_t b[4][2];
#pragma unroll
            for (int j = 0; j < 2; j++) {
                uint32_t r[4];
                ldm_x4(r, base + (brow + j * 16) * 80 + kk * 32 + kb);
                b[2 * j][0] = r[0]; b[2 * j][1] = r[2];
                b[2 * j + 1][0] = r[1]; b[2 * j + 1][1] = r[3];
            }
#pragma unroll
            for (int mt = 0; mt < 2; mt++)
#pragma unroll
                for (int nt = 0; nt < 4; nt++) {
                    mma16816h(acc[mt][nt], a_hi[mt], b[nt]);
                    mma16816h(acc[mt][nt], a_lo[mt], b[nt]);
                }
        }
    }

    // epilogue
    const int gid = lane >> 2, tig = lane & 3;
#pragma unroll
    for (int mt = 0; mt < 2; mt++) {
#pragma unroll
        for (int half = 0; half < 2; half++) {
            int row = bm + wm * 32 + mt * 16 + half * 8 + gid;
            bool valid = row < M;
#pragma unroll
            for (int nt = 0; nt < 4; nt++) {
                int col = bn + wn * 32 + nt * 8 + tig * 2;
                float v0 = 0.f, v1 = 0.f;
                if (valid) {
                    v0 = acc[mt][nt][2 * half + 0] + bias[col];
                    v1 = acc[mt][nt][2 * half + 1] + bias[col + 1];
                    if (act) {
                        v0 = v0 > 0.f ? v0 : 0.1f * v0;
                        v1 = v1 > 0.f ? v1 : 0.1f * v1;
                    }
                    if (halfOut) {
                        *reinterpret_cast<__half2*>(
                            (__half*)Cout + (size_t)row * Nc + col) =
                            __floats2half2_rn(v0, v1);
                    } else {
                        *reinterpret_cast<float2*>(
                            (float*)Cout + (size_t)row * Nc + col) =
                            make_float2(v0, v1);
                    }
                }
                if (S) {
                    __half h0, l0, h1, l1;
                    hsplit(v0, h0, l0); hsplit(v1, h1, l1);
                    size_t sb = (size_t)row * 2 * sKp + col;
                    *reinterpret_cast<__half2*>(S + sb) = __halves2half2(h0, h1);
                    *reinterpret_cast<__half2*>(S + sb + sKp) = __halves2half2(l0, l1);
                }
            }
        }
    }
}

// ====================== LSTM gate fusion ===================================

__device__ __forceinline__ float sigf(float x) { return 1.0f / (1.0f + expf(-x)); }

__device__ __forceinline__ float gate_eval_h(const __half* g, const float* wcO, int H, int o) {
    float I = sigf(__half2float(g[o]));
    float T = tanhf(__half2float(g[H + o]));
    float Cv = I * T;
    float O = sigf(__half2float(g[2 * H + o]) + wcO[o] * Cv);
    float y = O * tanhf(Cv);
    return y > 0.f ? y : 0.1f * y;   // fused leaky relu
}

__global__ void k_gates(const __half* __restrict__ G, const float* __restrict__ wcO,
                        float* __restrict__ Y, int n, int H) {
    int idx = blockIdx.x * blockDim.x + threadIdx.x;
    if (idx >= n * H) return;
    int r = idx / H, o = idx % H;
    Y[(size_t)r * H + o] = gate_eval_h(G + (size_t)r * 3 * H, wcO, H, o);
}

// gates -> [hi|lo] split A (Kp == H)
__global__ void k_gates_split(const __half* __restrict__ G, const float* __restrict__ wcO,
                              __half* __restrict__ A2, int n, int npad, int H) {
    int idx = blockIdx.x * blockDim.x + threadIdx.x;
    if (idx >= npad * H) return;
    int r = idx / H, o = idx % H;
    float y = 0.0f;
    if (r < n) y = gate_eval_h(G + (size_t)r * 3 * H, wcO, H, o);
    __half hi, lo; hsplit(y, hi, lo);
    size_t base = (size_t)r * 2 * H;
    A2[base + o] = hi;
    A2[base + H + o] = lo;
}

// ====================== final small GEMM [N,64]@[64,3] =====================

__global__ void k_lin3(const float* __restrict__ Hin, const float* __restrict__ W,
                       const float* __restrict__ b, float* __restrict__ out, int n) {
    __shared__ float w[64 * 3];
    if (threadIdx.x < 192) w[threadIdx.x] = W[threadIdx.x];
    __syncthreads();
    int r = blockIdx.x * blockDim.x + threadIdx.x;
    if (r >= n) return;
    float a0 = b[0], a1 = b[1], a2 = b[2];
    const float* h = Hin + (size_t)r * 64;
#pragma unroll
    for (int k = 0; k < 64; k++) {
        float hv = h[k];
        a0 += hv * w[k * 3 + 0];
        a1 += hv * w[k * 3 + 1];
        a2 += hv * w[k * 3 + 2];
    }
    float* o = out + (size_t)r * 3;
    o[0] = a0; o[1] = a1; o[2] = a2;
}

// ====================== host orchestration =================================

static inline int ceildiv(int a, int b) { return (a + b - 1) / b; }

extern "C" void kernel_launch(void* const* d_in, const int* in_sizes, int n_in,
                              void* d_out, int out_size) {
    const float* x = (const float*)d_in[0];
    const int* ei = (const int*)d_in[1];
    int N = in_sizes[0] / 3;
    int E = in_sizes[1] / 2;
    const int* src = ei;
    const int* dst = ei + E;
    int Npad = (N + 127) & ~127;
    int Mt = Npad / 128;

    const float* l1_Wx = (const float*)d_in[2];
    const float* l1_bx = (const float*)d_in[3];
    const float* l1_bh = (const float*)d_in[5];
    const float* l1_wc = (const float*)d_in[6];
    const float* l1_b  = (const float*)d_in[7];
    const float* l2_Wx = (const float*)d_in[8];
    const float* l2_bx = (const float*)d_in[9];
    const float* l2_bh = (const float*)d_in[11];
    const float* l2_wc = (const float*)d_in[12];
    const float* l2_b  = (const float*)d_in[13];
    const float* l3_Wx = (const float*)d_in[14];
    const float* l3_bx = (const float*)d_in[15];
    const float* l3_bh = (const float*)d_in[17];
    const float* l3_wc = (const float*)d_in[18];
    const float* l3_b  = (const float*)d_in[19];
    const float* lin1_W = (const float*)d_in[20];
    const float* lin1_b = (const float*)d_in[21];
    const float* lin2_W = (const float*)d_in[22];
    const float* lin2_b = (const float*)d_in[23];
    const float* lin3_W = (const float*)d_in[24];
    const float* lin3_b = (const float*)d_in[25];
    float* out = (float*)d_out;

    void* p;
    cudaGetSymbolAddress(&p, g_tmp);   int* tmp = (int*)p;
    cudaGetSymbolAddress(&p, g_xc);    float* xc = (float*)p;
    cudaGetSymbolAddress(&p, g_gate);  __half* G = (__half*)p;
    cudaGetSymbolAddress(&p, g_h);     float* Hbuf = (float*)p;
    cudaGetSymbolAddress(&p, g_h2);    float* H2 = (float*)p;
    cudaGetSymbolAddress(&p, g_wbias); float* wb = (float*)p;
    cudaGetSymbolAddress(&p, g_bufA);  __half* bufA = (__half*)p;
    cudaGetSymbolAddress(&p, g_bufB);  __half* bufB = (__half*)p;
    cudaGetSymbolAddress(&p, g_bbuf);  __half* bb = (__half*)p;

    cudaFuncSetAttribute(gemm_mma2, cudaFuncAttributeMaxDynamicSharedMemorySize,
                         3 * GSTAGE);

    cudaStream_t s = 0;

    // ---- graph preprocessing ----
    cudaMemsetAsync(tmp, 0, 3 * MAXN * sizeof(int), s);
    k_degree<<<ceildiv(E, 256), 256, 0, s>>>(src, dst, E);
    k_scan<<<1, 1024, 0, s>>>(N);
    k_fill<<<ceildiv(E, 256), 256, 0, s>>>(src, dst, E);

    // ---- all weight/bias preprocessing in one kernel ----
    k_prep_all<<<ceildiv(E6, 256), 256, 0, s>>>(
        l1_Wx, l2_Wx, l3_Wx, lin1_W, lin2_W,
        l1_bx, l1_bh, l1_b, l2_bx, l2_bh, l2_b, l3_bx, l3_bh, l3_b);

    // ================= layer 1 (F=3, H=256) =================
    k_l1a<<<ceildiv(Npad, 256), 256, 0, s>>>(x, xc, bufA, N, Npad);
    k_l1b<<<ceildiv(Npad, 256), 256, 0, s>>>(xc, x, bufA, N, Npad);
    gemm_mma2<<<dim3(768 / 64, Mt), 256, 3 * GSTAGE, s>>>(
        bufA, bb + O_B1, wb, G, 1, nullptr, 0, N, 32, 768, 0);
    k_gates_split<<<ceildiv(Npad * 256, 256), 256, 0, s>>>(G, l1_wc + 512, bufB, N, Npad, 256);
    // lin1: [N,256]@[256,128] + lrelu, fused split of T0 (layer2 Kp=384)
    gemm_mma2<<<dim3(128 / 64, Mt), 256, 3 * GSTAGE, s>>>(
        bufB, bb + O_BL1, lin1_b, H2, 0, bufA, 384, N, 256, 128, 1);

    // ================= layer 2 (F=128, H=128) =================
    k_spmv_split<128, 0><<<ceildiv(Npad, 8), 256, 0, s>>>(H2, nullptr, xc, bufA, 384, 128, N, Npad);
    k_spmv_split<128, 1><<<ceildiv(Npad, 8), 256, 0, s>>>(xc, H2, nullptr, bufA, 384, 256, N, Npad);
    gemm_mma2<<<dim3(384 / 64, Mt), 256, 3 * GSTAGE, s>>>(
        bufA, bb + O_B2, wb + 768, G, 1, nullptr, 0, N, 384, 384, 0);
    k_gates_split<<<ceildiv(Npad * 128, 256), 256, 0, s>>>(G, l2_wc + 256, bufB, N, Npad, 128);
    // lin2: [N,128]@[128,64] + lrelu, fused split of T0 (layer3 Kp=192)
    gemm_mma2<<<dim3(64 / 64, Mt), 256, 3 * GSTAGE, s>>>(
        bufB, bb + O_BL2, lin2_b, H2, 0, bufA, 192, N, 128, 64, 1);

    // ================= layer 3 (F=64, H=64) =================
    k_spmv_split<64, 0><<<ceildiv(Npad, 16), 256, 0, s>>>(H2, nullptr, xc, bufA, 192, 64, N, Npad);
    k_spmv_split<64, 1><<<ceildiv(Npad, 16), 256, 0, s>>>(xc, H2, nullptr, bufA, 192, 128, N, Npad);
    gemm_mma2<<<dim3(192 / 64, Mt), 256, 3 * GSTAGE, s>>>(
        bufA, bb + O_B3, wb + 1152, G, 1, nullptr, 0, N, 192, 192, 0);
    k_gates<<<ceildiv(N * 64, 256), 256, 0, s>>>(G, l3_wc + 128, Hbuf, N, 64);
    k_lin3<<<ceildiv(N, 256), 256, 0, s>>>(Hbuf, lin3_W, lin3_b, out, N);
}

// round 7
// speedup vs baseline: 1.5379x; 1.3608x over previous
#include <cuda_runtime.h>
#include <cuda_fp16.h>
#include <math.h>
#include <stdint.h>

// ---------------- problem-size caps (fixed by setup_inputs) ----------------
#define MAXN 50000
#define NPADMAX 50048   // MAXN rounded up to 128

// ---------------- device scratch (no allocation allowed) -------------------
__device__ int   g_tmp[3 * MAXN];    // deg | cnt | cur (one memset)
__device__ int   g_roff[MAXN + 1];
__device__ int   g_csrc[800000];
__device__ float g_cw[800000];
__device__ float g_xc[(size_t)MAXN * 384];     // dense Tx1 scratch (fp16 view) / l1 fp32
__device__ float g_gate[(size_t)MAXN * 768];   // gate pre-activations (fp16 view)
__device__ float g_h[(size_t)MAXN * 64];       // layer3 gconv output fp32
__device__ float g_h2[(size_t)MAXN * 128];     // post-linear output (fp16 view)
__device__ float g_wbias[1344];                // combined gate biases (l1|l2|l3)
__device__ __align__(256) __half g_bufA[(size_t)NPADMAX * 384]; // gconv A (single)
__device__ __align__(256) __half g_bufB[(size_t)NPADMAX * 256]; // lin A (single)
__device__ __align__(256) __half g_bbuf[262144];                // all weights fp16

// weight buffer element offsets (rows x Kp, single fp16)
#define O_B1  0        // l1 gate: 768 x 32
#define O_B2  24576    // l2 gate: 384 x 384
#define O_B3  172032   // l3 gate: 192 x 192
#define O_BL1 208896   // lin1: 128 x 256
#define O_BL2 241664   // lin2: 64 x 128

// ====================== graph preprocessing ================================

__global__ void k_degree(const int* __restrict__ src, const int* __restrict__ dst, int E) {
    int e = blockIdx.x * blockDim.x + threadIdx.x;
    if (e >= E) return;
    atomicAdd(&g_tmp[src[e]], 1);            // deg
    atomicAdd(&g_tmp[MAXN + dst[e]], 1);     // cnt
}

__global__ void k_scan(int n) {
    __shared__ int ssum[1024];
    int tid = threadIdx.x;
    const int T = 1024;
    int chunk = (n + T - 1) / T;
    int beg = tid * chunk;
    int end = beg + chunk; if (end > n) end = n;
    int s = 0;
    for (int i = beg; i < end; i++) s += g_tmp[MAXN + i];
    ssum[tid] = s;
    __syncthreads();
    for (int off = 1; off < T; off <<= 1) {
        int v = (tid >= off) ? ssum[tid - off] : 0;
        __syncthreads();
        ssum[tid] += v;
        __syncthreads();
    }
    int run = (tid > 0) ? ssum[tid - 1] : 0;
    for (int i = beg; i < end; i++) { g_roff[i] = run; run += g_tmp[MAXN + i]; }
    if (tid == T - 1) g_roff[n] = ssum[T - 1];
}

__global__ void k_fill(const int* __restrict__ src, const int* __restrict__ dst, int E) {
    int e = blockIdx.x * blockDim.x + threadIdx.x;
    if (e >= E) return;
    int s = src[e], d = dst[e];
    int pos = g_roff[d] + atomicAdd(&g_tmp[2 * MAXN + d], 1);
    int ds = g_tmp[s], dd = g_tmp[d];
    float is = ds > 0 ? rsqrtf((float)ds) : 0.0f;
    float id = dd > 0 ? rsqrtf((float)dd) : 0.0f;
    g_csrc[pos] = s;
    g_cw[pos] = -is * id;
}

// ====================== merged weight/bias preprocessing ===================

__device__ __forceinline__ void prep_gateB(const float* __restrict__ Wx, int F, int H,
                                           int Kp, int nrow, int kk,
                                           __half* __restrict__ dst) {
    int gp = nrow / H, o = nrow % H;
    int gate = (gp == 0) ? 0 : (gp + 1);   // gates {0,2,3}
    float w = 0.0f;
    if (kk < 3 * F) {
        int kc = kk / F, f = kk % F;
        w = Wx[(((size_t)gate * 3 + kc) * F + f) * H + o];
    }
    dst[(size_t)nrow * Kp + kk] = __float2half_rn(w);
}

__device__ __forceinline__ void prep_linB(const float* __restrict__ W, int Hout,
                                          int Kp, int nrow, int kk,
                                          __half* __restrict__ dst) {
    dst[(size_t)nrow * Kp + kk] = __float2half_rn(W[(size_t)kk * Hout + nrow]);
}

#define E1 24576     // 768*32
#define E2 172032    // +384*384
#define E3 208896    // +192*192
#define E4 241664    // +128*256
#define E5 249856    // +64*128
#define E6 251200    // +1344 biases

__global__ void k_prep_all(
    const float* __restrict__ w1, const float* __restrict__ w2, const float* __restrict__ w3,
    const float* __restrict__ wl1, const float* __restrict__ wl2,
    const float* __restrict__ bx1, const float* __restrict__ bh1, const float* __restrict__ b1,
    const float* __restrict__ bx2, const float* __restrict__ bh2, const float* __restrict__ b2,
    const float* __restrict__ bx3, const float* __restrict__ bh3, const float* __restrict__ b3) {
    int idx = blockIdx.x * blockDim.x + threadIdx.x;
    if (idx >= E6) return;
    if (idx < E1) {
        prep_gateB(w1, 3, 256, 32, idx / 32, idx % 32, g_bbuf + O_B1);
    } else if (idx < E2) {
        int t = idx - E1;
        prep_gateB(w2, 128, 128, 384, t / 384, t % 384, g_bbuf + O_B2);
    } else if (idx < E3) {
        int t = idx - E2;
        prep_gateB(w3, 64, 64, 192, t / 192, t % 192, g_bbuf + O_B3);
    } else if (idx < E4) {
        int t = idx - E3;
        prep_linB(wl1, 128, 256, t / 256, t % 256, g_bbuf + O_BL1);
    } else if (idx < E5) {
        int t = idx - E4;
        prep_linB(wl2, 64, 128, t / 128, t % 128, g_bbuf + O_BL2);
    } else {
        int t = idx - E5;
        const float *bx, *bh, *bb; int H, base;
        if (t < 768)       { bx = bx1; bh = bh1; bb = b1; H = 256; base = 0; }
        else if (t < 1152) { bx = bx2; bh = bh2; bb = b2; H = 128; base = 768; t -= 768; }
        else               { bx = bx3; bh = bh3; bb = b3; H = 64;  base = 1152; t -= 1152; }
        int gp = t / H, o = t % H;
        int gate = (gp == 0) ? 0 : (gp + 1);
        g_wbias[base + t] = bx[gate * H + o] + bh[gate * H + o] + bb[gate * H + o];
    }
}

// ====================== layer-1 cheb prep (F=3) ============================
// A row layout (Kp=32): [T0(0-2) T1(3-5) T2(6-8) 0(9-31)] single fp16.

__global__ void k_l1a(const float* __restrict__ x, float* __restrict__ t1d,
                      __half* __restrict__ A2, int n, int npad) {
    int row = blockIdx.x * blockDim.x + threadIdx.x;
    if (row >= npad) return;
    float t0[3] = {0, 0, 0}, t1[3] = {0, 0, 0};
    if (row < n) {
        t0[0] = x[row * 3]; t0[1] = x[row * 3 + 1]; t0[2] = x[row * 3 + 2];
        int j0 = g_roff[row], j1 = g_roff[row + 1];
        for (int j = j0; j < j1; j++) {
            int sidx = g_csrc[j]; float w = g_cw[j];
            t1[0] += w * x[sidx * 3];
            t1[1] += w * x[sidx * 3 + 1];
            t1[2] += w * x[sidx * 3 + 2];
        }
        t1d[row * 3] = t1[0]; t1d[row * 3 + 1] = t1[1]; t1d[row * 3 + 2] = t1[2];
    }
    size_t base = (size_t)row * 32;
#pragma unroll
    for (int k = 0; k < 3; k++) {
        A2[base + k] = __float2half_rn(t0[k]);
        A2[base + 3 + k] = __float2half_rn(t1[k]);
    }
#pragma unroll
    for (int k = 9; k < 32; k++) A2[base + k] = __float2half(0.f);
}

__global__ void k_l1b(const float* __restrict__ t1d, const float* __restrict__ x,
                      __half* __restrict__ A2, int n, int npad) {
    int row = blockIdx.x * blockDim.x + threadIdx.x;
    if (row >= npad) return;
    float t2[3] = {0, 0, 0};
    if (row < n) {
        int j0 = g_roff[row], j1 = g_roff[row + 1];
        for (int j = j0; j < j1; j++) {
            int sidx = g_csrc[j]; float w = g_cw[j];
            t2[0] += w * t1d[sidx * 3];
            t2[1] += w * t1d[sidx * 3 + 1];
            t2[2] += w * t1d[sidx * 3 + 2];
        }
        t2[0] = 2.f * t2[0] - x[row * 3];
        t2[1] = 2.f * t2[1] - x[row * 3 + 1];
        t2[2] = 2.f * t2[2] - x[row * 3 + 2];
    }
    size_t base = (size_t)row * 32;
#pragma unroll
    for (int k = 0; k < 3; k++) A2[base + 6 + k] = __float2half_rn(t2[k]);
}

// ====================== fused SpMV + split (fp16 IO) =======================

template <int F, int CHEB2>
__global__ void k_spmv_split(const __half* __restrict__ X, const __half* __restrict__ X0,
                             __half* __restrict__ Yd,
                             __half* __restrict__ A2, int Kp, int sec,
                             int n, int npad) {
    const int TPR = F / 4;
    int tid = threadIdx.x;
    int row = blockIdx.x * (256 / TPR) + tid / TPR;
    int f = (tid % TPR) * 4;
    if (row >= npad) return;
    float a0 = 0.f, a1 = 0.f, a2 = 0.f, a3 = 0.f;
    if (row < n) {
        int j0 = g_roff[row], j1 = g_roff[row + 1];
        for (int j = j0; j < j1; j++) {
            int sidx = g_csrc[j]; float w = g_cw[j];
            float2 raw = *reinterpret_cast<const float2*>(X + (size_t)sidx * F + f);
            __half2 h01 = *reinterpret_cast<__half2*>(&raw.x);
            __half2 h23 = *reinterpret_cast<__half2*>(&raw.y);
            float2 f01 = __half22float2(h01), f23 = __half22float2(h23);
            a0 += w * f01.x; a1 += w * f01.y; a2 += w * f23.x; a3 += w * f23.y;
        }
        if (CHEB2) {
            float2 raw = *reinterpret_cast<const float2*>(X0 + (size_t)row * F + f);
            __half2 h01 = *reinterpret_cast<__half2*>(&raw.x);
            __half2 h23 = *reinterpret_cast<__half2*>(&raw.y);
            float2 f01 = __half22float2(h01), f23 = __half22float2(h23);
            a0 = 2.f * a0 - f01.x; a1 = 2.f * a1 - f01.y;
            a2 = 2.f * a2 - f23.x; a3 = 2.f * a3 - f23.y;
        }
    }
    float2 packed;
    *reinterpret_cast<__half2*>(&packed.x) = __floats2half2_rn(a0, a1);
    *reinterpret_cast<__half2*>(&packed.y) = __floats2half2_rn(a2, a3);
    if (Yd && row < n)
        *reinterpret_cast<float2*>(Yd + (size_t)row * F + f) = packed;
    *reinterpret_cast<float2*>(A2 + (size_t)row * Kp + sec + f) = packed;
}

// ====================== mma.sync fp16 GEMM =================================
// C[M,Nc] = A @ B^T, both single fp16, K-major (A stride Kp, B stride Kp).
// CTA 128x64, BK=32, 8 warps (4x2), 3-stage cp.async, one barrier/k-tile.

#define CP16(dst, src) \
    asm volatile("cp.async.ca.shared.global [%0], [%1], 16;\n" :: "r"(dst), "l"(src))
#define CP_COMMIT() asm volatile("cp.async.commit_group;\n" ::: "memory")
#define CP_WAIT1()  asm volatile("cp.async.wait_group 1;\n" ::: "memory")
#define CP_WAIT0()  asm volatile("cp.async.wait_group 0;\n" ::: "memory")

__device__ __forceinline__ uint32_t smem_u32(const void* p) {
    uint32_t a;
    asm("{ .reg .u64 t; cvta.to.shared.u64 t, %1; cvt.u32.u64 %0, t; }"
        : "=r"(a) : "l"(p));
    return a;
}

__device__ __forceinline__ void ldm_x4(uint32_t* r, uint32_t addr) {
    asm volatile("ldmatrix.sync.aligned.m8n8.x4.shared.b16 {%0,%1,%2,%3}, [%4];"
                 : "=r"(r[0]), "=r"(r[1]), "=r"(r[2]), "=r"(r[3]) : "r"(addr));
}

__device__ __forceinline__ void mma16816h(float* c, const uint32_t* a, const uint32_t* b) {
    asm volatile(
        "mma.sync.aligned.m16n8k16.row.col.f32.f16.f16.f32 "
        "{%0,%1,%2,%3}, {%4,%5,%6,%7}, {%8,%9}, {%0,%1,%2,%3};"
        : "+f"(c[0]), "+f"(c[1]), "+f"(c[2]), "+f"(c[3])
        : "r"(a[0]), "r"(a[1]), "r"(a[2]), "r"(a[3]), "r"(b[0]), "r"(b[1]));
}

// stage layout (80B rows): A rows 0-127, B rows 128-191.
// Stage = 192*80 = 15360B, 3 stages = 46080B.
#define GSTAGE 15360

__global__ __launch_bounds__(256, 2) void gemm_mma2(
    const __half* __restrict__ A, const __half* __restrict__ B,
    const float* __restrict__ bias, void* __restrict__ Cout, int halfOut,
    __half* __restrict__ S, int sKp,
    int M, int Kp, int Nc, int act) {
    extern __shared__ char smem[];
    const uint32_t s0 = smem_u32(smem);
    const int tid = threadIdx.x;
    const int wid = tid >> 5;
    const int lane = tid & 31;
    const int wm = wid & 3, wn = wid >> 2;
    const int bn = blockIdx.x << 6;
    const int bm = blockIdx.y << 7;

    float acc[2][4][4];
#pragma unroll
    for (int i = 0; i < 2; i++)
#pragma unroll
        for (int j = 0; j < 4; j++)
#pragma unroll
            for (int k = 0; k < 4; k++) acc[i][j][k] = 0.f;

#define LOAD_STAGE(stg, kc) do {                                             \
    uint32_t dstBase = s0 + (stg) * GSTAGE;                                  \
    _Pragma("unroll")                                                        \
    for (int u = tid; u < 768; u += 256) {                                   \
        uint32_t d; const char* g;                                           \
        if (u < 512) {                                                       \
            int row = u >> 2, seg = u & 3;                                   \
            d = dstBase + row * 80 + seg * 16;                               \
            g = (const char*)A + ((size_t)(bm + row) * Kp + (kc)) * 2        \
                + seg * 16;                                                  \
        } else {                                                             \
            int t = u - 512; int row = t >> 2, seg = t & 3;                  \
            d = dstBase + (128 + row) * 80 + seg * 16;                       \
            g = (const char*)B + ((size_t)(bn + row) * Kp + (kc)) * 2        \
                + seg * 16;                                                  \
        }                                                                    \
        CP16(d, g);                                                          \
    } } while (0)

    const int nK = Kp >> 5;
    LOAD_STAGE(0, 0);
    CP_COMMIT();
    if (nK > 1) { LOAD_STAGE(1, 32); CP_COMMIT(); }

    for (int kt = 0; kt < nK; kt++) {
        if (kt + 1 < nK) CP_WAIT1(); else CP_WAIT0();
        __syncthreads();
        if (kt + 2 < nK) {
            LOAD_STAGE((kt + 2) % 3, (kt + 2) << 5);
            CP_COMMIT();
        }
        uint32_t base = s0 + (kt % 3) * GSTAGE;
        uint32_t kb = (lane >> 4) * 16;
        uint32_t arow = wm * 32 + (lane & 15);
        uint32_t brow = 128 + wn * 32 + (lane & 15);
#pragma unroll
        for (int kk = 0; kk < 2; kk++) {
            uint32_t a[2][4];
#pragma unroll
            for (int mt = 0; mt < 2; mt++)
                ldm_x4(a[mt], base + (arow + mt * 16) * 80 + kk * 32 + kb);
            uint32_t b[4][2];
#pragma unroll
            for (int j = 0; j < 2; j++) {
                uint32_t r[4];
                ldm_x4(r, base + (brow + j * 16) * 80 + kk * 32 + kb);
                b[2 * j][0] = r[0]; b[2 * j][1] = r[2];
                b[2 * j + 1][0] = r[1]; b[2 * j + 1][1] = r[3];
            }
#pragma unroll
            for (int mt = 0; mt < 2; mt++)
#pragma unroll
                for (int nt = 0; nt < 4; nt++)
                    mma16816h(acc[mt][nt], a[mt], b[nt]);
        }
    }

    // epilogue
    const int gid = lane >> 2, tig = lane & 3;
#pragma unroll
    for (int mt = 0; mt < 2; mt++) {
#pragma unroll
        for (int half = 0; half < 2; half++) {
            int row = bm + wm * 32 + mt * 16 + half * 8 + gid;
            bool valid = row < M;
#pragma unroll
            for (int nt = 0; nt < 4; nt++) {
                int col = bn + wn * 32 + nt * 8 + tig * 2;
                float v0 = 0.f, v1 = 0.f;
                if (valid) {
                    v0 = acc[mt][nt][2 * half + 0] + bias[col];
                    v1 = acc[mt][nt][2 * half + 1] + bias[col + 1];
                    if (act) {
                        v0 = v0 > 0.f ? v0 : 0.1f * v0;
                        v1 = v1 > 0.f ? v1 : 0.1f * v1;
                    }
                    if (halfOut) {
                        *reinterpret_cast<__half2*>(
                            (__half*)Cout + (size_t)row * Nc + col) =
                            __floats2half2_rn(v0, v1);
                    } else {
                        *reinterpret_cast<float2*>(
                            (float*)Cout + (size_t)row * Nc + col) =
                            make_float2(v0, v1);
                    }
                }
                if (S) {
                    *reinterpret_cast<__half2*>(S + (size_t)row * sKp + col) =
                        __floats2half2_rn(v0, v1);
                }
            }
        }
    }
}

// ====================== LSTM gate fusion (fast math) =======================

__device__ __forceinline__ float fsig(float x) {
    return __fdividef(1.f, 1.f + __expf(-x));
}
__device__ __forceinline__ float ftanh(float x) {
    x = fminf(fmaxf(x, -20.f), 20.f);
    float e = __expf(2.f * x);
    return __fdividef(e - 1.f, e + 1.f);
}

__device__ __forceinline__ float gate_eval_h(const __half* g, const float* wcO, int H, int o) {
    float I = fsig(__half2float(g[o]));
    float T = ftanh(__half2float(g[H + o]));
    float Cv = I * T;
    float O = fsig(__half2float(g[2 * H + o]) + wcO[o] * Cv);
    float y = O * ftanh(Cv);
    return y > 0.f ? y : 0.1f * y;   // fused leaky relu
}

__global__ void k_gates(const __half* __restrict__ G, const float* __restrict__ wcO,
                        float* __restrict__ Y, int n, int H) {
    int idx = blockIdx.x * blockDim.x + threadIdx.x;
    if (idx >= n * H) return;
    int r = idx / H, o = idx % H;
    Y[(size_t)r * H + o] = gate_eval_h(G + (size_t)r * 3 * H, wcO, H, o);
}

// gates -> single fp16 A (stride H)
__global__ void k_gates_split(const __half* __restrict__ G, const float* __restrict__ wcO,
                              __half* __restrict__ A2, int n, int npad, int H) {
    int idx = blockIdx.x * blockDim.x + threadIdx.x;
    if (idx >= npad * H) return;
    int r = idx / H, o = idx % H;
    float y = 0.0f;
    if (r < n) y = gate_eval_h(G + (size_t)r * 3 * H, wcO, H, o);
    A2[(size_t)r * H + o] = __float2half_rn(y);
}

// ====================== final small GEMM [N,64]@[64,3] =====================

__global__ void k_lin3(const float* __restrict__ Hin, const float* __restrict__ W,
                       const float* __restrict__ b, float* __restrict__ out, int n) {
    __shared__ float w[64 * 3];
    if (threadIdx.x < 192) w[threadIdx.x] = W[threadIdx.x];
    __syncthreads();
    int r = blockIdx.x * blockDim.x + threadIdx.x;
    if (r >= n) return;
    float a0 = b[0], a1 = b[1], a2 = b[2];
    const float* h = Hin + (size_t)r * 64;
#pragma unroll
    for (int k = 0; k < 64; k++) {
        float hv = h[k];
        a0 += hv * w[k * 3 + 0];
        a1 += hv * w[k * 3 + 1];
        a2 += hv * w[k * 3 + 2];
    }
    float* o = out + (size_t)r * 3;
    o[0] = a0; o[1] = a1; o[2] = a2;
}

// ====================== host orchestration =================================

static inline int ceildiv(int a, int b) { return (a + b - 1) / b; }

extern "C" void kernel_launch(void* const* d_in, const int* in_sizes, int n_in,
                              void* d_out, int out_size) {
    const float* x = (const float*)d_in[0];
    const int* ei = (const int*)d_in[1];
    int N = in_sizes[0] / 3;
    int E = in_sizes[1] / 2;
    const int* src = ei;
    const int* dst = ei + E;
    int Npad = (N + 127) & ~127;
    int Mt = Npad / 128;

    const float* l1_Wx = (const float*)d_in[2];
    const float* l1_bx = (const float*)d_in[3];
    const float* l1_bh = (const float*)d_in[5];
    const float* l1_wc = (const float*)d_in[6];
    const float* l1_b  = (const float*)d_in[7];
    const float* l2_Wx = (const float*)d_in[8];
    const float* l2_bx = (const float*)d_in[9];
    const float* l2_bh = (const float*)d_in[11];
    const float* l2_wc = (const float*)d_in[12];
    const float* l2_b  = (const float*)d_in[13];
    const float* l3_Wx = (const float*)d_in[14];
    const float* l3_bx = (const float*)d_in[15];
    const float* l3_bh = (const float*)d_in[17];
    const float* l3_wc = (const float*)d_in[18];
    const float* l3_b  = (const float*)d_in[19];
    const float* lin1_W = (const float*)d_in[20];
    const float* lin1_b = (const float*)d_in[21];
    const float* lin2_W = (const float*)d_in[22];
    const float* lin2_b = (const float*)d_in[23];
    const float* lin3_W = (const float*)d_in[24];
    const float* lin3_b = (const float*)d_in[25];
    float* out = (float*)d_out;

    void* p;
    cudaGetSymbolAddress(&p, g_tmp);   int* tmp = (int*)p;
    cudaGetSymbolAddress(&p, g_xc);    float* xcf = (float*)p;
    __half* xch = (__half*)xcf;
    cudaGetSymbolAddress(&p, g_gate);  __half* G = (__half*)p;
    cudaGetSymbolAddress(&p, g_h);     float* Hbuf = (float*)p;
    cudaGetSymbolAddress(&p, g_h2);    __half* H2 = (__half*)p;
    cudaGetSymbolAddress(&p, g_wbias); float* wb = (float*)p;
    cudaGetSymbolAddress(&p, g_bufA);  __half* bufA = (__half*)p;
    cudaGetSymbolAddress(&p, g_bufB);  __half* bufB = (__half*)p;
    cudaGetSymbolAddress(&p, g_bbuf);  __half* bb = (__half*)p;

    cudaFuncSetAttribute(gemm_mma2, cudaFuncAttributeMaxDynamicSharedMemorySize,
                         3 * GSTAGE);

    cudaStream_t s = 0;

    // ---- graph preprocessing ----
    cudaMemsetAsync(tmp, 0, 3 * MAXN * sizeof(int), s);
    k_degree<<<ceildiv(E, 256), 256, 0, s>>>(src, dst, E);
    k_scan<<<1, 1024, 0, s>>>(N);
    k_fill<<<ceildiv(E, 256), 256, 0, s>>>(src, dst, E);

    // ---- all weight/bias preprocessing in one kernel ----
    k_prep_all<<<ceildiv(E6, 256), 256, 0, s>>>(
        l1_Wx, l2_Wx, l3_Wx, lin1_W, lin2_W,
        l1_bx, l1_bh, l1_b, l2_bx, l2_bh, l2_b, l3_bx, l3_bh, l3_b);

    // ================= layer 1 (F=3, H=256) =================
    k_l1a<<<ceildiv(Npad, 256), 256, 0, s>>>(x, xcf, bufA, N, Npad);
    k_l1b<<<ceildiv(Npad, 256), 256, 0, s>>>(xcf, x, bufA, N, Npad);
    gemm_mma2<<<dim3(768 / 64, Mt), 256, 3 * GSTAGE, s>>>(
        bufA, bb + O_B1, wb, G, 1, nullptr, 0, N, 32, 768, 0);
    k_gates_split<<<ceildiv(Npad * 256, 256), 256, 0, s>>>(G, l1_wc + 512, bufB, N, Npad, 256);
    // lin1: [N,256]@[256,128] + lrelu -> fp16 H2 + T0 section of layer2 A
    gemm_mma2<<<dim3(128 / 64, Mt), 256, 3 * GSTAGE, s>>>(
        bufB, bb + O_BL1, lin1_b, H2, 1, bufA, 384, N, 256, 128, 1);

    // ================= layer 2 (F=128, H=128) =================
    k_spmv_split<128, 0><<<ceildiv(Npad, 8), 256, 0, s>>>(H2, nullptr, xch, bufA, 384, 128, N, Npad);
    k_spmv_split<128, 1><<<ceildiv(Npad, 8), 256, 0, s>>>(xch, H2, nullptr, bufA, 384, 256, N, Npad);
    gemm_mma2<<<dim3(384 / 64, Mt), 256, 3 * GSTAGE, s>>>(
        bufA, bb + O_B2, wb + 768, G, 1, nullptr, 0, N, 384, 384, 0);
    k_gates_split<<<ceildiv(Npad * 128, 256), 256, 0, s>>>(G, l2_wc + 256, bufB, N, Npad, 128);
    // lin2: [N,128]@[128,64] + lrelu -> fp16 H2 + T0 section of layer3 A
    gemm_mma2<<<dim3(64 / 64, Mt), 256, 3 * GSTAGE, s>>>(
        bufB, bb + O_BL2, lin2_b, H2, 1, bufA, 192, N, 128, 64, 1);

    // ================= layer 3 (F=64, H=64) =================
    k_spmv_split<64, 0><<<ceildiv(Npad, 16), 256, 0, s>>>(H2, nullptr, xch, bufA, 192, 64, N, Npad);
    k_spmv_split<64, 1><<<ceildiv(Npad, 16), 256, 0, s>>>(xch, H2, nullptr, bufA, 192, 128, N, Npad);
    gemm_mma2<<<dim3(192 / 64, Mt), 256, 3 * GSTAGE, s>>>(
        bufA, bb + O_B3, wb + 1152, G, 1, nullptr, 0, N, 192, 192, 0);
    k_gates<<<ceildiv(N * 64, 256), 256, 0, s>>>(G, l3_wc + 128, Hbuf, N, 64);
    k_lin3<<<ceildiv(N, 256), 256, 0, s>>>(Hbuf, lin3_W, lin3_b, out, N);
}

// round 8
// speedup vs baseline: 1.7766x; 1.1552x over previous
#include <cuda_runtime.h>
#include <cuda_fp16.h>
#include <math.h>
#include <stdint.h>

// ---------------- problem-size caps (fixed by setup_inputs) ----------------
#define MAXN 50000
#define NPADMAX 50048   // MAXN rounded up to 128

// ---------------- device scratch (no allocation allowed) -------------------
__device__ int   g_tmp[3 * MAXN];    // deg | cnt | cur (one memset)
__device__ int   g_roff[MAXN + 1];
__device__ int2  g_edge[800000];     // packed (src, weight-bits)
__device__ float g_xc[(size_t)MAXN * 384];     // dense Tx1 scratch (fp16 view) / l1 fp32
__device__ float g_gate[(size_t)MAXN * 768];   // gate pre-activations (fp16 view)
__device__ float g_h2[(size_t)MAXN * 128];     // post-linear output (fp16 view)
__device__ float g_wbias[1344];                // combined gate biases (l1|l2|l3)
__device__ float g_w1t[9 * 768];               // layer1 gate weights transposed fp32
__device__ __align__(256) __half g_bufA[(size_t)NPADMAX * 384]; // gconv A (single)
__device__ __align__(256) __half g_bufB[(size_t)NPADMAX * 256]; // lin A (single)
__device__ __align__(256) __half g_bbuf[262144];                // weights fp16

// weight buffer element offsets (rows x Kp, single fp16)
#define O_B2  24576    // l2 gate: 384 x 384
#define O_B3  172032   // l3 gate: 192 x 192
#define O_BL1 208896   // lin1: 128 x 256
#define O_BL2 241664   // lin2: 64 x 128

// ====================== graph preprocessing ================================

__global__ void k_degree(const int* __restrict__ src, const int* __restrict__ dst, int E) {
    int e = blockIdx.x * blockDim.x + threadIdx.x;
    if (e >= E) return;
    atomicAdd(&g_tmp[src[e]], 1);            // deg
    atomicAdd(&g_tmp[MAXN + dst[e]], 1);     // cnt
}

__global__ void k_scan(int n) {
    __shared__ int ssum[1024];
    int tid = threadIdx.x;
    const int T = 1024;
    int chunk = (n + T - 1) / T;
    int beg = tid * chunk;
    int end = beg + chunk; if (end > n) end = n;
    int s = 0;
    for (int i = beg; i < end; i++) s += g_tmp[MAXN + i];
    ssum[tid] = s;
    __syncthreads();
    for (int off = 1; off < T; off <<= 1) {
        int v = (tid >= off) ? ssum[tid - off] : 0;
        __syncthreads();
        ssum[tid] += v;
        __syncthreads();
    }
    int run = (tid > 0) ? ssum[tid - 1] : 0;
    for (int i = beg; i < end; i++) { g_roff[i] = run; run += g_tmp[MAXN + i]; }
    if (tid == T - 1) g_roff[n] = ssum[T - 1];
}

__global__ void k_fill(const int* __restrict__ src, const int* __restrict__ dst, int E) {
    int e = blockIdx.x * blockDim.x + threadIdx.x;
    if (e >= E) return;
    int s = src[e], d = dst[e];
    int pos = g_roff[d] + atomicAdd(&g_tmp[2 * MAXN + d], 1);
    int ds = g_tmp[s], dd = g_tmp[d];
    float is = ds > 0 ? rsqrtf((float)ds) : 0.0f;
    float id = dd > 0 ? rsqrtf((float)dd) : 0.0f;
    g_edge[pos] = make_int2(s, __float_as_int(-is * id));
}

// ====================== merged weight/bias preprocessing ===================

__device__ __forceinline__ void prep_gateB(const float* __restrict__ Wx, int F, int H,
                                           int Kp, int nrow, int kk,
                                           __half* __restrict__ dst) {
    int gp = nrow / H, o = nrow % H;
    int gate = (gp == 0) ? 0 : (gp + 1);   // gates {0,2,3}
    float w = 0.0f;
    if (kk < 3 * F) {
        int kc = kk / F, f = kk % F;
        w = Wx[(((size_t)gate * 3 + kc) * F + f) * H + o];
    }
    dst[(size_t)nrow * Kp + kk] = __float2half_rn(w);
}

__device__ __forceinline__ void prep_linB(const float* __restrict__ W, int Hout,
                                          int Kp, int nrow, int kk,
                                          __half* __restrict__ dst) {
    dst[(size_t)nrow * Kp + kk] = __float2half_rn(W[(size_t)kk * Hout + nrow]);
}

#define E1 24576     // 768*32 (layer1 -> transposed fp32 table)
#define E2 172032    // +384*384
#define E3 208896    // +192*192
#define E4 241664    // +128*256
#define E5 249856    // +64*128
#define E6 251200    // +1344 biases

__global__ void k_prep_all(
    const float* __restrict__ w1, const float* __restrict__ w2, const float* __restrict__ w3,
    const float* __restrict__ wl1, const float* __restrict__ wl2,
    const float* __restrict__ bx1, const float* __restrict__ bh1, const float* __restrict__ b1,
    const float* __restrict__ bx2, const float* __restrict__ bh2, const float* __restrict__ b2,
    const float* __restrict__ bx3, const float* __restrict__ bh3, const float* __restrict__ b3) {
    int idx = blockIdx.x * blockDim.x + threadIdx.x;
    if (idx >= E6) return;
    if (idx < E1) {
        int nrow = idx / 32, kk = idx % 32;
        if (kk < 9) {
            int gp = nrow / 256, o = nrow % 256;
            int gate = (gp == 0) ? 0 : (gp + 1);
            int kc = kk / 3, f = kk % 3;
            g_w1t[kk * 768 + nrow] = w1[(((size_t)gate * 3 + kc) * 3 + f) * 256 + o];
        }
    } else if (idx < E2) {
        int t = idx - E1;
        prep_gateB(w2, 128, 128, 384, t / 384, t % 384, g_bbuf + O_B2);
    } else if (idx < E3) {
        int t = idx - E2;
        prep_gateB(w3, 64, 64, 192, t / 192, t % 192, g_bbuf + O_B3);
    } else if (idx < E4) {
        int t = idx - E3;
        prep_linB(wl1, 128, 256, t / 256, t % 256, g_bbuf + O_BL1);
    } else if (idx < E5) {
        int t = idx - E4;
        prep_linB(wl2, 64, 128, t / 128, t % 128, g_bbuf + O_BL2);
    } else {
        int t = idx - E5;
        const float *bx, *bh, *bb; int H, base;
        if (t < 768)       { bx = bx1; bh = bh1; bb = b1; H = 256; base = 0; }
        else if (t < 1152) { bx = bx2; bh = bh2; bb = b2; H = 128; base = 768; t -= 768; }
        else               { bx = bx3; bh = bh3; bb = b3; H = 64;  base = 1152; t -= 1152; }
        int gp = t / H, o = t % H;
        int gate = (gp == 0) ? 0 : (gp + 1);
        g_wbias[base + t] = bx[gate * H + o] + bh[gate * H + o] + bb[gate * H + o];
    }
}

// ====================== fast transcendentals ===============================

__device__ __forceinline__ float fsig(float x) {
    return __fdividef(1.f, 1.f + __expf(-x));
}
__device__ __forceinline__ float ftanh(float x) {
    x = fminf(fmaxf(x, -20.f), 20.f);
    float e = __expf(2.f * x);
    return __fdividef(e - 1.f, e + 1.f);
}

// ====================== layer-1: T1 dense pass =============================

__global__ void k_l1a(const float* __restrict__ x, float* __restrict__ t1d, int n) {
    int row = blockIdx.x * blockDim.x + threadIdx.x;
    if (row >= n) return;
    float t1[3] = {0, 0, 0};
    int j0 = g_roff[row], j1 = g_roff[row + 1];
    for (int j = j0; j < j1; j++) {
        int2 e = g_edge[j];
        float w = __int_as_float(e.y);
        const float* xr = x + (size_t)e.x * 3;
        t1[0] += w * xr[0]; t1[1] += w * xr[1]; t1[2] += w * xr[2];
    }
    t1d[row * 3] = t1[0]; t1d[row * 3 + 1] = t1[1]; t1d[row * 3 + 2] = t1[2];
}

// ====================== layer-1 fused: T2 gather + gates -> bufB ===========
// warp per row (8 rows/warp loop), weights in smem half2, units 2*lane+64*c.

__global__ __launch_bounds__(256) void k_l1gates(
    const float* __restrict__ x, const float* __restrict__ t1d,
    const float* __restrict__ wcO, __half* __restrict__ outA, int n, int npad) {
    __shared__ __half sW[9 * 768];
    __shared__ float sB[768];
    int tid = threadIdx.x;
    for (int i = tid; i < 9 * 768; i += 256) sW[i] = __float2half_rn(g_w1t[i]);
    for (int i = tid; i < 768; i += 256) sB[i] = g_wbias[i];
    __syncthreads();
    const __half2* sW2 = reinterpret_cast<const __half2*>(sW);
    int lane = tid & 31, w = tid >> 5;

    for (int rr = 0; rr < 8; rr++) {
        int r = blockIdx.x * 64 + w * 8 + rr;
        if (r >= npad) return;
        if (r >= n) {
#pragma unroll
            for (int c = 0; c < 4; c++)
                *reinterpret_cast<__half2*>(outA + (size_t)r * 256 + 2 * lane + 64 * c) =
                    __floats2half2_rn(0.f, 0.f);
            continue;
        }
        float p0 = 0.f, p1 = 0.f, p2 = 0.f;
        int j0 = g_roff[r], j1 = g_roff[r + 1];
        for (int j = j0 + lane; j < j1; j += 32) {
            int2 e = g_edge[j];
            float wgt = __int_as_float(e.y);
            const float* tr = t1d + (size_t)e.x * 3;
            p0 += wgt * tr[0]; p1 += wgt * tr[1]; p2 += wgt * tr[2];
        }
#pragma unroll
        for (int off = 16; off; off >>= 1) {
            p0 += __shfl_xor_sync(0xffffffffu, p0, off);
            p1 += __shfl_xor_sync(0xffffffffu, p1, off);
            p2 += __shfl_xor_sync(0xffffffffu, p2, off);
        }
        float a[9];
        a[0] = x[r * 3]; a[1] = x[r * 3 + 1]; a[2] = x[r * 3 + 2];
        a[3] = t1d[r * 3]; a[4] = t1d[r * 3 + 1]; a[5] = t1d[r * 3 + 2];
        a[6] = 2.f * p0 - a[0]; a[7] = 2.f * p1 - a[1]; a[8] = 2.f * p2 - a[2];

        float2 pi[4], pc[4], po[4];
#pragma unroll
        for (int c = 0; c < 4; c++) {
            int u = 2 * lane + 64 * c;
            pi[c] = make_float2(sB[u], sB[u + 1]);
            pc[c] = make_float2(sB[256 + u], sB[256 + u + 1]);
            po[c] = make_float2(sB[512 + u], sB[512 + u + 1]);
        }
#pragma unroll
        for (int k = 0; k < 9; k++) {
            float ak = a[k];
            int kb = k * 384;   // half2 units per k-row of sW
#pragma unroll
            for (int c = 0; c < 4; c++) {
                int h2i = lane + 32 * c;
                float2 wi = __half22float2(sW2[kb + h2i]);
                pi[c].x += ak * wi.x; pi[c].y += ak * wi.y;
                float2 wc2 = __half22float2(sW2[kb + 128 + h2i]);
                pc[c].x += ak * wc2.x; pc[c].y += ak * wc2.y;
                float2 wo = __half22float2(sW2[kb + 256 + h2i]);
                po[c].x += ak * wo.x; po[c].y += ak * wo.y;
            }
        }
#pragma unroll
        for (int c = 0; c < 4; c++) {
            int u = 2 * lane + 64 * c;
            float I0 = fsig(pi[c].x), T0 = ftanh(pc[c].x), C0 = I0 * T0;
            float O0 = fsig(po[c].x + wcO[u] * C0);
            float y0 = O0 * ftanh(C0); y0 = y0 > 0.f ? y0 : 0.1f * y0;
            float I1 = fsig(pi[c].y), T1 = ftanh(pc[c].y), C1 = I1 * T1;
            float O1 = fsig(po[c].y + wcO[u + 1] * C1);
            float y1 = O1 * ftanh(C1); y1 = y1 > 0.f ? y1 : 0.1f * y1;
            *reinterpret_cast<__half2*>(outA + (size_t)r * 256 + u) =
                __floats2half2_rn(y0, y1);
        }
    }
}

// ====================== fused SpMV + split (fp16 IO) =======================

template <int F, int CHEB2>
__global__ void k_spmv_split(const __half* __restrict__ X, const __half* __restrict__ X0,
                             __half* __restrict__ Yd,
                             __half* __restrict__ A2, int Kp, int sec,
                             int n, int npad) {
    const int TPR = F / 4;
    int tid = threadIdx.x;
    int row = blockIdx.x * (256 / TPR) + tid / TPR;
    int f = (tid % TPR) * 4;
    if (row >= npad) return;
    float a0 = 0.f, a1 = 0.f, a2 = 0.f, a3 = 0.f;
    if (row < n) {
        int j0 = g_roff[row], j1 = g_roff[row + 1];
        for (int j = j0; j < j1; j++) {
            int2 e = g_edge[j];
            float w = __int_as_float(e.y);
            float2 raw = *reinterpret_cast<const float2*>(X + (size_t)e.x * F + f);
            __half2 h01 = *reinterpret_cast<__half2*>(&raw.x);
            __half2 h23 = *reinterpret_cast<__half2*>(&raw.y);
            float2 f01 = __half22float2(h01), f23 = __half22float2(h23);
            a0 += w * f01.x; a1 += w * f01.y; a2 += w * f23.x; a3 += w * f23.y;
        }
        if (CHEB2) {
            float2 raw = *reinterpret_cast<const float2*>(X0 + (size_t)row * F + f);
            __half2 h01 = *reinterpret_cast<__half2*>(&raw.x);
            __half2 h23 = *reinterpret_cast<__half2*>(&raw.y);
            float2 f01 = __half22float2(h01), f23 = __half22float2(h23);
            a0 = 2.f * a0 - f01.x; a1 = 2.f * a1 - f01.y;
            a2 = 2.f * a2 - f23.x; a3 = 2.f * a3 - f23.y;
        }
    }
    float2 packed;
    *reinterpret_cast<__half2*>(&packed.x) = __floats2half2_rn(a0, a1);
    *reinterpret_cast<__half2*>(&packed.y) = __floats2half2_rn(a2, a3);
    if (Yd && row < n)
        *reinterpret_cast<float2*>(Yd + (size_t)row * F + f) = packed;
    *reinterpret_cast<float2*>(A2 + (size_t)row * Kp + sec + f) = packed;
}

// ====================== mma.sync fp16 GEMM =================================

#define CP16(dst, src) \
    asm volatile("cp.async.ca.shared.global [%0], [%1], 16;\n" :: "r"(dst), "l"(src))
#define CP_COMMIT() asm volatile("cp.async.commit_group;\n" ::: "memory")
#define CP_WAIT1()  asm volatile("cp.async.wait_group 1;\n" ::: "memory")
#define CP_WAIT0()  asm volatile("cp.async.wait_group 0;\n" ::: "memory")

__device__ __forceinline__ uint32_t smem_u32(const void* p) {
    uint32_t a;
    asm("{ .reg .u64 t; cvta.to.shared.u64 t, %1; cvt.u32.u64 %0, t; }"
        : "=r"(a) : "l"(p));
    return a;
}

__device__ __forceinline__ void ldm_x4(uint32_t* r, uint32_t addr) {
    asm volatile("ldmatrix.sync.aligned.m8n8.x4.shared.b16 {%0,%1,%2,%3}, [%4];"
                 : "=r"(r[0]), "=r"(r[1]), "=r"(r[2]), "=r"(r[3]) : "r"(addr));
}

__device__ __forceinline__ void mma16816h(float* c, const uint32_t* a, const uint32_t* b) {
    asm volatile(
        "mma.sync.aligned.m16n8k16.row.col.f32.f16.f16.f32 "
        "{%0,%1,%2,%3}, {%4,%5,%6,%7}, {%8,%9}, {%0,%1,%2,%3};"
        : "+f"(c[0]), "+f"(c[1]), "+f"(c[2]), "+f"(c[3])
        : "r"(a[0]), "r"(a[1]), "r"(a[2]), "r"(a[3]), "r"(b[0]), "r"(b[1]));
}

// stage layout (80B rows): A rows 0-127, B rows 128-191.
// Stage = 192*80 = 15360B, 3 stages = 46080B.
#define GSTAGE 15360

__global__ __launch_bounds__(256, 2) void gemm_mma2(
    const __half* __restrict__ A, const __half* __restrict__ B,
    const float* __restrict__ bias, void* __restrict__ Cout, int halfOut,
    __half* __restrict__ S, int sKp,
    int M, int Kp, int Nc, int act) {
    extern __shared__ char smem[];
    const uint32_t s0 = smem_u32(smem);
    const int tid = threadIdx.x;
    const int wid = tid >> 5;
    const int lane = tid & 31;
    const int wm = wid & 3, wn = wid >> 2;
    const int bn = blockIdx.x << 6;
    const int bm = blockIdx.y << 7;

    float acc[2][4][4];
#pragma unroll
    for (int i = 0; i < 2; i++)
#pragma unroll
        for (int j = 0; j < 4; j++)
#pragma unroll
            for (int k = 0; k < 4; k++) acc[i][j][k] = 0.f;

#define LOAD_STAGE(stg, kc) do {                                             \
    uint32_t dstBase = s0 + (stg) * GSTAGE;                                  \
    _Pragma("unroll")                                                        \
    for (int u = tid; u < 768; u += 256) {                                   \
        uint32_t d; const char* g;                                           \
        if (u < 512) {                                                       \
            int row = u >> 2, seg = u & 3;                                   \
            d = dstBase + row * 80 + seg * 16;                               \
            g = (const char*)A + ((size_t)(bm + row) * Kp + (kc)) * 2        \
                + seg * 16;                                                  \
        } else {                                                             \
            int t = u - 512; int row = t >> 2, seg = t & 3;                  \
            d = dstBase + (128 + row) * 80 + seg * 16;                       \
            g = (const char*)B + ((size_t)(bn + row) * Kp + (kc)) * 2        \
                + seg * 16;                                                  \
        }                                                                    \
        CP16(d, g);                                                          \
    } } while (0)

    const int nK = Kp >> 5;
    LOAD_STAGE(0, 0);
    CP_COMMIT();
    if (nK > 1) { LOAD_STAGE(1, 32); CP_COMMIT(); }

    for (int kt = 0; kt < nK; kt++) {
        if (kt + 1 < nK) CP_WAIT1(); else CP_WAIT0();
        __syncthreads();
        if (kt + 2 < nK) {
            LOAD_STAGE((kt + 2) % 3, (kt + 2) << 5);
            CP_COMMIT();
        }
        uint32_t base = s0 + (kt % 3) * GSTAGE;
        uint32_t kb = (lane >> 4) * 16;
        uint32_t arow = wm * 32 + (lane & 15);
        uint32_t brow = 128 + wn * 32 + (lane & 15);
#pragma unroll
        for (int kk = 0; kk < 2; kk++) {
            uint32_t a[2][4];
#pragma unroll
            for (int mt = 0; mt < 2; mt++)
                ldm_x4(a[mt], base + (arow + mt * 16) * 80 + kk * 32 + kb);
            uint32_t b[4][2];
#pragma unroll
            for (int j = 0; j < 2; j++) {
                uint32_t r[4];
                ldm_x4(r, base + (brow + j * 16) * 80 + kk * 32 + kb);
                b[2 * j][0] = r[0]; b[2 * j][1] = r[2];
                b[2 * j + 1][0] = r[1]; b[2 * j + 1][1] = r[3];
            }
#pragma unroll
            for (int mt = 0; mt < 2; mt++)
#pragma unroll
                for (int nt = 0; nt < 4; nt++)
                    mma16816h(acc[mt][nt], a[mt], b[nt]);
        }
    }

    // epilogue
    const int gid = lane >> 2, tig = lane & 3;
#pragma unroll
    for (int mt = 0; mt < 2; mt++) {
#pragma unroll
        for (int half = 0; half < 2; half++) {
            int row = bm + wm * 32 + mt * 16 + half * 8 + gid;
            bool valid = row < M;
#pragma unroll
            for (int nt = 0; nt < 4; nt++) {
                int col = bn + wn * 32 + nt * 8 + tig * 2;
                float v0 = 0.f, v1 = 0.f;
                if (valid) {
                    v0 = acc[mt][nt][2 * half + 0] + bias[col];
                    v1 = acc[mt][nt][2 * half + 1] + bias[col + 1];
                    if (act) {
                        v0 = v0 > 0.f ? v0 : 0.1f * v0;
                        v1 = v1 > 0.f ? v1 : 0.1f * v1;
                    }
                    if (halfOut) {
                        *reinterpret_cast<__half2*>(
                            (__half*)Cout + (size_t)row * Nc + col) =
                            __floats2half2_rn(v0, v1);
                    } else {
                        *reinterpret_cast<float2*>(
                            (float*)Cout + (size_t)row * Nc + col) =
                            make_float2(v0, v1);
                    }
                }
                if (S) {
                    *reinterpret_cast<__half2*>(S + (size_t)row * sKp + col) =
                        __floats2half2_rn(v0, v1);
                }
            }
        }
    }
}

// ====================== layer-2 gate fusion ================================

__device__ __forceinline__ float gate_eval_h(const __half* g, const float* wcO, int H, int o) {
    float I = fsig(__half2float(g[o]));
    float T = ftanh(__half2float(g[H + o]));
    float Cv = I * T;
    float O = fsig(__half2float(g[2 * H + o]) + wcO[o] * Cv);
    float y = O * ftanh(Cv);
    return y > 0.f ? y : 0.1f * y;   // fused leaky relu
}

__global__ void k_gates_split(const __half* __restrict__ G, const float* __restrict__ wcO,
                              __half* __restrict__ A2, int n, int npad, int H) {
    int idx = blockIdx.x * blockDim.x + threadIdx.x;
    if (idx >= npad * H) return;
    int r = idx / H, o = idx % H;
    float y = 0.0f;
    if (r < n) y = gate_eval_h(G + (size_t)r * 3 * H, wcO, H, o);
    A2[(size_t)r * H + o] = __float2half_rn(y);
}

// ====================== layer-3 fused tail: gates + lin3 ===================

__global__ __launch_bounds__(256) void k_gates_lin3(
    const __half* __restrict__ G, const float* __restrict__ wcO,
    const float* __restrict__ W, const float* __restrict__ b,
    float* __restrict__ out, int n) {
    __shared__ float sW3[192];
    int tid = threadIdx.x;
    if (tid < 192) sW3[tid] = W[tid];
    __syncthreads();
    int lane = tid & 31, w = tid >> 5;
    for (int rr = 0; rr < 8; rr++) {
        int r = blockIdx.x * 64 + w * 8 + rr;
        if (r >= n) return;
        const __half* g = G + (size_t)r * 192;
        float p0 = 0.f, p1 = 0.f, p2 = 0.f;
#pragma unroll
        for (int k = 0; k < 2; k++) {
            int u = lane + 32 * k;
            float y = gate_eval_h(g, wcO, 64, u);
            p0 += y * sW3[u * 3]; p1 += y * sW3[u * 3 + 1]; p2 += y * sW3[u * 3 + 2];
        }
#pragma unroll
        for (int off = 16; off; off >>= 1) {
            p0 += __shfl_xor_sync(0xffffffffu, p0, off);
            p1 += __shfl_xor_sync(0xffffffffu, p1, off);
            p2 += __shfl_xor_sync(0xffffffffu, p2, off);
        }
        if (lane == 0) {
            out[r * 3] = p0 + b[0];
            out[r * 3 + 1] = p1 + b[1];
            out[r * 3 + 2] = p2 + b[2];
        }
    }
}

// ====================== host orchestration =================================

static inline int ceildiv(int a, int b) { return (a + b - 1) / b; }

extern "C" void kernel_launch(void* const* d_in, const int* in_sizes, int n_in,
                              void* d_out, int out_size) {
    const float* x = (const float*)d_in[0];
    const int* ei = (const int*)d_in[1];
    int N = in_sizes[0] / 3;
    int E = in_sizes[1] / 2;
    const int* src = ei;
    const int* dst = ei + E;
    int Npad = (N + 127) & ~127;
    int Mt = Npad / 128;

    const float* l1_Wx = (const float*)d_in[2];
    const float* l1_bx = (const float*)d_in[3];
    const float* l1_bh = (const float*)d_in[5];
    const float* l1_wc = (const float*)d_in[6];
    const float* l1_b  = (const float*)d_in[7];
    const float* l2_Wx = (const float*)d_in[8];
    const float* l2_bx = (const float*)d_in[9];
    const float* l2_bh = (const float*)d_in[11];
    const float* l2_wc = (const float*)d_in[12];
    const float* l2_b  = (const float*)d_in[13];
    const float* l3_Wx = (const float*)d_in[14];
    const float* l3_bx = (const float*)d_in[15];
    const float* l3_bh = (const float*)d_in[17];
    const float* l3_wc = (const float*)d_in[18];
    const float* l3_b  = (const float*)d_in[19];
    const float* lin1_W = (const float*)d_in[20];
    const float* lin1_b = (const float*)d_in[21];
    const float* lin2_W = (const float*)d_in[22];
    const float* lin2_b = (const float*)d_in[23];
    const float* lin3_W = (const float*)d_in[24];
    const float* lin3_b = (const float*)d_in[25];
    float* out = (float*)d_out;

    void* p;
    cudaGetSymbolAddress(&p, g_tmp);   int* tmp = (int*)p;
    cudaGetSymbolAddress(&p, g_xc);    float* xcf = (float*)p;
    __half* xch = (__half*)xcf;
    cudaGetSymbolAddress(&p, g_gate);  __half* G = (__half*)p;
    cudaGetSymbolAddress(&p, g_h2);    __half* H2 = (__half*)p;
    cudaGetSymbolAddress(&p, g_wbias); float* wb = (float*)p;
    cudaGetSymbolAddress(&p, g_bufA);  __half* bufA = (__half*)p;
    cudaGetSymbolAddress(&p, g_bufB);  __half* bufB = (__half*)p;
    cudaGetSymbolAddress(&p, g_bbuf);  __half* bb = (__half*)p;

    cudaFuncSetAttribute(gemm_mma2, cudaFuncAttributeMaxDynamicSharedMemorySize,
                         3 * GSTAGE);

    cudaStream_t s = 0;

    // ---- graph preprocessing ----
    cudaMemsetAsync(tmp, 0, 3 * MAXN * sizeof(int), s);
    k_degree<<<ceildiv(E, 256), 256, 0, s>>>(src, dst, E);
    k_scan<<<1, 1024, 0, s>>>(N);
    k_fill<<<ceildiv(E, 256), 256, 0, s>>>(src, dst, E);

    // ---- all weight/bias preprocessing in one kernel ----
    k_prep_all<<<ceildiv(E6, 256), 256, 0, s>>>(
        l1_Wx, l2_Wx, l3_Wx, lin1_W, lin2_W,
        l1_bx, l1_bh, l1_b, l2_bx, l2_bh, l2_b, l3_bx, l3_bh, l3_b);

    // ================= layer 1 (F=3, H=256) — fully fused ===================
    k_l1a<<<ceildiv(N, 256), 256, 0, s>>>(x, xcf, N);
    k_l1gates<<<ceildiv(Npad, 64), 256, 0, s>>>(x, xcf, l1_wc + 512, bufB, N, Npad);
    // lin1: [N,256]@[256,128] + lrelu -> fp16 H2 + T0 section of layer2 A
    gemm_mma2<<<dim3(128 / 64, Mt), 256, 3 * GSTAGE, s>>>(
        bufB, bb + O_BL1, lin1_b, H2, 1, bufA, 384, N, 256, 128, 1);

    // ================= layer 2 (F=128, H=128) =================
    k_spmv_split<128, 0><<<ceildiv(Npad, 8), 256, 0, s>>>(H2, nullptr, xch, bufA, 384, 128, N, Npad);
    k_spmv_split<128, 1><<<ceildiv(Npad, 8), 256, 0, s>>>(xch, H2, nullptr, bufA, 384, 256, N, Npad);
    gemm_mma2<<<dim3(384 / 64, Mt), 256, 3 * GSTAGE, s>>>(
        bufA, bb + O_B2, wb + 768, G, 1, nullptr, 0, N, 384, 384, 0);
    k_gates_split<<<ceildiv(Npad * 128, 256), 256, 0, s>>>(G, l2_wc + 256, bufB, N, Npad, 128);
    // lin2: [N,128]@[128,64] + lrelu -> fp16 H2 + T0 section of layer3 A
    gemm_mma2<<<dim3(64 / 64, Mt), 256, 3 * GSTAGE, s>>>(
        bufB, bb + O_BL2, lin2_b, H2, 1, bufA, 192, N, 128, 64, 1);

    // ================= layer 3 (F=64, H=64) =================
    k_spmv_split<64, 0><<<ceildiv(Npad, 16), 256, 0, s>>>(H2, nullptr, xch, bufA, 192, 64, N, Npad);
    k_spmv_split<64, 1><<<ceildiv(Npad, 16), 256, 0, s>>>(xch, H2, nullptr, bufA, 192, 128, N, Npad);
    gemm_mma2<<<dim3(192 / 64, Mt), 256, 3 * GSTAGE, s>>>(
        bufA, bb + O_B3, wb + 1152, G, 1, nullptr, 0, N, 192, 192, 0);
    k_gates_lin3<<<ceildiv(N, 64), 256, 0, s>>>(G, l3_wc + 128, lin3_W, lin3_b, out, N);
}

// round 9
// speedup vs baseline: 1.8019x; 1.0142x over previous
#include <cuda_runtime.h>
#include <cuda_fp16.h>
#include <math.h>
#include <stdint.h>

// ---------------- problem-size caps (fixed by setup_inputs) ----------------
#define MAXN 50000
#define NPADMAX 50048   // MAXN rounded up to 128

// ---------------- device scratch (no allocation allowed) -------------------
__device__ int   g_tmp[3 * MAXN];    // deg | cnt | cur (one memset)
__device__ int   g_roff[MAXN + 1];
__device__ int2  g_edge[800000];     // packed (src, weight-bits)
__device__ float g_xc[(size_t)MAXN * 384];     // dense Tx1 scratch (fp16 view) / l1 fp32
__device__ float g_gate[(size_t)MAXN * 768];   // gate pre-activations (fp16 view)
__device__ float g_h2[(size_t)MAXN * 128];     // post-linear output (fp16 view)
__device__ float g_wbias[1344];                // combined gate biases (l1|l2|l3)
__device__ float g_w1t[9 * 768];               // layer1 gate weights transposed fp32
__device__ __align__(256) __half g_bufA[(size_t)NPADMAX * 384]; // gconv A (single)
__device__ __align__(256) __half g_bufB[(size_t)NPADMAX * 256]; // lin A (single)
__device__ __align__(256) __half g_bbuf[262144];                // weights fp16

// weight buffer element offsets (rows x Kp, single fp16)
#define O_B2  24576    // l2 gate: 384 x 384
#define O_B3  172032   // l3 gate: 192 x 192
#define O_BL1 208896   // lin1: 128 x 256
#define O_BL2 241664   // lin2: 64 x 128

// ====================== graph preprocessing ================================

__global__ void k_degree(const int* __restrict__ src, const int* __restrict__ dst, int E) {
    int e = blockIdx.x * blockDim.x + threadIdx.x;
    if (e >= E) return;
    atomicAdd(&g_tmp[src[e]], 1);            // deg
    atomicAdd(&g_tmp[MAXN + dst[e]], 1);     // cnt
}

__global__ void k_scan(int n) {
    __shared__ int ssum[1024];
    int tid = threadIdx.x;
    const int T = 1024;
    int chunk = (n + T - 1) / T;
    int beg = tid * chunk;
    int end = beg + chunk; if (end > n) end = n;
    int s = 0;
    for (int i = beg; i < end; i++) s += g_tmp[MAXN + i];
    ssum[tid] = s;
    __syncthreads();
    for (int off = 1; off < T; off <<= 1) {
        int v = (tid >= off) ? ssum[tid - off] : 0;
        __syncthreads();
        ssum[tid] += v;
        __syncthreads();
    }
    int run = (tid > 0) ? ssum[tid - 1] : 0;
    for (int i = beg; i < end; i++) { g_roff[i] = run; run += g_tmp[MAXN + i]; }
    if (tid == T - 1) g_roff[n] = ssum[T - 1];
}

__global__ void k_fill(const int* __restrict__ src, const int* __restrict__ dst, int E) {
    int e = blockIdx.x * blockDim.x + threadIdx.x;
    if (e >= E) return;
    int s = src[e], d = dst[e];
    int pos = g_roff[d] + atomicAdd(&g_tmp[2 * MAXN + d], 1);
    int ds = g_tmp[s], dd = g_tmp[d];
    float is = ds > 0 ? rsqrtf((float)ds) : 0.0f;
    float id = dd > 0 ? rsqrtf((float)dd) : 0.0f;
    g_edge[pos] = make_int2(s, __float_as_int(-is * id));
}

// ====================== merged weight/bias preprocessing ===================

__device__ __forceinline__ void prep_gateB(const float* __restrict__ Wx, int F, int H,
                                           int Kp, int nrow, int kk,
                                           __half* __restrict__ dst) {
    int gp = nrow / H, o = nrow % H;
    int gate = (gp == 0) ? 0 : (gp + 1);   // gates {0,2,3}
    float w = 0.0f;
    if (kk < 3 * F) {
        int kc = kk / F, f = kk % F;
        w = Wx[(((size_t)gate * 3 + kc) * F + f) * H + o];
    }
    dst[(size_t)nrow * Kp + kk] = __float2half_rn(w);
}

__device__ __forceinline__ void prep_linB(const float* __restrict__ W, int Hout,
                                          int Kp, int nrow, int kk,
                                          __half* __restrict__ dst) {
    dst[(size_t)nrow * Kp + kk] = __float2half_rn(W[(size_t)kk * Hout + nrow]);
}

#define E1 24576     // 768*32 (layer1 -> transposed fp32 table)
#define E2 172032    // +384*384
#define E3 208896    // +192*192
#define E4 241664    // +128*256
#define E5 249856    // +64*128
#define E6 251200    // +1344 biases

__global__ void k_prep_all(
    const float* __restrict__ w1, const float* __restrict__ w2, const float* __restrict__ w3,
    const float* __restrict__ wl1, const float* __restrict__ wl2,
    const float* __restrict__ bx1, const float* __restrict__ bh1, const float* __restrict__ b1,
    const float* __restrict__ bx2, const float* __restrict__ bh2, const float* __restrict__ b2,
    const float* __restrict__ bx3, const float* __restrict__ bh3, const float* __restrict__ b3) {
    int idx = blockIdx.x * blockDim.x + threadIdx.x;
    if (idx >= E6) return;
    if (idx < E1) {
        int nrow = idx / 32, kk = idx % 32;
        if (kk < 9) {
            int gp = nrow / 256, o = nrow % 256;
            int gate = (gp == 0) ? 0 : (gp + 1);
            int kc = kk / 3, f = kk % 3;
            g_w1t[kk * 768 + nrow] = w1[(((size_t)gate * 3 + kc) * 3 + f) * 256 + o];
        }
    } else if (idx < E2) {
        int t = idx - E1;
        prep_gateB(w2, 128, 128, 384, t / 384, t % 384, g_bbuf + O_B2);
    } else if (idx < E3) {
        int t = idx - E2;
        prep_gateB(w3, 64, 64, 192, t / 192, t % 192, g_bbuf + O_B3);
    } else if (idx < E4) {
        int t = idx - E3;
        prep_linB(wl1, 128, 256, t / 256, t % 256, g_bbuf + O_BL1);
    } else if (idx < E5) {
        int t = idx - E4;
        prep_linB(wl2, 64, 128, t / 128, t % 128, g_bbuf + O_BL2);
    } else {
        int t = idx - E5;
        const float *bx, *bh, *bb; int H, base;
        if (t < 768)       { bx = bx1; bh = bh1; bb = b1; H = 256; base = 0; }
        else if (t < 1152) { bx = bx2; bh = bh2; bb = b2; H = 128; base = 768; t -= 768; }
        else               { bx = bx3; bh = bh3; bb = b3; H = 64;  base = 1152; t -= 1152; }
        int gp = t / H, o = t % H;
        int gate = (gp == 0) ? 0 : (gp + 1);
        g_wbias[base + t] = bx[gate * H + o] + bh[gate * H + o] + bb[gate * H + o];
    }
}

// ====================== fast transcendentals ===============================

__device__ __forceinline__ float fsig(float x) {
    return __fdividef(1.f, 1.f + __expf(-x));
}
__device__ __forceinline__ float ftanh(float x) {
    x = fminf(fmaxf(x, -20.f), 20.f);
    float e = __expf(2.f * x);
    return __fdividef(e - 1.f, e + 1.f);
}

// ====================== layer-1: T1 dense pass (unroll-4) ==================

__global__ void k_l1a(const float* __restrict__ x, float* __restrict__ t1d, int n) {
    int row = blockIdx.x * blockDim.x + threadIdx.x;
    if (row >= n) return;
    float t1[3] = {0, 0, 0};
    int j0 = g_roff[row], j1 = g_roff[row + 1];
    int j = j0;
    int jend = j0 + ((j1 - j0) & ~3);
    for (; j < jend; j += 4) {
        int2 e0 = g_edge[j], e1 = g_edge[j + 1], e2 = g_edge[j + 2], e3 = g_edge[j + 3];
        const float* x0 = x + (size_t)e0.x * 3;
        const float* x1 = x + (size_t)e1.x * 3;
        const float* x2 = x + (size_t)e2.x * 3;
        const float* x3 = x + (size_t)e3.x * 3;
        float v00 = x0[0], v01 = x0[1], v02 = x0[2];
        float v10 = x1[0], v11 = x1[1], v12 = x1[2];
        float v20 = x2[0], v21 = x2[1], v22 = x2[2];
        float v30 = x3[0], v31 = x3[1], v32 = x3[2];
        float w0 = __int_as_float(e0.y), w1 = __int_as_float(e1.y);
        float w2 = __int_as_float(e2.y), w3 = __int_as_float(e3.y);
        t1[0] += w0 * v00 + w1 * v10 + w2 * v20 + w3 * v30;
        t1[1] += w0 * v01 + w1 * v11 + w2 * v21 + w3 * v31;
        t1[2] += w0 * v02 + w1 * v12 + w2 * v22 + w3 * v32;
    }
    for (; j < j1; j++) {
        int2 e = g_edge[j];
        float w = __int_as_float(e.y);
        const float* xr = x + (size_t)e.x * 3;
        t1[0] += w * xr[0]; t1[1] += w * xr[1]; t1[2] += w * xr[2];
    }
    t1d[row * 3] = t1[0]; t1d[row * 3 + 1] = t1[1]; t1d[row * 3 + 2] = t1[2];
}

// ====================== layer-1 fused: T2 gather + gates -> bufB ===========

__global__ __launch_bounds__(256) void k_l1gates(
    const float* __restrict__ x, const float* __restrict__ t1d,
    const float* __restrict__ wcO, __half* __restrict__ outA, int n, int npad) {
    __shared__ __half sW[9 * 768];
    __shared__ float sB[768];
    int tid = threadIdx.x;
    for (int i = tid; i < 9 * 768; i += 256) sW[i] = __float2half_rn(g_w1t[i]);
    for (int i = tid; i < 768; i += 256) sB[i] = g_wbias[i];
    __syncthreads();
    const __half2* sW2 = reinterpret_cast<const __half2*>(sW);
    int lane = tid & 31, w = tid >> 5;

    for (int rr = 0; rr < 8; rr++) {
        int r = blockIdx.x * 64 + w * 8 + rr;
        if (r >= npad) return;
        if (r >= n) {
#pragma unroll
            for (int c = 0; c < 4; c++)
                *reinterpret_cast<__half2*>(outA + (size_t)r * 256 + 2 * lane + 64 * c) =
                    __floats2half2_rn(0.f, 0.f);
            continue;
        }
        float p0 = 0.f, p1 = 0.f, p2 = 0.f;
        int j0 = g_roff[r], j1 = g_roff[r + 1];
        for (int j = j0 + lane; j < j1; j += 32) {
            int2 e = g_edge[j];
            float wgt = __int_as_float(e.y);
            const float* tr = t1d + (size_t)e.x * 3;
            p0 += wgt * tr[0]; p1 += wgt * tr[1]; p2 += wgt * tr[2];
        }
#pragma unroll
        for (int off = 16; off; off >>= 1) {
            p0 += __shfl_xor_sync(0xffffffffu, p0, off);
            p1 += __shfl_xor_sync(0xffffffffu, p1, off);
            p2 += __shfl_xor_sync(0xffffffffu, p2, off);
        }
        float a[9];
        a[0] = x[r * 3]; a[1] = x[r * 3 + 1]; a[2] = x[r * 3 + 2];
        a[3] = t1d[r * 3]; a[4] = t1d[r * 3 + 1]; a[5] = t1d[r * 3 + 2];
        a[6] = 2.f * p0 - a[0]; a[7] = 2.f * p1 - a[1]; a[8] = 2.f * p2 - a[2];

        float2 pi[4], pc[4], po[4];
#pragma unroll
        for (int c = 0; c < 4; c++) {
            int u = 2 * lane + 64 * c;
            pi[c] = make_float2(sB[u], sB[u + 1]);
            pc[c] = make_float2(sB[256 + u], sB[256 + u + 1]);
            po[c] = make_float2(sB[512 + u], sB[512 + u + 1]);
        }
#pragma unroll
        for (int k = 0; k < 9; k++) {
            float ak = a[k];
            int kb = k * 384;
#pragma unroll
            for (int c = 0; c < 4; c++) {
                int h2i = lane + 32 * c;
                float2 wi = __half22float2(sW2[kb + h2i]);
                pi[c].x += ak * wi.x; pi[c].y += ak * wi.y;
                float2 wc2 = __half22float2(sW2[kb + 128 + h2i]);
                pc[c].x += ak * wc2.x; pc[c].y += ak * wc2.y;
                float2 wo = __half22float2(sW2[kb + 256 + h2i]);
                po[c].x += ak * wo.x; po[c].y += ak * wo.y;
            }
        }
#pragma unroll
        for (int c = 0; c < 4; c++) {
            int u = 2 * lane + 64 * c;
            float I0 = fsig(pi[c].x), T0 = ftanh(pc[c].x), C0 = I0 * T0;
            float O0 = fsig(po[c].x + wcO[u] * C0);
            float y0 = O0 * ftanh(C0); y0 = y0 > 0.f ? y0 : 0.1f * y0;
            float I1 = fsig(pi[c].y), T1 = ftanh(pc[c].y), C1 = I1 * T1;
            float O1 = fsig(po[c].y + wcO[u + 1] * C1);
            float y1 = O1 * ftanh(C1); y1 = y1 > 0.f ? y1 : 0.1f * y1;
            *reinterpret_cast<__half2*>(outA + (size_t)r * 256 + u) =
                __floats2half2_rn(y0, y1);
        }
    }
}

// ====================== fused SpMV + split (fp16 IO, unroll-4) =============

template <int F, int CHEB2>
__global__ void k_spmv_split(const __half* __restrict__ X, const __half* __restrict__ X0,
                             __half* __restrict__ Yd,
                             __half* __restrict__ A2, int Kp, int sec,
                             int n, int npad) {
    const int TPR = F / 4;
    int tid = threadIdx.x;
    int row = blockIdx.x * (256 / TPR) + tid / TPR;
    int f = (tid % TPR) * 4;
    if (row >= npad) return;
    float a0 = 0.f, a1 = 0.f, a2 = 0.f, a3 = 0.f;
    if (row < n) {
        int j0 = g_roff[row], j1 = g_roff[row + 1];
        int j = j0;
        int jend = j0 + ((j1 - j0) & ~3);
        for (; j < jend; j += 4) {
            int2 e0 = g_edge[j], e1 = g_edge[j + 1];
            int2 e2 = g_edge[j + 2], e3 = g_edge[j + 3];
            float2 r0 = *reinterpret_cast<const float2*>(X + (size_t)e0.x * F + f);
            float2 r1 = *reinterpret_cast<const float2*>(X + (size_t)e1.x * F + f);
            float2 r2 = *reinterpret_cast<const float2*>(X + (size_t)e2.x * F + f);
            float2 r3 = *reinterpret_cast<const float2*>(X + (size_t)e3.x * F + f);
            float w0 = __int_as_float(e0.y), w1 = __int_as_float(e1.y);
            float w2 = __int_as_float(e2.y), w3 = __int_as_float(e3.y);
            {
                float2 f01 = __half22float2(*reinterpret_cast<__half2*>(&r0.x));
                float2 f23 = __half22float2(*reinterpret_cast<__half2*>(&r0.y));
                a0 += w0 * f01.x; a1 += w0 * f01.y; a2 += w0 * f23.x; a3 += w0 * f23.y;
            }
            {
                float2 f01 = __half22float2(*reinterpret_cast<__half2*>(&r1.x));
                float2 f23 = __half22float2(*reinterpret_cast<__half2*>(&r1.y));
                a0 += w1 * f01.x; a1 += w1 * f01.y; a2 += w1 * f23.x; a3 += w1 * f23.y;
            }
            {
                float2 f01 = __half22float2(*reinterpret_cast<__half2*>(&r2.x));
                float2 f23 = __half22float2(*reinterpret_cast<__half2*>(&r2.y));
                a0 += w2 * f01.x; a1 += w2 * f01.y; a2 += w2 * f23.x; a3 += w2 * f23.y;
            }
            {
                float2 f01 = __half22float2(*reinterpret_cast<__half2*>(&r3.x));
                float2 f23 = __half22float2(*reinterpret_cast<__half2*>(&r3.y));
                a0 += w3 * f01.x; a1 += w3 * f01.y; a2 += w3 * f23.x; a3 += w3 * f23.y;
            }
        }
        for (; j < j1; j++) {
            int2 e = g_edge[j];
            float w = __int_as_float(e.y);
            float2 raw = *reinterpret_cast<const float2*>(X + (size_t)e.x * F + f);
            float2 f01 = __half22float2(*reinterpret_cast<__half2*>(&raw.x));
            float2 f23 = __half22float2(*reinterpret_cast<__half2*>(&raw.y));
            a0 += w * f01.x; a1 += w * f01.y; a2 += w * f23.x; a3 += w * f23.y;
        }
        if (CHEB2) {
            float2 raw = *reinterpret_cast<const float2*>(X0 + (size_t)row * F + f);
            float2 f01 = __half22float2(*reinterpret_cast<__half2*>(&raw.x));
            float2 f23 = __half22float2(*reinterpret_cast<__half2*>(&raw.y));
            a0 = 2.f * a0 - f01.x; a1 = 2.f * a1 - f01.y;
            a2 = 2.f * a2 - f23.x; a3 = 2.f * a3 - f23.y;
        }
    }
    float2 packed;
    *reinterpret_cast<__half2*>(&packed.x) = __floats2half2_rn(a0, a1);
    *reinterpret_cast<__half2*>(&packed.y) = __floats2half2_rn(a2, a3);
    if (Yd && row < n)
        *reinterpret_cast<float2*>(Yd + (size_t)row * F + f) = packed;
    *reinterpret_cast<float2*>(A2 + (size_t)row * Kp + sec + f) = packed;
}

// ====================== mma.sync fp16 GEMM =================================

#define CP16(dst, src) \
    asm volatile("cp.async.ca.shared.global [%0], [%1], 16;\n" :: "r"(dst), "l"(src))
#define CP_COMMIT() asm volatile("cp.async.commit_group;\n" ::: "memory")
#define CP_WAIT1()  asm volatile("cp.async.wait_group 1;\n" ::: "memory")
#define CP_WAIT0()  asm volatile("cp.async.wait_group 0;\n" ::: "memory")

__device__ __forceinline__ uint32_t smem_u32(const void* p) {
    uint32_t a;
    asm("{ .reg .u64 t; cvta.to.shared.u64 t, %1; cvt.u32.u64 %0, t; }"
        : "=r"(a) : "l"(p));
    return a;
}

__device__ __forceinline__ void ldm_x4(uint32_t* r, uint32_t addr) {
    asm volatile("ldmatrix.sync.aligned.m8n8.x4.shared.b16 {%0,%1,%2,%3}, [%4];"
                 : "=r"(r[0]), "=r"(r[1]), "=r"(r[2]), "=r"(r[3]) : "r"(addr));
}

__device__ __forceinline__ void mma16816h(float* c, const uint32_t* a, const uint32_t* b) {
    asm volatile(
        "mma.sync.aligned.m16n8k16.row.col.f32.f16.f16.f32 "
        "{%0,%1,%2,%3}, {%4,%5,%6,%7}, {%8,%9}, {%0,%1,%2,%3};"
        : "+f"(c[0]), "+f"(c[1]), "+f"(c[2]), "+f"(c[3])
        : "r"(a[0]), "r"(a[1]), "r"(a[2]), "r"(a[3]), "r"(b[0]), "r"(b[1]));
}

// stage layout (80B rows): A rows 0-127, B rows 128-191.
// Stage = 192*80 = 15360B, 3 stages = 46080B.
#define GSTAGE 15360

__global__ __launch_bounds__(256, 2) void gemm_mma2(
    const __half* __restrict__ A, const __half* __restrict__ B,
    const float* __restrict__ bias, void* __restrict__ Cout, int halfOut,
    __half* __restrict__ S, int sKp,
    int M, int Kp, int Nc, int act) {
    extern __shared__ char smem[];
    const uint32_t s0 = smem_u32(smem);
    const int tid = threadIdx.x;
    const int wid = tid >> 5;
    const int lane = tid & 31;
    const int wm = wid & 3, wn = wid >> 2;
    const int bn = blockIdx.x << 6;
    const int bm = blockIdx.y << 7;

    float acc[2][4][4];
#pragma unroll
    for (int i = 0; i < 2; i++)
#pragma unroll
        for (int j = 0; j < 4; j++)
#pragma unroll
            for (int k = 0; k < 4; k++) acc[i][j][k] = 0.f;

#define LOAD_STAGE(stg, kc) do {                                             \
    uint32_t dstBase = s0 + (stg) * GSTAGE;                                  \
    _Pragma("unroll")                                                        \
    for (int u = tid; u < 768; u += 256) {                                   \
        uint32_t d; const char* g;                                           \
        if (u < 512) {                                                       \
            int row = u >> 2, seg = u & 3;                                   \
            d = dstBase + row * 80 + seg * 16;                               \
            g = (const char*)A + ((size_t)(bm + row) * Kp + (kc)) * 2        \
                + seg * 16;                                                  \
        } else {                                                             \
            int t = u - 512; int row = t >> 2, seg = t & 3;                  \
            d = dstBase + (128 + row) * 80 + seg * 16;                       \
            g = (const char*)B + ((size_t)(bn + row) * Kp + (kc)) * 2        \
                + seg * 16;                                                  \
        }                                                                    \
        CP16(d, g);                                                          \
    } } while (0)

    const int nK = Kp >> 5;
    LOAD_STAGE(0, 0);
    CP_COMMIT();
    if (nK > 1) { LOAD_STAGE(1, 32); CP_COMMIT(); }

    for (int kt = 0; kt < nK; kt++) {
        if (kt + 1 < nK) CP_WAIT1(); else CP_WAIT0();
        __syncthreads();
        if (kt + 2 < nK) {
            LOAD_STAGE((kt + 2) % 3, (kt + 2) << 5);
            CP_COMMIT();
        }
        uint32_t base = s0 + (kt % 3) * GSTAGE;
        uint32_t kb = (lane >> 4) * 16;
        uint32_t arow = wm * 32 + (lane & 15);
        uint32_t brow = 128 + wn * 32 + (lane & 15);
#pragma unroll
        for (int kk = 0; kk < 2; kk++) {
            uint32_t a[2][4];
#pragma unroll
            for (int mt = 0; mt < 2; mt++)
                ldm_x4(a[mt], base + (arow + mt * 16) * 80 + kk * 32 + kb);
            uint32_t b[4][2];
#pragma unroll
            for (int j = 0; j < 2; j++) {
                uint32_t r[4];
                ldm_x4(r, base + (brow + j * 16) * 80 + kk * 32 + kb);
                b[2 * j][0] = r[0]; b[2 * j][1] = r[2];
                b[2 * j + 1][0] = r[1]; b[2 * j + 1][1] = r[3];
            }
#pragma unroll
            for (int mt = 0; mt < 2; mt++)
#pragma unroll
                for (int nt = 0; nt < 4; nt++)
                    mma16816h(acc[mt][nt], a[mt], b[nt]);
        }
    }

    // epilogue
    const int gid = lane >> 2, tig = lane & 3;
#pragma unroll
    for (int mt = 0; mt < 2; mt++) {
#pragma unroll
        for (int half = 0; half < 2; half++) {
            int row = bm + wm * 32 + mt * 16 + half * 8 + gid;
            bool valid = row < M;
#pragma unroll
            for (int nt = 0; nt < 4; nt++) {
                int col = bn + wn * 32 + nt * 8 + tig * 2;
                float v0 = 0.f, v1 = 0.f;
                if (valid) {
                    v0 = acc[mt][nt][2 * half + 0] + bias[col];
                    v1 = acc[mt][nt][2 * half + 1] + bias[col + 1];
                    if (act) {
                        v0 = v0 > 0.f ? v0 : 0.1f * v0;
                        v1 = v1 > 0.f ? v1 : 0.1f * v1;
                    }
                    if (halfOut) {
                        *reinterpret_cast<__half2*>(
                            (__half*)Cout + (size_t)row * Nc + col) =
                            __floats2half2_rn(v0, v1);
                    } else {
                        *reinterpret_cast<float2*>(
                            (float*)Cout + (size_t)row * Nc + col) =
                            make_float2(v0, v1);
                    }
                }
                if (S) {
                    *reinterpret_cast<__half2*>(S + (size_t)row * sKp + col) =
                        __floats2half2_rn(v0, v1);
                }
            }
        }
    }
}

// ====================== layer-2 gate fusion ================================

__device__ __forceinline__ float gate_eval_h(const __half* g, const float* wcO, int H, int o) {
    float I = fsig(__half2float(g[o]));
    float T = ftanh(__half2float(g[H + o]));
    float Cv = I * T;
    float O = fsig(__half2float(g[2 * H + o]) + wcO[o] * Cv);
    float y = O * ftanh(Cv);
    return y > 0.f ? y : 0.1f * y;   // fused leaky relu
}

__global__ void k_gates_split(const __half* __restrict__ G, const float* __restrict__ wcO,
                              __half* __restrict__ A2, int n, int npad, int H) {
    int idx = blockIdx.x * blockDim.x + threadIdx.x;
    if (idx >= npad * H) return;
    int r = idx / H, o = idx % H;
    float y = 0.0f;
    if (r < n) y = gate_eval_h(G + (size_t)r * 3 * H, wcO, H, o);
    A2[(size_t)r * H + o] = __float2half_rn(y);
}

// ====================== layer-3 fused tail: gates + lin3 ===================

__global__ __launch_bounds__(256) void k_gates_lin3(
    const __half* __restrict__ G, const float* __restrict__ wcO,
    const float* __restrict__ W, const float* __restrict__ b,
    float* __restrict__ out, int n) {
    __shared__ float sW3[192];
    int tid = threadIdx.x;
    if (tid < 192) sW3[tid] = W[tid];
    __syncthreads();
    int lane = tid & 31, w = tid >> 5;
    for (int rr = 0; rr < 8; rr++) {
        int r = blockIdx.x * 64 + w * 8 + rr;
        if (r >= n) return;
        const __half* g = G + (size_t)r * 192;
        float p0 = 0.f, p1 = 0.f, p2 = 0.f;
#pragma unroll
        for (int k = 0; k < 2; k++) {
            int u = lane + 32 * k;
            float y = gate_eval_h(g, wcO, 64, u);
            p0 += y * sW3[u * 3]; p1 += y * sW3[u * 3 + 1]; p2 += y * sW3[u * 3 + 2];
        }
#pragma unroll
        for (int off = 16; off; off >>= 1) {
            p0 += __shfl_xor_sync(0xffffffffu, p0, off);
            p1 += __shfl_xor_sync(0xffffffffu, p1, off);
            p2 += __shfl_xor_sync(0xffffffffu, p2, off);
        }
        if (lane == 0) {
            out[r * 3] = p0 + b[0];
            out[r * 3 + 1] = p1 + b[1];
            out[r * 3 + 2] = p2 + b[2];
        }
    }
}

// ====================== host orchestration =================================

static inline int ceildiv(int a, int b) { return (a + b - 1) / b; }

extern "C" void kernel_launch(void* const* d_in, const int* in_sizes, int n_in,
                              void* d_out, int out_size) {
    const float* x = (const float*)d_in[0];
    const int* ei = (const int*)d_in[1];
    int N = in_sizes[0] / 3;
    int E = in_sizes[1] / 2;
    const int* src = ei;
    const int* dst = ei + E;
    int Npad = (N + 127) & ~127;
    int Mt = Npad / 128;

    const float* l1_Wx = (const float*)d_in[2];
    const float* l1_bx = (const float*)d_in[3];
    const float* l1_bh = (const float*)d_in[5];
    const float* l1_wc = (const float*)d_in[6];
    const float* l1_b  = (const float*)d_in[7];
    const float* l2_Wx = (const float*)d_in[8];
    const float* l2_bx = (const float*)d_in[9];
    const float* l2_bh = (const float*)d_in[11];
    const float* l2_wc = (const float*)d_in[12];
    const float* l2_b  = (const float*)d_in[13];
    const float* l3_Wx = (const float*)d_in[14];
    const float* l3_bx = (const float*)d_in[15];
    const float* l3_bh = (const float*)d_in[17];
    const float* l3_wc = (const float*)d_in[18];
    const float* l3_b  = (const float*)d_in[19];
    const float* lin1_W = (const float*)d_in[20];
    const float* lin1_b = (const float*)d_in[21];
    const float* lin2_W = (const float*)d_in[22];
    const float* lin2_b = (const float*)d_in[23];
    const float* lin3_W = (const float*)d_in[24];
    const float* lin3_b = (const float*)d_in[25];
    float* out = (float*)d_out;

    void* p;
    cudaGetSymbolAddress(&p, g_tmp);   int* tmp = (int*)p;
    cudaGetSymbolAddress(&p, g_xc);    float* xcf = (float*)p;
    __half* xch = (__half*)xcf;
    cudaGetSymbolAddress(&p, g_gate);  __half* G = (__half*)p;
    cudaGetSymbolAddress(&p, g_h2);    __half* H2 = (__half*)p;
    cudaGetSymbolAddress(&p, g_wbias); float* wb = (float*)p;
    cudaGetSymbolAddress(&p, g_bufA);  __half* bufA = (__half*)p;
    cudaGetSymbolAddress(&p, g_bufB);  __half* bufB = (__half*)p;
    cudaGetSymbolAddress(&p, g_bbuf);  __half* bb = (__half*)p;

    cudaFuncSetAttribute(gemm_mma2, cudaFuncAttributeMaxDynamicSharedMemorySize,
                         3 * GSTAGE);

    cudaStream_t s = 0;

    // ---- graph preprocessing ----
    cudaMemsetAsync(tmp, 0, 3 * MAXN * sizeof(int), s);
    k_degree<<<ceildiv(E, 256), 256, 0, s>>>(src, dst, E);
    k_scan<<<1, 1024, 0, s>>>(N);
    k_fill<<<ceildiv(E, 256), 256, 0, s>>>(src, dst, E);

    // ---- all weight/bias preprocessing in one kernel ----
    k_prep_all<<<ceildiv(E6, 256), 256, 0, s>>>(
        l1_Wx, l2_Wx, l3_Wx, lin1_W, lin2_W,
        l1_bx, l1_bh, l1_b, l2_bx, l2_bh, l2_b, l3_bx, l3_bh, l3_b);

    // ================= layer 1 (F=3, H=256) — fully fused ===================
    k_l1a<<<ceildiv(N, 256), 256, 0, s>>>(x, xcf, N);
    k_l1gates<<<ceildiv(Npad, 64), 256, 0, s>>>(x, xcf, l1_wc + 512, bufB, N, Npad);
    // lin1: [N,256]@[256,128] + lrelu -> fp16 H2 + T0 section of layer2 A
    gemm_mma2<<<dim3(128 / 64, Mt), 256, 3 * GSTAGE, s>>>(
        bufB, bb + O_BL1, lin1_b, H2, 1, bufA, 384, N, 256, 128, 1);

    // ================= layer 2 (F=128, H=128) =================
    k_spmv_split<128, 0><<<ceildiv(Npad, 8), 256, 0, s>>>(H2, nullptr, xch, bufA, 384, 128, N, Npad);
    k_spmv_split<128, 1><<<ceildiv(Npad, 8), 256, 0, s>>>(xch, H2, nullptr, bufA, 384, 256, N, Npad);
    gemm_mma2<<<dim3(384 / 64, Mt), 256, 3 * GSTAGE, s>>>(
        bufA, bb + O_B2, wb + 768, G, 1, nullptr, 0, N, 384, 384, 0);
    k_gates_split<<<ceildiv(Npad * 128, 256), 256, 0, s>>>(G, l2_wc + 256, bufB, N, Npad, 128);
    // lin2: [N,128]@[128,64] + lrelu -> fp16 H2 + T0 section of layer3 A
    gemm_mma2<<<dim3(64 / 64, Mt), 256, 3 * GSTAGE, s>>>(
        bufB, bb + O_BL2, lin2_b, H2, 1, bufA, 192, N, 128, 64, 1);

    // ================= layer 3 (F=64, H=64) =================
    k_spmv_split<64, 0><<<ceildiv(Npad, 16), 256, 0, s>>>(H2, nullptr, xch, bufA, 192, 64, N, Npad);
    k_spmv_split<64, 1><<<ceildiv(Npad, 16), 256, 0, s>>>(xch, H2, nullptr, bufA, 192, 128, N, Npad);
    gemm_mma2<<<dim3(192 / 64, Mt), 256, 3 * GSTAGE, s>>>(
        bufA, bb + O_B3, wb + 1152, G, 1, nullptr, 0, N, 192, 192, 0);
    k_gates_lin3<<<ceildiv(N, 64), 256, 0, s>>>(G, l3_wc + 128, lin3_W, lin3_b, out, N);
}

// round 10
// speedup vs baseline: 1.9291x; 1.0706x over previous
#include <cuda_runtime.h>
#include <cuda_fp16.h>
#include <math.h>
#include <stdint.h>

// ---------------- problem-size caps (fixed by setup_inputs) ----------------
#define MAXN 50000
#define NPADMAX 50048   // MAXN rounded up to 128

// ---------------- device scratch (no allocation allowed) -------------------
__device__ int   g_tmp[3 * MAXN];    // deg | cnt | cur (one memset)
__device__ int   g_roff[MAXN + 1];
__device__ int2  g_edge[800000];     // packed (src, weight-bits)
__device__ float g_xc[(size_t)MAXN * 384];     // dense Tx1 scratch (fp16 view) / l1 fp32
__device__ float g_gate[(size_t)MAXN * 768];   // gate pre-activations (fp16 view)
__device__ float g_h2[(size_t)MAXN * 128];     // post-linear output (fp16 view)
__device__ float g_wbias[1344];                // combined gate biases (l1|l2|l3)
__device__ float g_w1t[9 * 768];               // layer1 gate weights transposed fp32
__device__ __align__(256) __half g_bufA[(size_t)NPADMAX * 384]; // gconv A (single)
__device__ __align__(256) __half g_bufB[(size_t)NPADMAX * 256]; // lin A (single)
__device__ __align__(256) __half g_bbuf[262144];                // weights fp16

// weight buffer element offsets (rows x Kp, single fp16)
#define O_B2  24576    // l2 gate: 384 x 384
#define O_B3  172032   // l3 gate: 192 x 192
#define O_BL1 208896   // lin1: 128 x 256
#define O_BL2 241664   // lin2: 64 x 128

// ====================== graph preprocessing ================================

__global__ void k_degree(const int* __restrict__ src, const int* __restrict__ dst, int E) {
    int e = blockIdx.x * blockDim.x + threadIdx.x;
    if (e >= E) return;
    atomicAdd(&g_tmp[src[e]], 1);            // deg
    atomicAdd(&g_tmp[MAXN + dst[e]], 1);     // cnt
}

__global__ void k_scan(int n) {
    __shared__ int ssum[1024];
    int tid = threadIdx.x;
    const int T = 1024;
    int chunk = (n + T - 1) / T;
    int beg = tid * chunk;
    int end = beg + chunk; if (end > n) end = n;
    int s = 0;
    for (int i = beg; i < end; i++) s += g_tmp[MAXN + i];
    ssum[tid] = s;
    __syncthreads();
    for (int off = 1; off < T; off <<= 1) {
        int v = (tid >= off) ? ssum[tid - off] : 0;
        __syncthreads();
        ssum[tid] += v;
        __syncthreads();
    }
    int run = (tid > 0) ? ssum[tid - 1] : 0;
    for (int i = beg; i < end; i++) { g_roff[i] = run; run += g_tmp[MAXN + i]; }
    if (tid == T - 1) g_roff[n] = ssum[T - 1];
}

__global__ void k_fill(const int* __restrict__ src, const int* __restrict__ dst, int E) {
    int e = blockIdx.x * blockDim.x + threadIdx.x;
    if (e >= E) return;
    int s = src[e], d = dst[e];
    int pos = g_roff[d] + atomicAdd(&g_tmp[2 * MAXN + d], 1);
    int ds = g_tmp[s], dd = g_tmp[d];
    float is = ds > 0 ? rsqrtf((float)ds) : 0.0f;
    float id = dd > 0 ? rsqrtf((float)dd) : 0.0f;
    g_edge[pos] = make_int2(s, __float_as_int(-is * id));
}

// ====================== merged weight/bias preprocessing ===================

__device__ __forceinline__ void prep_gateB(const float* __restrict__ Wx, int F, int H,
                                           int Kp, int nrow, int kk,
                                           __half* __restrict__ dst) {
    int gp = nrow / H, o = nrow % H;
    int gate = (gp == 0) ? 0 : (gp + 1);   // gates {0,2,3}
    float w = 0.0f;
    if (kk < 3 * F) {
        int kc = kk / F, f = kk % F;
        w = Wx[(((size_t)gate * 3 + kc) * F + f) * H + o];
    }
    dst[(size_t)nrow * Kp + kk] = __float2half_rn(w);
}

__device__ __forceinline__ void prep_linB(const float* __restrict__ W, int Hout,
                                          int Kp, int nrow, int kk,
                                          __half* __restrict__ dst) {
    dst[(size_t)nrow * Kp + kk] = __float2half_rn(W[(size_t)kk * Hout + nrow]);
}

#define E1 24576     // 768*32 (layer1 -> transposed fp32 table)
#define E2 172032    // +384*384
#define E3 208896    // +192*192
#define E4 241664    // +128*256
#define E5 249856    // +64*128
#define E6 251200    // +1344 biases

__global__ void k_prep_all(
    const float* __restrict__ w1, const float* __restrict__ w2, const float* __restrict__ w3,
    const float* __restrict__ wl1, const float* __restrict__ wl2,
    const float* __restrict__ bx1, const float* __restrict__ bh1, const float* __restrict__ b1,
    const float* __restrict__ bx2, const float* __restrict__ bh2, const float* __restrict__ b2,
    const float* __restrict__ bx3, const float* __restrict__ bh3, const float* __restrict__ b3) {
    int idx = blockIdx.x * blockDim.x + threadIdx.x;
    if (idx >= E6) return;
    if (idx < E1) {
        int nrow = idx / 32, kk = idx % 32;
        if (kk < 9) {
            int gp = nrow / 256, o = nrow % 256;
            int gate = (gp == 0) ? 0 : (gp + 1);
            int kc = kk / 3, f = kk % 3;
            g_w1t[kk * 768 + nrow] = w1[(((size_t)gate * 3 + kc) * 3 + f) * 256 + o];
        }
    } else if (idx < E2) {
        int t = idx - E1;
        prep_gateB(w2, 128, 128, 384, t / 384, t % 384, g_bbuf + O_B2);
    } else if (idx < E3) {
        int t = idx - E2;
        prep_gateB(w3, 64, 64, 192, t / 192, t % 192, g_bbuf + O_B3);
    } else if (idx < E4) {
        int t = idx - E3;
        prep_linB(wl1, 128, 256, t / 256, t % 256, g_bbuf + O_BL1);
    } else if (idx < E5) {
        int t = idx - E4;
        prep_linB(wl2, 64, 128, t / 128, t % 128, g_bbuf + O_BL2);
    } else {
        int t = idx - E5;
        const float *bx, *bh, *bb; int H, base;
        if (t < 768)       { bx = bx1; bh = bh1; bb = b1; H = 256; base = 0; }
        else if (t < 1152) { bx = bx2; bh = bh2; bb = b2; H = 128; base = 768; t -= 768; }
        else               { bx = bx3; bh = bh3; bb = b3; H = 64;  base = 1152; t -= 1152; }
        int gp = t / H, o = t % H;
        int gate = (gp == 0) ? 0 : (gp + 1);
        g_wbias[base + t] = bx[gate * H + o] + bh[gate * H + o] + bb[gate * H + o];
    }
}

// ====================== fast transcendentals (HW tanh) =====================

__device__ __forceinline__ float ftanh(float x) {
    float y;
    asm("tanh.approx.f32 %0, %1;" : "=f"(y) : "f"(x));
    return y;
}
__device__ __forceinline__ float fsig(float x) {
    return fmaf(ftanh(0.5f * x), 0.5f, 0.5f);
}

// ====================== layer-1: T1 dense pass (unroll-4) ==================

__global__ void k_l1a(const float* __restrict__ x, float* __restrict__ t1d, int n) {
    int row = blockIdx.x * blockDim.x + threadIdx.x;
    if (row >= n) return;
    float t1[3] = {0, 0, 0};
    int j0 = g_roff[row], j1 = g_roff[row + 1];
    int j = j0;
    int jend = j0 + ((j1 - j0) & ~3);
    for (; j < jend; j += 4) {
        int2 e0 = g_edge[j], e1 = g_edge[j + 1], e2 = g_edge[j + 2], e3 = g_edge[j + 3];
        const float* x0 = x + (size_t)e0.x * 3;
        const float* x1 = x + (size_t)e1.x * 3;
        const float* x2 = x + (size_t)e2.x * 3;
        const float* x3 = x + (size_t)e3.x * 3;
        float v00 = x0[0], v01 = x0[1], v02 = x0[2];
        float v10 = x1[0], v11 = x1[1], v12 = x1[2];
        float v20 = x2[0], v21 = x2[1], v22 = x2[2];
        float v30 = x3[0], v31 = x3[1], v32 = x3[2];
        float w0 = __int_as_float(e0.y), w1 = __int_as_float(e1.y);
        float w2 = __int_as_float(e2.y), w3 = __int_as_float(e3.y);
        t1[0] += w0 * v00 + w1 * v10 + w2 * v20 + w3 * v30;
        t1[1] += w0 * v01 + w1 * v11 + w2 * v21 + w3 * v31;
        t1[2] += w0 * v02 + w1 * v12 + w2 * v22 + w3 * v32;
    }
    for (; j < j1; j++) {
        int2 e = g_edge[j];
        float w = __int_as_float(e.y);
        const float* xr = x + (size_t)e.x * 3;
        t1[0] += w * xr[0]; t1[1] += w * xr[1]; t1[2] += w * xr[2];
    }
    t1d[row * 3] = t1[0]; t1d[row * 3 + 1] = t1[1]; t1d[row * 3 + 2] = t1[2];
}

// ====================== layer-1 fused: T2 gather + gates -> bufB ===========

__global__ __launch_bounds__(256) void k_l1gates(
    const float* __restrict__ x, const float* __restrict__ t1d,
    const float* __restrict__ wcO, __half* __restrict__ outA, int n, int npad) {
    __shared__ __half sW[9 * 768];
    __shared__ float sB[768];
    int tid = threadIdx.x;
    for (int i = tid; i < 9 * 768; i += 256) sW[i] = __float2half_rn(g_w1t[i]);
    for (int i = tid; i < 768; i += 256) sB[i] = g_wbias[i];
    __syncthreads();
    const __half2* sW2 = reinterpret_cast<const __half2*>(sW);
    int lane = tid & 31, w = tid >> 5;

    for (int rr = 0; rr < 8; rr++) {
        int r = blockIdx.x * 64 + w * 8 + rr;
        if (r >= npad) return;
        if (r >= n) {
#pragma unroll
            for (int c = 0; c < 4; c++)
                *reinterpret_cast<__half2*>(outA + (size_t)r * 256 + 2 * lane + 64 * c) =
                    __floats2half2_rn(0.f, 0.f);
            continue;
        }
        float p0 = 0.f, p1 = 0.f, p2 = 0.f;
        int j0 = g_roff[r], j1 = g_roff[r + 1];
        for (int j = j0 + lane; j < j1; j += 32) {
            int2 e = g_edge[j];
            float wgt = __int_as_float(e.y);
            const float* tr = t1d + (size_t)e.x * 3;
            p0 += wgt * tr[0]; p1 += wgt * tr[1]; p2 += wgt * tr[2];
        }
#pragma unroll
        for (int off = 16; off; off >>= 1) {
            p0 += __shfl_xor_sync(0xffffffffu, p0, off);
            p1 += __shfl_xor_sync(0xffffffffu, p1, off);
            p2 += __shfl_xor_sync(0xffffffffu, p2, off);
        }
        float a[9];
        a[0] = x[r * 3]; a[1] = x[r * 3 + 1]; a[2] = x[r * 3 + 2];
        a[3] = t1d[r * 3]; a[4] = t1d[r * 3 + 1]; a[5] = t1d[r * 3 + 2];
        a[6] = 2.f * p0 - a[0]; a[7] = 2.f * p1 - a[1]; a[8] = 2.f * p2 - a[2];

        float2 pi[4], pc[4], po[4];
#pragma unroll
        for (int c = 0; c < 4; c++) {
            int u = 2 * lane + 64 * c;
            pi[c] = make_float2(sB[u], sB[u + 1]);
            pc[c] = make_float2(sB[256 + u], sB[256 + u + 1]);
            po[c] = make_float2(sB[512 + u], sB[512 + u + 1]);
        }
#pragma unroll
        for (int k = 0; k < 9; k++) {
            float ak = a[k];
            int kb = k * 384;
#pragma unroll
            for (int c = 0; c < 4; c++) {
                int h2i = lane + 32 * c;
                float2 wi = __half22float2(sW2[kb + h2i]);
                pi[c].x += ak * wi.x; pi[c].y += ak * wi.y;
                float2 wc2 = __half22float2(sW2[kb + 128 + h2i]);
                pc[c].x += ak * wc2.x; pc[c].y += ak * wc2.y;
                float2 wo = __half22float2(sW2[kb + 256 + h2i]);
                po[c].x += ak * wo.x; po[c].y += ak * wo.y;
            }
        }
#pragma unroll
        for (int c = 0; c < 4; c++) {
            int u = 2 * lane + 64 * c;
            float I0 = fsig(pi[c].x), T0 = ftanh(pc[c].x), C0 = I0 * T0;
            float O0 = fsig(po[c].x + wcO[u] * C0);
            float y0 = O0 * ftanh(C0); y0 = y0 > 0.f ? y0 : 0.1f * y0;
            float I1 = fsig(pi[c].y), T1 = ftanh(pc[c].y), C1 = I1 * T1;
            float O1 = fsig(po[c].y + wcO[u + 1] * C1);
            float y1 = O1 * ftanh(C1); y1 = y1 > 0.f ? y1 : 0.1f * y1;
            *reinterpret_cast<__half2*>(outA + (size_t)r * 256 + u) =
                __floats2half2_rn(y0, y1);
        }
    }
}

// ====================== fused SpMV + split (fp16 IO, unroll-4) =============

template <int F, int CHEB2>
__global__ void k_spmv_split(const __half* __restrict__ X, const __half* __restrict__ X0,
                             __half* __restrict__ Yd,
                             __half* __restrict__ A2, int Kp, int sec,
                             int n, int npad) {
    const int TPR = F / 4;
    int tid = threadIdx.x;
    int row = blockIdx.x * (256 / TPR) + tid / TPR;
    int f = (tid % TPR) * 4;
    if (row >= npad) return;
    float a0 = 0.f, a1 = 0.f, a2 = 0.f, a3 = 0.f;
    if (row < n) {
        int j0 = g_roff[row], j1 = g_roff[row + 1];
        int j = j0;
        int jend = j0 + ((j1 - j0) & ~3);
        for (; j < jend; j += 4) {
            int2 e0 = g_edge[j], e1 = g_edge[j + 1];
            int2 e2 = g_edge[j + 2], e3 = g_edge[j + 3];
            float2 r0 = *reinterpret_cast<const float2*>(X + (size_t)e0.x * F + f);
            float2 r1 = *reinterpret_cast<const float2*>(X + (size_t)e1.x * F + f);
            float2 r2 = *reinterpret_cast<const float2*>(X + (size_t)e2.x * F + f);
            float2 r3 = *reinterpret_cast<const float2*>(X + (size_t)e3.x * F + f);
            float w0 = __int_as_float(e0.y), w1 = __int_as_float(e1.y);
            float w2 = __int_as_float(e2.y), w3 = __int_as_float(e3.y);
            {
                float2 f01 = __half22float2(*reinterpret_cast<__half2*>(&r0.x));
                float2 f23 = __half22float2(*reinterpret_cast<__half2*>(&r0.y));
                a0 += w0 * f01.x; a1 += w0 * f01.y; a2 += w0 * f23.x; a3 += w0 * f23.y;
            }
            {
                float2 f01 = __half22float2(*reinterpret_cast<__half2*>(&r1.x));
                float2 f23 = __half22float2(*reinterpret_cast<__half2*>(&r1.y));
                a0 += w1 * f01.x; a1 += w1 * f01.y; a2 += w1 * f23.x; a3 += w1 * f23.y;
            }
            {
                float2 f01 = __half22float2(*reinterpret_cast<__half2*>(&r2.x));
                float2 f23 = __half22float2(*reinterpret_cast<__half2*>(&r2.y));
                a0 += w2 * f01.x; a1 += w2 * f01.y; a2 += w2 * f23.x; a3 += w2 * f23.y;
            }
            {
                float2 f01 = __half22float2(*reinterpret_cast<__half2*>(&r3.x));
                float2 f23 = __half22float2(*reinterpret_cast<__half2*>(&r3.y));
                a0 += w3 * f01.x; a1 += w3 * f01.y; a2 += w3 * f23.x; a3 += w3 * f23.y;
            }
        }
        for (; j < j1; j++) {
            int2 e = g_edge[j];
            float w = __int_as_float(e.y);
            float2 raw = *reinterpret_cast<const float2*>(X + (size_t)e.x * F + f);
            float2 f01 = __half22float2(*reinterpret_cast<__half2*>(&raw.x));
            float2 f23 = __half22float2(*reinterpret_cast<__half2*>(&raw.y));
            a0 += w * f01.x; a1 += w * f01.y; a2 += w * f23.x; a3 += w * f23.y;
        }
        if (CHEB2) {
            float2 raw = *reinterpret_cast<const float2*>(X0 + (size_t)row * F + f);
            float2 f01 = __half22float2(*reinterpret_cast<__half2*>(&raw.x));
            float2 f23 = __half22float2(*reinterpret_cast<__half2*>(&raw.y));
            a0 = 2.f * a0 - f01.x; a1 = 2.f * a1 - f01.y;
            a2 = 2.f * a2 - f23.x; a3 = 2.f * a3 - f23.y;
        }
    }
    float2 packed;
    *reinterpret_cast<__half2*>(&packed.x) = __floats2half2_rn(a0, a1);
    *reinterpret_cast<__half2*>(&packed.y) = __floats2half2_rn(a2, a3);
    if (Yd && row < n)
        *reinterpret_cast<float2*>(Yd + (size_t)row * F + f) = packed;
    *reinterpret_cast<float2*>(A2 + (size_t)row * Kp + sec + f) = packed;
}

// ====================== mma.sync fp16 GEMM =================================

#define CP16(dst, src) \
    asm volatile("cp.async.ca.shared.global [%0], [%1], 16;\n" :: "r"(dst), "l"(src))
#define CP_COMMIT() asm volatile("cp.async.commit_group;\n" ::: "memory")
#define CP_WAIT1()  asm volatile("cp.async.wait_group 1;\n" ::: "memory")
#define CP_WAIT0()  asm volatile("cp.async.wait_group 0;\n" ::: "memory")

__device__ __forceinline__ uint32_t smem_u32(const void* p) {
    uint32_t a;
    asm("{ .reg .u64 t; cvta.to.shared.u64 t, %1; cvt.u32.u64 %0, t; }"
        : "=r"(a) : "l"(p));
    return a;
}

__device__ __forceinline__ void ldm_x4(uint32_t* r, uint32_t addr) {
    asm volatile("ldmatrix.sync.aligned.m8n8.x4.shared.b16 {%0,%1,%2,%3}, [%4];"
                 : "=r"(r[0]), "=r"(r[1]), "=r"(r[2]), "=r"(r[3]) : "r"(addr));
}

__device__ __forceinline__ void mma16816h(float* c, const uint32_t* a, const uint32_t* b) {
    asm volatile(
        "mma.sync.aligned.m16n8k16.row.col.f32.f16.f16.f32 "
        "{%0,%1,%2,%3}, {%4,%5,%6,%7}, {%8,%9}, {%0,%1,%2,%3};"
        : "+f"(c[0]), "+f"(c[1]), "+f"(c[2]), "+f"(c[3])
        : "r"(a[0]), "r"(a[1]), "r"(a[2]), "r"(a[3]), "r"(b[0]), "r"(b[1]));
}

// stage layout (80B rows): A rows 0-127, B rows 128-191.
// Stage = 192*80 = 15360B, 3 stages = 46080B.
#define GSTAGE 15360

__global__ __launch_bounds__(256, 2) void gemm_mma2(
    const __half* __restrict__ A, const __half* __restrict__ B,
    const float* __restrict__ bias, void* __restrict__ Cout, int halfOut,
    __half* __restrict__ S, int sKp,
    int M, int Kp, int Nc, int act) {
    extern __shared__ char smem[];
    const uint32_t s0 = smem_u32(smem);
    const int tid = threadIdx.x;
    const int wid = tid >> 5;
    const int lane = tid & 31;
    const int wm = wid & 3, wn = wid >> 2;
    const int bn = blockIdx.x << 6;
    const int bm = blockIdx.y << 7;

    float acc[2][4][4];
#pragma unroll
    for (int i = 0; i < 2; i++)
#pragma unroll
        for (int j = 0; j < 4; j++)
#pragma unroll
            for (int k = 0; k < 4; k++) acc[i][j][k] = 0.f;

#define LOAD_STAGE(stg, kc) do {                                             \
    uint32_t dstBase = s0 + (stg) * GSTAGE;                                  \
    _Pragma("unroll")                                                        \
    for (int u = tid; u < 768; u += 256) {                                   \
        uint32_t d; const char* g;                                           \
        if (u < 512) {                                                       \
            int row = u >> 2, seg = u & 3;                                   \
            d = dstBase + row * 80 + seg * 16;                               \
            g = (const char*)A + ((size_t)(bm + row) * Kp + (kc)) * 2        \
                + seg * 16;                                                  \
        } else {                                                             \
            int t = u - 512; int row = t >> 2, seg = t & 3;                  \
            d = dstBase + (128 + row) * 80 + seg * 16;                       \
            g = (const char*)B + ((size_t)(bn + row) * Kp + (kc)) * 2        \
                + seg * 16;                                                  \
        }                                                                    \
        CP16(d, g);                                                          \
    } } while (0)

    const int nK = Kp >> 5;
    LOAD_STAGE(0, 0);
    CP_COMMIT();
    if (nK > 1) { LOAD_STAGE(1, 32); CP_COMMIT(); }

    for (int kt = 0; kt < nK; kt++) {
        if (kt + 1 < nK) CP_WAIT1(); else CP_WAIT0();
        __syncthreads();
        if (kt + 2 < nK) {
            LOAD_STAGE((kt + 2) % 3, (kt + 2) << 5);
            CP_COMMIT();
        }
        uint32_t base = s0 + (kt % 3) * GSTAGE;
        uint32_t kb = (lane >> 4) * 16;
        uint32_t arow = wm * 32 + (lane & 15);
        uint32_t brow = 128 + wn * 32 + (lane & 15);
#pragma unroll
        for (int kk = 0; kk < 2; kk++) {
            uint32_t a[2][4];
#pragma unroll
            for (int mt = 0; mt < 2; mt++)
                ldm_x4(a[mt], base + (arow + mt * 16) * 80 + kk * 32 + kb);
            uint32_t b[4][2];
#pragma unroll
            for (int j = 0; j < 2; j++) {
                uint32_t r[4];
                ldm_x4(r, base + (brow + j * 16) * 80 + kk * 32 + kb);
                b[2 * j][0] = r[0]; b[2 * j][1] = r[2];
                b[2 * j + 1][0] = r[1]; b[2 * j + 1][1] = r[3];
            }
#pragma unroll
            for (int mt = 0; mt < 2; mt++)
#pragma unroll
                for (int nt = 0; nt < 4; nt++)
                    mma16816h(acc[mt][nt], a[mt], b[nt]);
        }
    }

    // epilogue
    const int gid = lane >> 2, tig = lane & 3;
#pragma unroll
    for (int mt = 0; mt < 2; mt++) {
#pragma unroll
        for (int half = 0; half < 2; half++) {
            int row = bm + wm * 32 + mt * 16 + half * 8 + gid;
            bool valid = row < M;
#pragma unroll
            for (int nt = 0; nt < 4; nt++) {
                int col = bn + wn * 32 + nt * 8 + tig * 2;
                float v0 = 0.f, v1 = 0.f;
                if (valid) {
                    v0 = acc[mt][nt][2 * half + 0] + bias[col];
                    v1 = acc[mt][nt][2 * half + 1] + bias[col + 1];
                    if (act) {
                        v0 = v0 > 0.f ? v0 : 0.1f * v0;
                        v1 = v1 > 0.f ? v1 : 0.1f * v1;
                    }
                    if (halfOut) {
                        *reinterpret_cast<__half2*>(
                            (__half*)Cout + (size_t)row * Nc + col) =
                            __floats2half2_rn(v0, v1);
                    } else {
                        *reinterpret_cast<float2*>(
                            (float*)Cout + (size_t)row * Nc + col) =
                            make_float2(v0, v1);
                    }
                }
                if (S) {
                    *reinterpret_cast<__half2*>(S + (size_t)row * sKp + col) =
                        __floats2half2_rn(v0, v1);
                }
            }
        }
    }
}

// ====================== layer-2 gate fusion (half2 vectorized) =============

__global__ void k_gates_split(const __half* __restrict__ G, const float* __restrict__ wcO,
                              __half* __restrict__ A2, int n, int npad, int H) {
    int idx = blockIdx.x * blockDim.x + threadIdx.x;
    int half_per_row = H >> 1;
    if (idx >= npad * half_per_row) return;
    int r = idx / half_per_row, o2 = (idx % half_per_row) * 2;
    float y0 = 0.f, y1 = 0.f;
    if (r < n) {
        const __half* g = G + (size_t)r * 3 * H;
        float2 gi = __half22float2(*reinterpret_cast<const __half2*>(g + o2));
        float2 gc = __half22float2(*reinterpret_cast<const __half2*>(g + H + o2));
        float2 go = __half22float2(*reinterpret_cast<const __half2*>(g + 2 * H + o2));
        float I0 = fsig(gi.x), T0 = ftanh(gc.x), C0 = I0 * T0;
        float O0 = fsig(go.x + wcO[o2] * C0);
        y0 = O0 * ftanh(C0); y0 = y0 > 0.f ? y0 : 0.1f * y0;
        float I1 = fsig(gi.y), T1 = ftanh(gc.y), C1 = I1 * T1;
        float O1 = fsig(go.y + wcO[o2 + 1] * C1);
        y1 = O1 * ftanh(C1); y1 = y1 > 0.f ? y1 : 0.1f * y1;
    }
    *reinterpret_cast<__half2*>(A2 + (size_t)r * H + o2) = __floats2half2_rn(y0, y1);
}

// ====================== layer-3 fused tail: gates + lin3 ===================

__global__ __launch_bounds__(256) void k_gates_lin3(
    const __half* __restrict__ G, const float* __restrict__ wcO,
    const float* __restrict__ W, const float* __restrict__ b,
    float* __restrict__ out, int n) {
    __shared__ float sW3[192];
    int tid = threadIdx.x;
    if (tid < 192) sW3[tid] = W[tid];
    __syncthreads();
    int lane = tid & 31, w = tid >> 5;
    for (int rr = 0; rr < 8; rr++) {
        int r = blockIdx.x * 64 + w * 8 + rr;
        if (r >= n) return;
        const __half* g = G + (size_t)r * 192;
        float p0 = 0.f, p1 = 0.f, p2 = 0.f;
#pragma unroll
        for (int k = 0; k < 2; k++) {
            int u = lane + 32 * k;
            float I = fsig(__half2float(g[u]));
            float T = ftanh(__half2float(g[64 + u]));
            float Cv = I * T;
            float O = fsig(__half2float(g[128 + u]) + wcO[u] * Cv);
            float y = O * ftanh(Cv);
            y = y > 0.f ? y : 0.1f * y;
            p0 += y * sW3[u * 3]; p1 += y * sW3[u * 3 + 1]; p2 += y * sW3[u * 3 + 2];
        }
#pragma unroll
        for (int off = 16; off; off >>= 1) {
            p0 += __shfl_xor_sync(0xffffffffu, p0, off);
            p1 += __shfl_xor_sync(0xffffffffu, p1, off);
            p2 += __shfl_xor_sync(0xffffffffu, p2, off);
        }
        if (lane == 0) {
            out[r * 3] = p0 + b[0];
            out[r * 3 + 1] = p1 + b[1];
            out[r * 3 + 2] = p2 + b[2];
        }
    }
}

// ====================== host orchestration =================================

static inline int ceildiv(int a, int b) { return (a + b - 1) / b; }

extern "C" void kernel_launch(void* const* d_in, const int* in_sizes, int n_in,
                              void* d_out, int out_size) {
    const float* x = (const float*)d_in[0];
    const int* ei = (const int*)d_in[1];
    int N = in_sizes[0] / 3;
    int E = in_sizes[1] / 2;
    const int* src = ei;
    const int* dst = ei + E;
    int Npad = (N + 127) & ~127;
    int Mt = Npad / 128;

    const float* l1_Wx = (const float*)d_in[2];
    const float* l1_bx = (const float*)d_in[3];
    const float* l1_bh = (const float*)d_in[5];
    const float* l1_wc = (const float*)d_in[6];
    const float* l1_b  = (const float*)d_in[7];
    const float* l2_Wx = (const float*)d_in[8];
    const float* l2_bx = (const float*)d_in[9];
    const float* l2_bh = (const float*)d_in[11];
    const float* l2_wc = (const float*)d_in[12];
    const float* l2_b  = (const float*)d_in[13];
    const float* l3_Wx = (const float*)d_in[14];
    const float* l3_bx = (const float*)d_in[15];
    const float* l3_bh = (const float*)d_in[17];
    const float* l3_wc = (const float*)d_in[18];
    const float* l3_b  = (const float*)d_in[19];
    const float* lin1_W = (const float*)d_in[20];
    const float* lin1_b = (const float*)d_in[21];
    const float* lin2_W = (const float*)d_in[22];
    const float* lin2_b = (const float*)d_in[23];
    const float* lin3_W = (const float*)d_in[24];
    const float* lin3_b = (const float*)d_in[25];
    float* out = (float*)d_out;

    void* p;
    cudaGetSymbolAddress(&p, g_tmp);   int* tmp = (int*)p;
    cudaGetSymbolAddress(&p, g_xc);    float* xcf = (float*)p;
    __half* xch = (__half*)xcf;
    cudaGetSymbolAddress(&p, g_gate);  __half* G = (__half*)p;
    cudaGetSymbolAddress(&p, g_h2);    __half* H2 = (__half*)p;
    cudaGetSymbolAddress(&p, g_wbias); float* wb = (float*)p;
    cudaGetSymbolAddress(&p, g_bufA);  __half* bufA = (__half*)p;
    cudaGetSymbolAddress(&p, g_bufB);  __half* bufB = (__half*)p;
    cudaGetSymbolAddress(&p, g_bbuf);  __half* bb = (__half*)p;

    cudaFuncSetAttribute(gemm_mma2, cudaFuncAttributeMaxDynamicSharedMemorySize,
                         3 * GSTAGE);

    cudaStream_t s = 0;

    // ---- graph preprocessing ----
    cudaMemsetAsync(tmp, 0, 3 * MAXN * sizeof(int), s);
    k_degree<<<ceildiv(E, 256), 256, 0, s>>>(src, dst, E);
    k_scan<<<1, 1024, 0, s>>>(N);
    k_fill<<<ceildiv(E, 256), 256, 0, s>>>(src, dst, E);

    // ---- all weight/bias preprocessing in one kernel ----
    k_prep_all<<<ceildiv(E6, 256), 256, 0, s>>>(
        l1_Wx, l2_Wx, l3_Wx, lin1_W, lin2_W,
        l1_bx, l1_bh, l1_b, l2_bx, l2_bh, l2_b, l3_bx, l3_bh, l3_b);

    // ================= layer 1 (F=3, H=256) — fully fused ===================
    k_l1a<<<ceildiv(N, 256), 256, 0, s>>>(x, xcf, N);
    k_l1gates<<<ceildiv(Npad, 64), 256, 0, s>>>(x, xcf, l1_wc + 512, bufB, N, Npad);
    // lin1: [N,256]@[256,128] + lrelu -> fp16 H2 + T0 section of layer2 A
    gemm_mma2<<<dim3(128 / 64, Mt), 256, 3 * GSTAGE, s>>>(
        bufB, bb + O_BL1, lin1_b, H2, 1, bufA, 384, N, 256, 128, 1);

    // ================= layer 2 (F=128, H=128) =================
    k_spmv_split<128, 0><<<ceildiv(Npad, 8), 256, 0, s>>>(H2, nullptr, xch, bufA, 384, 128, N, Npad);
    k_spmv_split<128, 1><<<ceildiv(Npad, 8), 256, 0, s>>>(xch, H2, nullptr, bufA, 384, 256, N, Npad);
    gemm_mma2<<<dim3(384 / 64, Mt), 256, 3 * GSTAGE, s>>>(
        bufA, bb + O_B2, wb + 768, G, 1, nullptr, 0, N, 384, 384, 0);
    k_gates_split<<<ceildiv(Npad * 64, 256), 256, 0, s>>>(G, l2_wc + 256, bufB, N, Npad, 128);
    // lin2: [N,128]@[128,64] + lrelu -> fp16 H2 + T0 section of layer3 A
    gemm_mma2<<<dim3(64 / 64, Mt), 256, 3 * GSTAGE, s>>>(
        bufB, bb + O_BL2, lin2_b, H2, 1, bufA, 192, N, 128, 64, 1);

    // ================= layer 3 (F=64, H=64) =================
    k_spmv_split<64, 0><<<ceildiv(Npad, 16), 256, 0, s>>>(H2, nullptr, xch, bufA, 192, 64, N, Npad);
    k_spmv_split<64, 1><<<ceildiv(Npad, 16), 256, 0, s>>>(xch, H2, nullptr, bufA, 192, 128, N, Npad);
    gemm_mma2<<<dim3(192 / 64, Mt), 256, 3 * GSTAGE, s>>>(
        bufA, bb + O_B3, wb + 1152, G, 1, nullptr, 0, N, 192, 192, 0);
    k_gates_lin3<<<ceildiv(N, 64), 256, 0, s>>>(G, l3_wc + 128, lin3_W, lin3_b, out, N);
}

// round 11
// speedup vs baseline: 2.1105x; 1.0940x over previous
#include <cuda_runtime.h>
#include <cuda_fp16.h>
#include <math.h>
#include <stdint.h>

// ---------------- problem-size caps (fixed by setup_inputs) ----------------
#define MAXN 50000
#define NPADMAX 50048   // MAXN rounded up to 128

// ---------------- device scratch (no allocation allowed) -------------------
__device__ int   g_tmp[3 * MAXN];    // deg | cnt | cur (one memset)
__device__ int   g_roff[MAXN + 1];
__device__ int2  g_edge[800000];     // packed (src, weight-bits)
__device__ float g_xc[(size_t)MAXN * 384];     // dense Tx1 scratch (fp16 view) / l1 fp32
__device__ float g_h2[(size_t)MAXN * 128];     // post-linear output (fp16 view)
__device__ float g_wbias[1344];                // combined gate biases (l1|l2|l3)
__device__ float g_w1t[9 * 768];               // layer1 gate weights transposed fp32
__device__ __align__(256) __half g_bufA[(size_t)NPADMAX * 384]; // gconv A (single)
__device__ __align__(256) __half g_bufB[(size_t)NPADMAX * 256]; // lin A / gate-out
__device__ __align__(256) __half g_bbuf[262144];                // weights fp16

// weight buffer element offsets (rows x Kp, single fp16)
#define O_B2  24576    // l2 gate: 384 x 384
#define O_B3  172032   // l3 gate: 192 x 192
#define O_BL1 208896   // lin1: 128 x 256
#define O_BL2 241664   // lin2: 64 x 128

// ====================== graph preprocessing ================================

__global__ void k_degree(const int* __restrict__ src, const int* __restrict__ dst, int E) {
    int e = blockIdx.x * blockDim.x + threadIdx.x;
    if (e >= E) return;
    atomicAdd(&g_tmp[src[e]], 1);            // deg
    atomicAdd(&g_tmp[MAXN + dst[e]], 1);     // cnt
}

__global__ void k_scan(int n) {
    __shared__ int ssum[1024];
    int tid = threadIdx.x;
    const int T = 1024;
    int chunk = (n + T - 1) / T;
    int beg = tid * chunk;
    int end = beg + chunk; if (end > n) end = n;
    int s = 0;
    for (int i = beg; i < end; i++) s += g_tmp[MAXN + i];
    ssum[tid] = s;
    __syncthreads();
    for (int off = 1; off < T; off <<= 1) {
        int v = (tid >= off) ? ssum[tid - off] : 0;
        __syncthreads();
        ssum[tid] += v;
        __syncthreads();
    }
    int run = (tid > 0) ? ssum[tid - 1] : 0;
    for (int i = beg; i < end; i++) { g_roff[i] = run; run += g_tmp[MAXN + i]; }
    if (tid == T - 1) g_roff[n] = ssum[T - 1];
}

__global__ void k_fill(const int* __restrict__ src, const int* __restrict__ dst, int E) {
    int e = blockIdx.x * blockDim.x + threadIdx.x;
    if (e >= E) return;
    int s = src[e], d = dst[e];
    int pos = g_roff[d] + atomicAdd(&g_tmp[2 * MAXN + d], 1);
    int ds = g_tmp[s], dd = g_tmp[d];
    float is = ds > 0 ? rsqrtf((float)ds) : 0.0f;
    float id = dd > 0 ? rsqrtf((float)dd) : 0.0f;
    g_edge[pos] = make_int2(s, __float_as_int(-is * id));
}

// ====================== merged weight/bias preprocessing ===================

__device__ __forceinline__ void prep_gateB(const float* __restrict__ Wx, int F, int H,
                                           int Kp, int nrow, int kk,
                                           __half* __restrict__ dst) {
    int gp = nrow / H, o = nrow % H;
    int gate = (gp == 0) ? 0 : (gp + 1);   // gates {0,2,3}
    float w = 0.0f;
    if (kk < 3 * F) {
        int kc = kk / F, f = kk % F;
        w = Wx[(((size_t)gate * 3 + kc) * F + f) * H + o];
    }
    dst[(size_t)nrow * Kp + kk] = __float2half_rn(w);
}

__device__ __forceinline__ void prep_linB(const float* __restrict__ W, int Hout,
                                          int Kp, int nrow, int kk,
                                          __half* __restrict__ dst) {
    dst[(size_t)nrow * Kp + kk] = __float2half_rn(W[(size_t)kk * Hout + nrow]);
}

#define E1 24576     // 768*32 (layer1 -> transposed fp32 table)
#define E2 172032    // +384*384
#define E3 208896    // +192*192
#define E4 241664    // +128*256
#define E5 249856    // +64*128
#define E6 251200    // +1344 biases

__global__ void k_prep_all(
    const float* __restrict__ w1, const float* __restrict__ w2, const float* __restrict__ w3,
    const float* __restrict__ wl1, const float* __restrict__ wl2,
    const float* __restrict__ bx1, const float* __restrict__ bh1, const float* __restrict__ b1,
    const float* __restrict__ bx2, const float* __restrict__ bh2, const float* __restrict__ b2,
    const float* __restrict__ bx3, const float* __restrict__ bh3, const float* __restrict__ b3) {
    int idx = blockIdx.x * blockDim.x + threadIdx.x;
    if (idx >= E6) return;
    if (idx < E1) {
        int nrow = idx / 32, kk = idx % 32;
        if (kk < 9) {
            int gp = nrow / 256, o = nrow % 256;
            int gate = (gp == 0) ? 0 : (gp + 1);
            int kc = kk / 3, f = kk % 3;
            g_w1t[kk * 768 + nrow] = w1[(((size_t)gate * 3 + kc) * 3 + f) * 256 + o];
        }
    } else if (idx < E2) {
        int t = idx - E1;
        prep_gateB(w2, 128, 128, 384, t / 384, t % 384, g_bbuf + O_B2);
    } else if (idx < E3) {
        int t = idx - E2;
        prep_gateB(w3, 64, 64, 192, t / 192, t % 192, g_bbuf + O_B3);
    } else if (idx < E4) {
        int t = idx - E3;
        prep_linB(wl1, 128, 256, t / 256, t % 256, g_bbuf + O_BL1);
    } else if (idx < E5) {
        int t = idx - E4;
        prep_linB(wl2, 64, 128, t / 128, t % 128, g_bbuf + O_BL2);
    } else {
        int t = idx - E5;
        const float *bx, *bh, *bb; int H, base;
        if (t < 768)       { bx = bx1; bh = bh1; bb = b1; H = 256; base = 0; }
        else if (t < 1152) { bx = bx2; bh = bh2; bb = b2; H = 128; base = 768; t -= 768; }
        else               { bx = bx3; bh = bh3; bb = b3; H = 64;  base = 1152; t -= 1152; }
        int gp = t / H, o = t % H;
        int gate = (gp == 0) ? 0 : (gp + 1);
        g_wbias[base + t] = bx[gate * H + o] + bh[gate * H + o] + bb[gate * H + o];
    }
}

// ====================== fast transcendentals (HW tanh) =====================

__device__ __forceinline__ float ftanh(float x) {
    float y;
    asm("tanh.approx.f32 %0, %1;" : "=f"(y) : "f"(x));
    return y;
}
__device__ __forceinline__ float fsig(float x) {
    return fmaf(ftanh(0.5f * x), 0.5f, 0.5f);
}

// ====================== layer-1: T1 dense pass (unroll-4) ==================

__global__ void k_l1a(const float* __restrict__ x, float* __restrict__ t1d, int n) {
    int row = blockIdx.x * blockDim.x + threadIdx.x;
    if (row >= n) return;
    float t1[3] = {0, 0, 0};
    int j0 = g_roff[row], j1 = g_roff[row + 1];
    int j = j0;
    int jend = j0 + ((j1 - j0) & ~3);
    for (; j < jend; j += 4) {
        int2 e0 = g_edge[j], e1 = g_edge[j + 1], e2 = g_edge[j + 2], e3 = g_edge[j + 3];
        const float* x0 = x + (size_t)e0.x * 3;
        const float* x1 = x + (size_t)e1.x * 3;
        const float* x2 = x + (size_t)e2.x * 3;
        const float* x3 = x + (size_t)e3.x * 3;
        float v00 = x0[0], v01 = x0[1], v02 = x0[2];
        float v10 = x1[0], v11 = x1[1], v12 = x1[2];
        float v20 = x2[0], v21 = x2[1], v22 = x2[2];
        float v30 = x3[0], v31 = x3[1], v32 = x3[2];
        float w0 = __int_as_float(e0.y), w1 = __int_as_float(e1.y);
        float w2 = __int_as_float(e2.y), w3 = __int_as_float(e3.y);
        t1[0] += w0 * v00 + w1 * v10 + w2 * v20 + w3 * v30;
        t1[1] += w0 * v01 + w1 * v11 + w2 * v21 + w3 * v31;
        t1[2] += w0 * v02 + w1 * v12 + w2 * v22 + w3 * v32;
    }
    for (; j < j1; j++) {
        int2 e = g_edge[j];
        float w = __int_as_float(e.y);
        const float* xr = x + (size_t)e.x * 3;
        t1[0] += w * xr[0]; t1[1] += w * xr[1]; t1[2] += w * xr[2];
    }
    t1d[row * 3] = t1[0]; t1d[row * 3 + 1] = t1[1]; t1d[row * 3 + 2] = t1[2];
}

// ====================== layer-1 fused: T2 gather + gates -> bufB ===========

__global__ __launch_bounds__(256) void k_l1gates(
    const float* __restrict__ x, const float* __restrict__ t1d,
    const float* __restrict__ wcO, __half* __restrict__ outA, int n, int npad) {
    __shared__ __half sW[9 * 768];
    __shared__ float sB[768];
    int tid = threadIdx.x;
    for (int i = tid; i < 9 * 768; i += 256) sW[i] = __float2half_rn(g_w1t[i]);
    for (int i = tid; i < 768; i += 256) sB[i] = g_wbias[i];
    __syncthreads();
    const __half2* sW2 = reinterpret_cast<const __half2*>(sW);
    int lane = tid & 31, w = tid >> 5;

    for (int rr = 0; rr < 8; rr++) {
        int r = blockIdx.x * 64 + w * 8 + rr;
        if (r >= npad) return;
        if (r >= n) {
#pragma unroll
            for (int c = 0; c < 4; c++)
                *reinterpret_cast<__half2*>(outA + (size_t)r * 256 + 2 * lane + 64 * c) =
                    __floats2half2_rn(0.f, 0.f);
            continue;
        }
        float p0 = 0.f, p1 = 0.f, p2 = 0.f;
        int j0 = g_roff[r], j1 = g_roff[r + 1];
        for (int j = j0 + lane; j < j1; j += 32) {
            int2 e = g_edge[j];
            float wgt = __int_as_float(e.y);
            const float* tr = t1d + (size_t)e.x * 3;
            p0 += wgt * tr[0]; p1 += wgt * tr[1]; p2 += wgt * tr[2];
        }
#pragma unroll
        for (int off = 16; off; off >>= 1) {
            p0 += __shfl_xor_sync(0xffffffffu, p0, off);
            p1 += __shfl_xor_sync(0xffffffffu, p1, off);
            p2 += __shfl_xor_sync(0xffffffffu, p2, off);
        }
        float a[9];
        a[0] = x[r * 3]; a[1] = x[r * 3 + 1]; a[2] = x[r * 3 + 2];
        a[3] = t1d[r * 3]; a[4] = t1d[r * 3 + 1]; a[5] = t1d[r * 3 + 2];
        a[6] = 2.f * p0 - a[0]; a[7] = 2.f * p1 - a[1]; a[8] = 2.f * p2 - a[2];

        float2 pi[4], pc[4], po[4];
#pragma unroll
        for (int c = 0; c < 4; c++) {
            int u = 2 * lane + 64 * c;
            pi[c] = make_float2(sB[u], sB[u + 1]);
            pc[c] = make_float2(sB[256 + u], sB[256 + u + 1]);
            po[c] = make_float2(sB[512 + u], sB[512 + u + 1]);
        }
#pragma unroll
        for (int k = 0; k < 9; k++) {
            float ak = a[k];
            int kb = k * 384;
#pragma unroll
            for (int c = 0; c < 4; c++) {
                int h2i = lane + 32 * c;
                float2 wi = __half22float2(sW2[kb + h2i]);
                pi[c].x += ak * wi.x; pi[c].y += ak * wi.y;
                float2 wc2 = __half22float2(sW2[kb + 128 + h2i]);
                pc[c].x += ak * wc2.x; pc[c].y += ak * wc2.y;
                float2 wo = __half22float2(sW2[kb + 256 + h2i]);
                po[c].x += ak * wo.x; po[c].y += ak * wo.y;
            }
        }
#pragma unroll
        for (int c = 0; c < 4; c++) {
            int u = 2 * lane + 64 * c;
            float I0 = fsig(pi[c].x), T0 = ftanh(pc[c].x), C0 = I0 * T0;
            float O0 = fsig(po[c].x + wcO[u] * C0);
            float y0 = O0 * ftanh(C0); y0 = y0 > 0.f ? y0 : 0.1f * y0;
            float I1 = fsig(pi[c].y), T1 = ftanh(pc[c].y), C1 = I1 * T1;
            float O1 = fsig(po[c].y + wcO[u + 1] * C1);
            float y1 = O1 * ftanh(C1); y1 = y1 > 0.f ? y1 : 0.1f * y1;
            *reinterpret_cast<__half2*>(outA + (size_t)r * 256 + u) =
                __floats2half2_rn(y0, y1);
        }
    }
}

// ====================== fused SpMV + split (fp16 IO, unroll-4) =============

template <int F, int CHEB2>
__global__ void k_spmv_split(const __half* __restrict__ X, const __half* __restrict__ X0,
                             __half* __restrict__ Yd,
                             __half* __restrict__ A2, int Kp, int sec,
                             int n, int npad) {
    const int TPR = F / 4;
    int tid = threadIdx.x;
    int row = blockIdx.x * (256 / TPR) + tid / TPR;
    int f = (tid % TPR) * 4;
    if (row >= npad) return;
    float a0 = 0.f, a1 = 0.f, a2 = 0.f, a3 = 0.f;
    if (row < n) {
        int j0 = g_roff[row], j1 = g_roff[row + 1];
        int j = j0;
        int jend = j0 + ((j1 - j0) & ~3);
        for (; j < jend; j += 4) {
            int2 e0 = g_edge[j], e1 = g_edge[j + 1];
            int2 e2 = g_edge[j + 2], e3 = g_edge[j + 3];
            float2 r0 = *reinterpret_cast<const float2*>(X + (size_t)e0.x * F + f);
            float2 r1 = *reinterpret_cast<const float2*>(X + (size_t)e1.x * F + f);
            float2 r2 = *reinterpret_cast<const float2*>(X + (size_t)e2.x * F + f);
            float2 r3 = *reinterpret_cast<const float2*>(X + (size_t)e3.x * F + f);
            float w0 = __int_as_float(e0.y), w1 = __int_as_float(e1.y);
            float w2 = __int_as_float(e2.y), w3 = __int_as_float(e3.y);
            {
                float2 f01 = __half22float2(*reinterpret_cast<__half2*>(&r0.x));
                float2 f23 = __half22float2(*reinterpret_cast<__half2*>(&r0.y));
                a0 += w0 * f01.x; a1 += w0 * f01.y; a2 += w0 * f23.x; a3 += w0 * f23.y;
            }
            {
                float2 f01 = __half22float2(*reinterpret_cast<__half2*>(&r1.x));
                float2 f23 = __half22float2(*reinterpret_cast<__half2*>(&r1.y));
                a0 += w1 * f01.x; a1 += w1 * f01.y; a2 += w1 * f23.x; a3 += w1 * f23.y;
            }
            {
                float2 f01 = __half22float2(*reinterpret_cast<__half2*>(&r2.x));
                float2 f23 = __half22float2(*reinterpret_cast<__half2*>(&r2.y));
                a0 += w2 * f01.x; a1 += w2 * f01.y; a2 += w2 * f23.x; a3 += w2 * f23.y;
            }
            {
                float2 f01 = __half22float2(*reinterpret_cast<__half2*>(&r3.x));
                float2 f23 = __half22float2(*reinterpret_cast<__half2*>(&r3.y));
                a0 += w3 * f01.x; a1 += w3 * f01.y; a2 += w3 * f23.x; a3 += w3 * f23.y;
            }
        }
        for (; j < j1; j++) {
            int2 e = g_edge[j];
            float w = __int_as_float(e.y);
            float2 raw = *reinterpret_cast<const float2*>(X + (size_t)e.x * F + f);
            float2 f01 = __half22float2(*reinterpret_cast<__half2*>(&raw.x));
            float2 f23 = __half22float2(*reinterpret_cast<__half2*>(&raw.y));
            a0 += w * f01.x; a1 += w * f01.y; a2 += w * f23.x; a3 += w * f23.y;
        }
        if (CHEB2) {
            float2 raw = *reinterpret_cast<const float2*>(X0 + (size_t)row * F + f);
            float2 f01 = __half22float2(*reinterpret_cast<__half2*>(&raw.x));
            float2 f23 = __half22float2(*reinterpret_cast<__half2*>(&raw.y));
            a0 = 2.f * a0 - f01.x; a1 = 2.f * a1 - f01.y;
            a2 = 2.f * a2 - f23.x; a3 = 2.f * a3 - f23.y;
        }
    }
    float2 packed;
    *reinterpret_cast<__half2*>(&packed.x) = __floats2half2_rn(a0, a1);
    *reinterpret_cast<__half2*>(&packed.y) = __floats2half2_rn(a2, a3);
    if (Yd && row < n)
        *reinterpret_cast<float2*>(Yd + (size_t)row * F + f) = packed;
    *reinterpret_cast<float2*>(A2 + (size_t)row * Kp + sec + f) = packed;
}

// ====================== mma.sync common helpers ============================

#define CP16(dst, src) \
    asm volatile("cp.async.ca.shared.global [%0], [%1], 16;\n" :: "r"(dst), "l"(src))
#define CP_COMMIT() asm volatile("cp.async.commit_group;\n" ::: "memory")
#define CP_WAIT1()  asm volatile("cp.async.wait_group 1;\n" ::: "memory")
#define CP_WAIT0()  asm volatile("cp.async.wait_group 0;\n" ::: "memory")

__device__ __forceinline__ uint32_t smem_u32(const void* p) {
    uint32_t a;
    asm("{ .reg .u64 t; cvta.to.shared.u64 t, %1; cvt.u32.u64 %0, t; }"
        : "=r"(a) : "l"(p));
    return a;
}

__device__ __forceinline__ void ldm_x4(uint32_t* r, uint32_t addr) {
    asm volatile("ldmatrix.sync.aligned.m8n8.x4.shared.b16 {%0,%1,%2,%3}, [%4];"
                 : "=r"(r[0]), "=r"(r[1]), "=r"(r[2]), "=r"(r[3]) : "r"(addr));
}

__device__ __forceinline__ void mma16816h(float* c, const uint32_t* a, const uint32_t* b) {
    asm volatile(
        "mma.sync.aligned.m16n8k16.row.col.f32.f16.f16.f32 "
        "{%0,%1,%2,%3}, {%4,%5,%6,%7}, {%8,%9}, {%0,%1,%2,%3};"
        : "+f"(c[0]), "+f"(c[1]), "+f"(c[2]), "+f"(c[3])
        : "r"(a[0]), "r"(a[1]), "r"(a[2]), "r"(a[3]), "r"(b[0]), "r"(b[1]));
}

// ====================== plain fp16 GEMM (lin layers) =======================
// stage layout (80B rows): A rows 0-127, B rows 128-191. Stage = 15360B.
#define GSTAGE 15360

__global__ __launch_bounds__(256, 2) void gemm_mma2(
    const __half* __restrict__ A, const __half* __restrict__ B,
    const float* __restrict__ bias, void* __restrict__ Cout, int halfOut,
    __half* __restrict__ S, int sKp,
    int M, int Kp, int Nc, int act) {
    extern __shared__ char smem[];
    const uint32_t s0 = smem_u32(smem);
    const int tid = threadIdx.x;
    const int wid = tid >> 5;
    const int lane = tid & 31;
    const int wm = wid & 3, wn = wid >> 2;
    const int bn = blockIdx.x << 6;
    const int bm = blockIdx.y << 7;

    float acc[2][4][4];
#pragma unroll
    for (int i = 0; i < 2; i++)
#pragma unroll
        for (int j = 0; j < 4; j++)
#pragma unroll
            for (int k = 0; k < 4; k++) acc[i][j][k] = 0.f;

#define LOAD_STAGE(stg, kc) do {                                             \
    uint32_t dstBase = s0 + (stg) * GSTAGE;                                  \
    _Pragma("unroll")                                                        \
    for (int u = tid; u < 768; u += 256) {                                   \
        uint32_t d; const char* g;                                           \
        if (u < 512) {                                                       \
            int row = u >> 2, seg = u & 3;                                   \
            d = dstBase + row * 80 + seg * 16;                               \
            g = (const char*)A + ((size_t)(bm + row) * Kp + (kc)) * 2        \
                + seg * 16;                                                  \
        } else {                                                             \
            int t = u - 512; int row = t >> 2, seg = t & 3;                  \
            d = dstBase + (128 + row) * 80 + seg * 16;                       \
            g = (const char*)B + ((size_t)(bn + row) * Kp + (kc)) * 2        \
                + seg * 16;                                                  \
        }                                                                    \
        CP16(d, g);                                                          \
    } } while (0)

    const int nK = Kp >> 5;
    LOAD_STAGE(0, 0);
    CP_COMMIT();
    if (nK > 1) { LOAD_STAGE(1, 32); CP_COMMIT(); }

    for (int kt = 0; kt < nK; kt++) {
        if (kt + 1 < nK) CP_WAIT1(); else CP_WAIT0();
        __syncthreads();
        if (kt + 2 < nK) {
            LOAD_STAGE((kt + 2) % 3, (kt + 2) << 5);
            CP_COMMIT();
        }
        uint32_t base = s0 + (kt % 3) * GSTAGE;
        uint32_t kb = (lane >> 4) * 16;
        uint32_t arow = wm * 32 + (lane & 15);
        uint32_t brow = 128 + wn * 32 + (lane & 15);
#pragma unroll
        for (int kk = 0; kk < 2; kk++) {
            uint32_t a[2][4];
#pragma unroll
            for (int mt = 0; mt < 2; mt++)
                ldm_x4(a[mt], base + (arow + mt * 16) * 80 + kk * 32 + kb);
            uint32_t b[4][2];
#pragma unroll
            for (int j = 0; j < 2; j++) {
                uint32_t r[4];
                ldm_x4(r, base + (brow + j * 16) * 80 + kk * 32 + kb);
                b[2 * j][0] = r[0]; b[2 * j][1] = r[2];
                b[2 * j + 1][0] = r[1]; b[2 * j + 1][1] = r[3];
            }
#pragma unroll
            for (int mt = 0; mt < 2; mt++)
#pragma unroll
                for (int nt = 0; nt < 4; nt++)
                    mma16816h(acc[mt][nt], a[mt], b[nt]);
        }
    }

    const int gid = lane >> 2, tig = lane & 3;
#pragma unroll
    for (int mt = 0; mt < 2; mt++) {
#pragma unroll
        for (int half = 0; half < 2; half++) {
            int row = bm + wm * 32 + mt * 16 + half * 8 + gid;
            bool valid = row < M;
#pragma unroll
            for (int nt = 0; nt < 4; nt++) {
                int col = bn + wn * 32 + nt * 8 + tig * 2;
                float v0 = 0.f, v1 = 0.f;
                if (valid) {
                    v0 = acc[mt][nt][2 * half + 0] + bias[col];
                    v1 = acc[mt][nt][2 * half + 1] + bias[col + 1];
                    if (act) {
                        v0 = v0 > 0.f ? v0 : 0.1f * v0;
                        v1 = v1 > 0.f ? v1 : 0.1f * v1;
                    }
                    if (halfOut) {
                        *reinterpret_cast<__half2*>(
                            (__half*)Cout + (size_t)row * Nc + col) =
                            __floats2half2_rn(v0, v1);
                    } else {
                        *reinterpret_cast<float2*>(
                            (float*)Cout + (size_t)row * Nc + col) =
                            make_float2(v0, v1);
                    }
                }
                if (S) {
                    *reinterpret_cast<__half2*>(S + (size_t)row * sKp + col) =
                        __floats2half2_rn(v0, v1);
                }
            }
        }
    }
}

// ====================== fused gate GEMM + gate eval ========================
// Computes I/C/O tiles (B rows bn, bn+H, bn+2H) in 3 register accumulator
// sets with identical fragment layout, then evaluates the LSTM gates + leaky
// relu per thread and writes y fp16 to outY [Mpad, H].
// stage: A 128 rows + B 3*64 rows, 80B padded = 25600B. 3 stages = 76800B.
#define GSTAGE_G 25600

__global__ __launch_bounds__(256) void gemm_gates(
    const __half* __restrict__ A, const __half* __restrict__ B,
    const float* __restrict__ bias, const float* __restrict__ wcO,
    __half* __restrict__ outY, int M, int Kp, int H) {
    extern __shared__ char smem[];
    const uint32_t s0 = smem_u32(smem);
    const int tid = threadIdx.x;
    const int wid = tid >> 5;
    const int lane = tid & 31;
    const int wm = wid & 3, wn = wid >> 2;
    const int bn = blockIdx.x << 6;
    const int bm = blockIdx.y << 7;

    float accI[2][4][4], accC[2][4][4], accO[2][4][4];
#pragma unroll
    for (int i = 0; i < 2; i++)
#pragma unroll
        for (int j = 0; j < 4; j++)
#pragma unroll
            for (int k = 0; k < 4; k++) {
                accI[i][j][k] = 0.f; accC[i][j][k] = 0.f; accO[i][j][k] = 0.f;
            }

#define LOAD_STAGE_G(stg, kc) do {                                           \
    uint32_t dstBase = s0 + (stg) * GSTAGE_G;                                \
    _Pragma("unroll")                                                        \
    for (int u = tid; u < 1280; u += 256) {                                  \
        uint32_t d; const char* g;                                           \
        if (u < 512) {                                                       \
            int row = u >> 2, seg = u & 3;                                   \
            d = dstBase + row * 80 + seg * 16;                               \
            g = (const char*)A + ((size_t)(bm + row) * Kp + (kc)) * 2        \
                + seg * 16;                                                  \
        } else {                                                             \
            int t = u - 512; int gate = t >> 8; int tt = t & 255;            \
            int row = tt >> 2, seg = tt & 3;                                 \
            d = dstBase + (128 + gate * 64 + row) * 80 + seg * 16;           \
            g = (const char*)B + ((size_t)(gate * H + bn + row) * Kp + (kc)) \
                * 2 + seg * 16;                                              \
        }                                                                    \
        CP16(d, g);                                                          \
    } } while (0)

    const int nK = Kp >> 5;
    LOAD_STAGE_G(0, 0);
    CP_COMMIT();
    if (nK > 1) { LOAD_STAGE_G(1, 32); CP_COMMIT(); }

    for (int kt = 0; kt < nK; kt++) {
        if (kt + 1 < nK) CP_WAIT1(); else CP_WAIT0();
        __syncthreads();
        if (kt + 2 < nK) {
            LOAD_STAGE_G((kt + 2) % 3, (kt + 2) << 5);
            CP_COMMIT();
        }
        uint32_t base = s0 + (kt % 3) * GSTAGE_G;
        uint32_t kb = (lane >> 4) * 16;
        uint32_t arow = wm * 32 + (lane & 15);
#pragma unroll
        for (int kk = 0; kk < 2; kk++) {
            uint32_t a[2][4];
#pragma unroll
            for (int mt = 0; mt < 2; mt++)
                ldm_x4(a[mt], base + (arow + mt * 16) * 80 + kk * 32 + kb);
#pragma unroll
            for (int gate = 0; gate < 3; gate++) {
                uint32_t brow = 128 + gate * 64 + wn * 32 + (lane & 15);
                uint32_t b[4][2];
#pragma unroll
                for (int j = 0; j < 2; j++) {
                    uint32_t r[4];
                    ldm_x4(r, base + (brow + j * 16) * 80 + kk * 32 + kb);
                    b[2 * j][0] = r[0]; b[2 * j][1] = r[2];
                    b[2 * j + 1][0] = r[1]; b[2 * j + 1][1] = r[3];
                }
                float (*acc)[4][4] = gate == 0 ? accI : (gate == 1 ? accC : accO);
#pragma unroll
                for (int mt = 0; mt < 2; mt++)
#pragma unroll
                    for (int nt = 0; nt < 4; nt++)
                        mma16816h(acc[mt][nt], a[mt], b[nt]);
            }
        }
    }

    // epilogue: gate eval in registers
    const int gid = lane >> 2, tig = lane & 3;
#pragma unroll
    for (int mt = 0; mt < 2; mt++) {
#pragma unroll
        for (int half = 0; half < 2; half++) {
            int row = bm + wm * 32 + mt * 16 + half * 8 + gid;
            bool valid = row < M;
#pragma unroll
            for (int nt = 0; nt < 4; nt++) {
                int col = bn + wn * 32 + nt * 8 + tig * 2;
                float y0 = 0.f, y1 = 0.f;
                if (valid) {
                    float vI0 = accI[mt][nt][2 * half + 0] + bias[col];
                    float vI1 = accI[mt][nt][2 * half + 1] + bias[col + 1];
                    float vC0 = accC[mt][nt][2 * half + 0] + bias[H + col];
                    float vC1 = accC[mt][nt][2 * half + 1] + bias[H + col + 1];
                    float vO0 = accO[mt][nt][2 * half + 0] + bias[2 * H + col];
                    float vO1 = accO[mt][nt][2 * half + 1] + bias[2 * H + col + 1];
                    float I0 = fsig(vI0), T0 = ftanh(vC0), Cv0 = I0 * T0;
                    float O0 = fsig(vO0 + wcO[col] * Cv0);
                    y0 = O0 * ftanh(Cv0); y0 = y0 > 0.f ? y0 : 0.1f * y0;
                    float I1 = fsig(vI1), T1 = ftanh(vC1), Cv1 = I1 * T1;
                    float O1 = fsig(vO1 + wcO[col + 1] * Cv1);
                    y1 = O1 * ftanh(Cv1); y1 = y1 > 0.f ? y1 : 0.1f * y1;
                }
                *reinterpret_cast<__half2*>(outY + (size_t)row * H + col) =
                    __floats2half2_rn(y0, y1);
            }
        }
    }
}

// ====================== layer-3 tail: lin3 on fp16 y =======================

__global__ __launch_bounds__(256) void k_lin3h(
    const __half* __restrict__ Y, const float* __restrict__ W,
    const float* __restrict__ b, float* __restrict__ out, int n) {
    __shared__ float sW3[192];
    int tid = threadIdx.x;
    if (tid < 192) sW3[tid] = W[tid];
    __syncthreads();
    int lane = tid & 31, w = tid >> 5;
    for (int rr = 0; rr < 8; rr++) {
        int r = blockIdx.x * 64 + w * 8 + rr;
        if (r >= n) return;
        const __half* y = Y + (size_t)r * 64;
        float p0 = 0.f, p1 = 0.f, p2 = 0.f;
#pragma unroll
        for (int k = 0; k < 2; k++) {
            int u = lane + 32 * k;
            float yv = __half2float(y[u]);
            p0 += yv * sW3[u * 3]; p1 += yv * sW3[u * 3 + 1]; p2 += yv * sW3[u * 3 + 2];
        }
#pragma unroll
        for (int off = 16; off; off >>= 1) {
            p0 += __shfl_xor_sync(0xffffffffu, p0, off);
            p1 += __shfl_xor_sync(0xffffffffu, p1, off);
            p2 += __shfl_xor_sync(0xffffffffu, p2, off);
        }
        if (lane == 0) {
            out[r * 3] = p0 + b[0];
            out[r * 3 + 1] = p1 + b[1];
            out[r * 3 + 2] = p2 + b[2];
        }
    }
}

// ====================== host orchestration =================================

static inline int ceildiv(int a, int b) { return (a + b - 1) / b; }

extern "C" void kernel_launch(void* const* d_in, const int* in_sizes, int n_in,
                              void* d_out, int out_size) {
    const float* x = (const float*)d_in[0];
    const int* ei = (const int*)d_in[1];
    int N = in_sizes[0] / 3;
    int E = in_sizes[1] / 2;
    const int* src = ei;
    const int* dst = ei + E;
    int Npad = (N + 127) & ~127;
    int Mt = Npad / 128;

    const float* l1_Wx = (const float*)d_in[2];
    const float* l1_bx = (const float*)d_in[3];
    const float* l1_bh = (const float*)d_in[5];
    const float* l1_wc = (const float*)d_in[6];
    const float* l1_b  = (const float*)d_in[7];
    const float* l2_Wx = (const float*)d_in[8];
    const float* l2_bx = (const float*)d_in[9];
    const float* l2_bh = (const float*)d_in[11];
    const float* l2_wc = (const float*)d_in[12];
    const float* l2_b  = (const float*)d_in[13];
    const float* l3_Wx = (const float*)d_in[14];
    const float* l3_bx = (const float*)d_in[15];
    const float* l3_bh = (const float*)d_in[17];
    const float* l3_wc = (const float*)d_in[18];
    const float* l3_b  = (const float*)d_in[19];
    const float* lin1_W = (const float*)d_in[20];
    const float* lin1_b = (const float*)d_in[21];
    const float* lin2_W = (const float*)d_in[22];
    const float* lin2_b = (const float*)d_in[23];
    const float* lin3_W = (const float*)d_in[24];
    const float* lin3_b = (const float*)d_in[25];
    float* out = (float*)d_out;

    void* p;
    cudaGetSymbolAddress(&p, g_tmp);   int* tmp = (int*)p;
    cudaGetSymbolAddress(&p, g_xc);    float* xcf = (float*)p;
    __half* xch = (__half*)xcf;
    cudaGetSymbolAddress(&p, g_h2);    __half* H2 = (__half*)p;
    cudaGetSymbolAddress(&p, g_wbias); float* wb = (float*)p;
    cudaGetSymbolAddress(&p, g_bufA);  __half* bufA = (__half*)p;
    cudaGetSymbolAddress(&p, g_bufB);  __half* bufB = (__half*)p;
    cudaGetSymbolAddress(&p, g_bbuf);  __half* bb = (__half*)p;

    cudaFuncSetAttribute(gemm_mma2, cudaFuncAttributeMaxDynamicSharedMemorySize,
                         3 * GSTAGE);
    cudaFuncSetAttribute(gemm_gates, cudaFuncAttributeMaxDynamicSharedMemorySize,
                         3 * GSTAGE_G);

    cudaStream_t s = 0;

    // ---- graph preprocessing ----
    cudaMemsetAsync(tmp, 0, 3 * MAXN * sizeof(int), s);
    k_degree<<<ceildiv(E, 256), 256, 0, s>>>(src, dst, E);
    k_scan<<<1, 1024, 0, s>>>(N);
    k_fill<<<ceildiv(E, 256), 256, 0, s>>>(src, dst, E);

    // ---- all weight/bias preprocessing in one kernel ----
    k_prep_all<<<ceildiv(E6, 256), 256, 0, s>>>(
        l1_Wx, l2_Wx, l3_Wx, lin1_W, lin2_W,
        l1_bx, l1_bh, l1_b, l2_bx, l2_bh, l2_b, l3_bx, l3_bh, l3_b);

    // ================= layer 1 (F=3, H=256) — fully fused ===================
    k_l1a<<<ceildiv(N, 256), 256, 0, s>>>(x, xcf, N);
    k_l1gates<<<ceildiv(Npad, 64), 256, 0, s>>>(x, xcf, l1_wc + 512, bufB, N, Npad);
    // lin1: [N,256]@[256,128] + lrelu -> fp16 H2 + T0 section of layer2 A
    gemm_mma2<<<dim3(128 / 64, Mt), 256, 3 * GSTAGE, s>>>(
        bufB, bb + O_BL1, lin1_b, H2, 1, bufA, 384, N, 256, 128, 1);

    // ================= layer 2 (F=128, H=128) =================
    k_spmv_split<128, 0><<<ceildiv(Npad, 8), 256, 0, s>>>(H2, nullptr, xch, bufA, 384, 128, N, Npad);
    k_spmv_split<128, 1><<<ceildiv(Npad, 8), 256, 0, s>>>(xch, H2, nullptr, bufA, 384, 256, N, Npad);
    // fused gate GEMM + gate eval -> bufB [Npad, 128] fp16
    gemm_gates<<<dim3(2, Mt), 256, 3 * GSTAGE_G, s>>>(
        bufA, bb + O_B2, wb + 768, l2_wc + 256, bufB, N, 384, 128);
    // lin2: [N,128]@[128,64] + lrelu -> fp16 H2 + T0 section of layer3 A
    gemm_mma2<<<dim3(64 / 64, Mt), 256, 3 * GSTAGE, s>>>(
        bufB, bb + O_BL2, lin2_b, H2, 1, bufA, 192, N, 128, 64, 1);

    // ================= layer 3 (F=64, H=64) =================
    k_spmv_split<64, 0><<<ceildiv(Npad, 16), 256, 0, s>>>(H2, nullptr, xch, bufA, 192, 64, N, Npad);
    k_spmv_split<64, 1><<<ceildiv(Npad, 16), 256, 0, s>>>(xch, H2, nullptr, bufA, 192, 128, N, Npad);
    // fused gate GEMM + gate eval -> bufB [Npad, 64] fp16
    gemm_gates<<<dim3(1, Mt), 256, 3 * GSTAGE_G, s>>>(
        bufA, bb + O_B3, wb + 1152, l3_wc + 128, bufB, N, 192, 64);
    k_lin3h<<<ceildiv(N, 64), 256, 0, s>>>(bufB, lin3_W, lin3_b, out, N);
}